// round 10
// baseline (speedup 1.0000x reference)
#include <cuda_runtime.h>
#include <cuda_fp16.h>
#include <cstdint>
#include <math.h>

// ---------------------------------------------------------------------------
// Problem constants
// ---------------------------------------------------------------------------
constexpr int NV  = 65;
constexpr int ND  = 384;
constexpr int NH  = 6;
constexpr int NHD = 64;
constexpr int NL  = 6;
constexpr int NT  = 256;
constexpr int NB  = 64;
constexpr int MT  = NB * NT;       // 16384
constexpr int ND4 = 4 * ND;        // 1536
constexpr int NQKV = 3 * ND;       // 1152

// ---------------------------------------------------------------------------
// Scratch (__device__ globals; allocation-free)
// ---------------------------------------------------------------------------
__device__ float  g_x   [MT * ND];      // fp32 residual stream
__device__ __half g_h16 [MT * ND];      // LN output (GEMM A)
__device__ __half g_qkv [MT * NQKV];    // q|k packed (v region unused)
__device__ __half g_vT  [NB * NH * NHD * NT];  // V transposed per (b,h): [hd][t]
__device__ __half g_att [MT * ND];
__device__ __half g_hid [MT * ND4];

constexpr size_t OFF_QKV  = 0;
constexpr size_t OFF_PROJ = OFF_QKV  + (size_t)NL * NQKV * ND;
constexpr size_t OFF_W1   = OFF_PROJ + (size_t)NL * ND * ND;
constexpr size_t OFF_W2   = OFF_W1   + (size_t)NL * ND4 * ND;
constexpr size_t OFF_HEAD = OFF_W2   + (size_t)NL * ND * ND4;
constexpr size_t WT_TOTAL = OFF_HEAD + (size_t)NV * ND;
__device__ __half g_wT[WT_TOTAL];

// ---------------------------------------------------------------------------
// Helpers
// ---------------------------------------------------------------------------
__device__ __forceinline__ uint32_t smem_u32(const void* p) {
    uint32_t a;
    asm("{ .reg .u64 t; cvta.to.shared.u64 t, %1; cvt.u32.u64 %0, t; }"
        : "=r"(a) : "l"(p));
    return a;
}
__device__ __forceinline__ void cp16(uint32_t dst, const void* src, int srcsize) {
    asm volatile("cp.async.cg.shared.global [%0], [%1], 16, %2;"
                 :: "r"(dst), "l"(src), "r"(srcsize) : "memory");
}
__device__ __forceinline__ void cp_commit() {
    asm volatile("cp.async.commit_group;" ::: "memory");
}
__device__ __forceinline__ void ldm4(uint32_t* r, uint32_t a) {
    asm volatile("ldmatrix.sync.aligned.m8n8.x4.shared.b16 {%0,%1,%2,%3}, [%4];"
                 : "=r"(r[0]), "=r"(r[1]), "=r"(r[2]), "=r"(r[3]) : "r"(a));
}
__device__ __forceinline__ void mma_f16(float* c, const uint32_t* a,
                                        uint32_t b0, uint32_t b1) {
    asm volatile(
        "mma.sync.aligned.m16n8k16.row.col.f32.f16.f16.f32 "
        "{%0,%1,%2,%3}, {%4,%5,%6,%7}, {%8,%9}, {%0,%1,%2,%3};"
        : "+f"(c[0]), "+f"(c[1]), "+f"(c[2]), "+f"(c[3])
        : "r"(a[0]), "r"(a[1]), "r"(a[2]), "r"(a[3]), "r"(b0), "r"(b1));
}
__device__ __forceinline__ uint32_t packh2(float x, float y) {
    __half2 h = __floats2half2_rn(x, y);
    return *reinterpret_cast<uint32_t*>(&h);
}

// ---------------------------------------------------------------------------
// Embedding (fp32 residual stream)
// ---------------------------------------------------------------------------
__global__ void embed_kernel(const int* __restrict__ idx,
                             const float* __restrict__ tok,
                             const float* __restrict__ pos,
                             float* __restrict__ out)
{
    int gid = blockIdx.x * blockDim.x + threadIdx.x;
    int m = gid / ND, d = gid - m * ND;
    out[gid] = tok[(size_t)idx[m] * ND + d] + pos[(m % NT) * ND + d];
}

// ---------------------------------------------------------------------------
// LayerNorm (eps 1e-3), warp-per-row, fp32 in -> fp16 out  (layer-0 ln1 only)
// ---------------------------------------------------------------------------
__global__ __launch_bounds__(256) void ln_kernel(const float* __restrict__ x,
                                                 const float* __restrict__ g,
                                                 const float* __restrict__ bb,
                                                 __half* __restrict__ out)
{
    int w = threadIdx.x >> 5, lane = threadIdx.x & 31;
    int row = blockIdx.x * 8 + w;
    const float* xr = x + (size_t)row * ND;

    float4 xv[3];
    float s1 = 0.f, s2 = 0.f;
#pragma unroll
    for (int j = 0; j < 3; j++) {
        float4 v = *(const float4*)(xr + lane * 4 + j * 128);
        xv[j] = v;
        s1 += v.x + v.y + v.z + v.w;
        s2 += v.x * v.x + v.y * v.y + v.z * v.z + v.w * v.w;
    }
#pragma unroll
    for (int o = 16; o > 0; o >>= 1) {
        s1 += __shfl_xor_sync(0xFFFFFFFFu, s1, o);
        s2 += __shfl_xor_sync(0xFFFFFFFFu, s2, o);
    }
    float mean = s1 * (1.f / ND);
    float var  = s2 * (1.f / ND) - mean * mean;
    float rstd = rsqrtf(var + 1e-3f);
#pragma unroll
    for (int j = 0; j < 3; j++) {
        int c = lane * 4 + j * 128;
        float4 gv = *(const float4*)(g + c);
        float4 bv = *(const float4*)(bb + c);
        __half2 h0 = __floats2half2_rn((xv[j].x - mean) * rstd * gv.x + bv.x,
                                       (xv[j].y - mean) * rstd * gv.y + bv.y);
        __half2 h1 = __floats2half2_rn((xv[j].z - mean) * rstd * gv.z + bv.z,
                                       (xv[j].w - mean) * rstd * gv.w + bv.w);
        *(__half2*)(out + (size_t)row * ND + c)     = h0;
        *(__half2*)(out + (size_t)row * ND + c + 2) = h1;
    }
}

// ---------------------------------------------------------------------------
// Tiled transpose: src [R,C] fp32 (+batch offsets) -> dst [C,R] fp16.
// ---------------------------------------------------------------------------
__global__ void transpose_kernel(const float* __restrict__ src,
                                 __half* __restrict__ dst,
                                 int R, int C, int div,
                                 size_t ssA, size_t ssB,
                                 size_t dsA, size_t dsB)
{
    __shared__ float tile[32][33];
    int z = blockIdx.z;
    const float* s = src + (z / div) * ssA + (z % div) * ssB;
    __half* d = dst + (z / div) * dsA + (z % div) * dsB;
    int c0 = blockIdx.x * 32, r0 = blockIdx.y * 32;
#pragma unroll
    for (int j = 0; j < 4; j++) {
        int r = r0 + threadIdx.y + j * 8, c = c0 + threadIdx.x;
        if (r < R && c < C)
            tile[threadIdx.y + j * 8][threadIdx.x] = s[(size_t)r * C + c];
    }
    __syncthreads();
#pragma unroll
    for (int j = 0; j < 4; j++) {
        int c = c0 + threadIdx.y + j * 8, r = r0 + threadIdx.x;
        if (c < C && r < R)
            d[(size_t)c * R + r] = __float2half(tile[threadIdx.x][threadIdx.y + j * 8]);
    }
}

// ---------------------------------------------------------------------------
// fp16 mma.sync GEMM (generic, BM=128): C[M,N] = A[M,K] * B^T
// 4 warps, warp tile 64x64; 4-stage cp.async ring; rows padded 80B.
// VSPLIT: QKV col blocks >= 768 stored transposed to vT.
// ---------------------------------------------------------------------------
constexpr int NSTAGE = 4;
constexpr int SMB_G = NSTAGE * (128 + 128) * 80;   // 81920

template <bool RELU, bool OUTH, bool VSPLIT>
__global__ __launch_bounds__(128) void hgemm(
    const __half* __restrict__ A, const __half* __restrict__ B,
    const float* __restrict__ bias, const float* __restrict__ resid,
    void* __restrict__ Cv, int N, int K)
{
    extern __shared__ __half smh[];
    __shared__ float sbias[128];
    const int tid = threadIdx.x;
    const int row0 = blockIdx.y * 128;
    const int col0 = blockIdx.x * 128;

    const uint32_t base = smem_u32(smh);
    uint32_t aAu[NSTAGE], aBu[NSTAGE];
#pragma unroll
    for (int s = 0; s < NSTAGE; s++) {
        aAu[s] = base + s * 128 * 80;
        aBu[s] = base + NSTAGE * 128 * 80 + s * 128 * 80;
    }

    {
        int c = col0 + tid;
        sbias[tid] = (bias && c < N) ? bias[c] : 0.f;
    }

    const int KT = K / 32;

    auto prefetch = [&](int kt, int s) {
#pragma unroll
        for (int i = 0; i < 4; i++) {
            int slot = tid + i * 128;
            int r = slot >> 2, c8 = slot & 3;
            cp16(aAu[s] + (uint32_t)(r * 80 + c8 * 16),
                 A + (size_t)(row0 + r) * K + kt * 32 + c8 * 8, 16);
        }
#pragma unroll
        for (int i = 0; i < 4; i++) {
            int slot = tid + i * 128;
            int r = slot >> 2, c8 = slot & 3;
            int n = col0 + r;
            cp16(aBu[s] + (uint32_t)(r * 80 + c8 * 16),
                 B + (size_t)(n < N ? n : N - 1) * K + kt * 32 + c8 * 8,
                 n < N ? 16 : 0);
        }
        cp_commit();
    };

    const int w = tid >> 5, lane = tid & 31;
    const int wm = (w & 1) * 64;
    const int wn = (w >> 1) * 64;
    const int g = lane >> 2, tg = lane & 3;
    const int lr = lane & 15, lc = (lane >> 4) * 16;

    float acc[4][8][4];
#pragma unroll
    for (int i = 0; i < 4; i++)
#pragma unroll
        for (int j = 0; j < 8; j++)
#pragma unroll
            for (int q = 0; q < 4; q++) acc[i][j][q] = 0.f;

    prefetch(0, 0); prefetch(1, 1); prefetch(2, 2);

    for (int kt = 0; kt < KT; kt++) {
        int rem = KT - 1 - kt;
        if (rem >= 2)      asm volatile("cp.async.wait_group 2;" ::: "memory");
        else if (rem == 1) asm volatile("cp.async.wait_group 1;" ::: "memory");
        else               asm volatile("cp.async.wait_group 0;" ::: "memory");
        __syncthreads();

        if (kt + 3 < KT) prefetch(kt + 3, (kt + 3) & 3);

        uint32_t bA = aAu[kt & 3], bB = aBu[kt & 3];
#pragma unroll
        for (int ks = 0; ks < 2; ks++) {
            uint32_t a[4][4];
#pragma unroll
            for (int i = 0; i < 4; i++)
                ldm4(a[i], bA + (uint32_t)((wm + 16 * i + lr) * 80 + ks * 32 + lc));
            uint32_t b[4][4];
#pragma unroll
            for (int p = 0; p < 4; p++)
                ldm4(b[p], bB + (uint32_t)((wn + 16 * p + lr) * 80 + ks * 32 + lc));
#pragma unroll
            for (int i = 0; i < 4; i++)
#pragma unroll
                for (int p = 0; p < 4; p++) {
                    mma_f16(acc[i][2 * p],     a[i], b[p][0], b[p][2]);
                    mma_f16(acc[i][2 * p + 1], a[i], b[p][1], b[p][3]);
                }
        }
    }

    const bool vec = (N & 127) == 0;
    float*  Cf = (float*)Cv;
    __half* Ch = (__half*)Cv;
    __half* vtp = (__half*)resid;   // vT buffer for VSPLIT
#pragma unroll
    for (int i = 0; i < 4; i++) {
#pragma unroll
        for (int half_ = 0; half_ < 2; half_++) {
            int r = row0 + wm + 16 * i + g + 8 * half_;
#pragma unroll
            for (int j = 0; j < 8; j++) {
                int cl = wn + 8 * j + 2 * tg;
                int c = col0 + cl;
                float2 v = { acc[i][j][half_ * 2], acc[i][j][half_ * 2 + 1] };
                v.x += sbias[cl]; v.y += sbias[cl + 1];
                if (RELU) { v.x = fmaxf(v.x, 0.f); v.y = fmaxf(v.y, 0.f); }
                if (OUTH) {
                    if (VSPLIT && col0 >= 2 * ND) {
                        int cc = c - 2 * ND;
                        int hh = cc >> 6, hd = cc & 63;
                        int bb2 = r >> 8, tt = r & 255;
                        size_t vbse = ((size_t)(bb2 * NH + hh) * NHD + hd) * NT + tt;
                        vtp[vbse]      = __float2half(v.x);
                        vtp[vbse + NT] = __float2half(v.y);
                    } else {
                        *(__half2*)&Ch[(size_t)r * N + c] = __floats2half2_rn(v.x, v.y);
                    }
                } else if (vec) {
                    *(float2*)&Cf[(size_t)r * N + c] = v;
                } else {
                    if (c < N)     Cf[(size_t)r * N + c]     = v.x;
                    if (c + 1 < N) Cf[(size_t)r * N + c + 1] = v.y;
                }
            }
        }
    }
}

// ---------------------------------------------------------------------------
// Fused GEMM + residual + LayerNorm (N = 384, full width per block).
// BM=64, 8 warps: warp tile 32x96 (wm = (w&1)*32, wn = (w>>1)*96).
// Epilogue: v = acc + bias + resid  -> write fp32 resid stream,
//           block-local LN stats    -> write fp16 LN output (next op's A).
// ---------------------------------------------------------------------------
constexpr int SMB_F = NSTAGE * (64 + 384) * 80;    // 143360

__global__ __launch_bounds__(256, 1) void hgemm_ln(
    const __half* __restrict__ A, const __half* __restrict__ B,
    const float* __restrict__ bias,
    const float* __restrict__ lng, const float* __restrict__ lnb,
    float* __restrict__ px, __half* __restrict__ outh, int K)
{
    extern __shared__ __half smh[];
    __shared__ float sbias[ND], sg[ND], sb[ND];
    __shared__ float ps1[64][17], ps2[64][17];
    __shared__ float sMean[64], sRstd[64];

    const int tid = threadIdx.x;
    const int row0 = blockIdx.x * 64;

    const uint32_t base = smem_u32(smh);
    uint32_t aAu[NSTAGE], aBu[NSTAGE];
#pragma unroll
    for (int s = 0; s < NSTAGE; s++) {
        aAu[s] = base + s * 64 * 80;
        aBu[s] = base + NSTAGE * 64 * 80 + s * 384 * 80;
    }

    // stage bias + LN params
    for (int c = tid; c < ND; c += 256) {
        sbias[c] = bias ? bias[c] : 0.f;
        sg[c] = lng[c];
        sb[c] = lnb[c];
    }

    const int KT = K / 32;

    auto prefetch = [&](int kt, int s) {
        {   // A: 64 rows x 4 chunks = 256 slots
            int r = tid >> 2, c8 = tid & 3;
            cp16(aAu[s] + (uint32_t)(r * 80 + c8 * 16),
                 A + (size_t)(row0 + r) * K + kt * 32 + c8 * 8, 16);
        }
#pragma unroll
        for (int i = 0; i < 6; i++) {   // B: 384 rows x 4 chunks = 1536 slots
            int slot = tid + i * 256;
            int r = slot >> 2, c8 = slot & 3;
            cp16(aBu[s] + (uint32_t)(r * 80 + c8 * 16),
                 B + (size_t)r * K + kt * 32 + c8 * 8, 16);
        }
        cp_commit();
    };

    const int w = tid >> 5, lane = tid & 31;
    const int wm = (w & 1) * 32;
    const int wn = (w >> 1) * 96;
    const int g = lane >> 2, tg = lane & 3;
    const int lr = lane & 15, lc = (lane >> 4) * 16;

    float acc[2][12][4];
#pragma unroll
    for (int i = 0; i < 2; i++)
#pragma unroll
        for (int j = 0; j < 12; j++)
#pragma unroll
            for (int q = 0; q < 4; q++) acc[i][j][q] = 0.f;

    prefetch(0, 0); prefetch(1, 1); prefetch(2, 2);

    for (int kt = 0; kt < KT; kt++) {
        int rem = KT - 1 - kt;
        if (rem >= 2)      asm volatile("cp.async.wait_group 2;" ::: "memory");
        else if (rem == 1) asm volatile("cp.async.wait_group 1;" ::: "memory");
        else               asm volatile("cp.async.wait_group 0;" ::: "memory");
        __syncthreads();

        if (kt + 3 < KT) prefetch(kt + 3, (kt + 3) & 3);

        uint32_t bA = aAu[kt & 3], bB = aBu[kt & 3];
#pragma unroll
        for (int ks = 0; ks < 2; ks++) {
            uint32_t a[2][4];
#pragma unroll
            for (int i = 0; i < 2; i++)
                ldm4(a[i], bA + (uint32_t)((wm + 16 * i + lr) * 80 + ks * 32 + lc));
            uint32_t b[6][4];
#pragma unroll
            for (int p = 0; p < 6; p++)
                ldm4(b[p], bB + (uint32_t)((wn + 16 * p + lr) * 80 + ks * 32 + lc));
#pragma unroll
            for (int i = 0; i < 2; i++)
#pragma unroll
                for (int p = 0; p < 6; p++) {
                    mma_f16(acc[i][2 * p],     a[i], b[p][0], b[p][2]);
                    mma_f16(acc[i][2 * p + 1], a[i], b[p][1], b[p][3]);
                }
        }
    }

    // --- Epilogue: residual add + write px + LN partials ---
    const int slot = (w >> 1) * 4 + tg;
#pragma unroll
    for (int i = 0; i < 2; i++) {
#pragma unroll
        for (int h = 0; h < 2; h++) {
            int rb = wm + 16 * i + g + 8 * h;
            int r = row0 + rb;
            float s1 = 0.f, s2 = 0.f;
#pragma unroll
            for (int j = 0; j < 12; j++) {
                int cl = wn + 8 * j + 2 * tg;
                float2 rv = *(const float2*)&px[(size_t)r * ND + cl];
                float vx = acc[i][j][2 * h]     + sbias[cl]     + rv.x;
                float vy = acc[i][j][2 * h + 1] + sbias[cl + 1] + rv.y;
                acc[i][j][2 * h] = vx; acc[i][j][2 * h + 1] = vy;
                *(float2*)&px[(size_t)r * ND + cl] = make_float2(vx, vy);
                s1 += vx + vy;
                s2 += vx * vx + vy * vy;
            }
            ps1[rb][slot] = s1;
            ps2[rb][slot] = s2;
        }
    }
    __syncthreads();
    if (tid < 64) {
        float s1 = 0.f, s2 = 0.f;
#pragma unroll
        for (int k = 0; k < 16; k++) { s1 += ps1[tid][k]; s2 += ps2[tid][k]; }
        float mean = s1 * (1.f / ND);
        float var  = s2 * (1.f / ND) - mean * mean;
        sMean[tid] = mean;
        sRstd[tid] = rsqrtf(var + 1e-3f);
    }
    __syncthreads();
#pragma unroll
    for (int i = 0; i < 2; i++) {
#pragma unroll
        for (int h = 0; h < 2; h++) {
            int rb = wm + 16 * i + g + 8 * h;
            int r = row0 + rb;
            float mean = sMean[rb], rstd = sRstd[rb];
#pragma unroll
            for (int j = 0; j < 12; j++) {
                int cl = wn + 8 * j + 2 * tg;
                float hx = (acc[i][j][2 * h]     - mean) * rstd * sg[cl]     + sb[cl];
                float hy = (acc[i][j][2 * h + 1] - mean) * rstd * sg[cl + 1] + sb[cl + 1];
                *(__half2*)&outh[(size_t)r * ND + cl] = __floats2half2_rn(hx, hy);
            }
        }
    }
}

// ---------------------------------------------------------------------------
// Flash attention (tensor cores). Block = (b*NH+h, qtile of 128); 8 warps.
// ---------------------------------------------------------------------------
constexpr int AST = 72;

__global__ __launch_bounds__(256) void fattn_kernel(
    const __half* __restrict__ qkv, const __half* __restrict__ vT,
    __half* __restrict__ out)
{
    __shared__ __half sQ[128 * AST], sK[64 * AST], sV[64 * AST];
    const int bh = blockIdx.x, qt = blockIdx.y;
    const int b = bh / NH, h = bh - b * NH;
    const int tid = threadIdx.x, w = tid >> 5, lane = tid & 31;
    const int g = lane >> 2, tg = lane & 3;
    const int lr = lane & 15;
    const uint32_t lc = (lane >> 4) * 16;

    const uint32_t qb = smem_u32(sQ), kb = smem_u32(sK), vb = smem_u32(sV);

    for (int i = tid; i < 1024; i += 256) {
        int r = i >> 3, c8 = i & 7;
        cp16(qb + (uint32_t)(r * AST * 2 + c8 * 16),
             qkv + (size_t)(b * NT + qt * 128 + r) * NQKV + h * NHD + c8 * 8, 16);
    }
    cp_commit();
    asm volatile("cp.async.wait_group 0;" ::: "memory");
    __syncthreads();

    uint32_t qf[4][4];
#pragma unroll
    for (int c = 0; c < 4; c++)
        ldm4(qf[c], qb + (uint32_t)((w * 16 + lr) * AST * 2 + c * 32) + lc);

    float O[8][4];
#pragma unroll
    for (int j = 0; j < 8; j++)
#pragma unroll
        for (int q = 0; q < 4; q++) O[j][q] = 0.f;
    float m0 = -1e30f, m1 = -1e30f, l0 = 0.f, l1 = 0.f;
    const float scale = rsqrtf((float)ND);

    const int wrow = qt * 128 + w * 16;
    const int smax = qt * 128 + 64;

    for (int s0 = 0; s0 <= smax; s0 += 64) {
        __syncthreads();
        for (int i = tid; i < 512; i += 256) {
            int r = i >> 3, c8 = i & 7;
            cp16(kb + (uint32_t)(r * AST * 2 + c8 * 16),
                 qkv + (size_t)(b * NT + s0 + r) * NQKV + ND + h * NHD + c8 * 8, 16);
            cp16(vb + (uint32_t)(r * AST * 2 + c8 * 16),
                 vT + ((size_t)bh * NHD + r) * NT + s0 + c8 * 8, 16);
        }
        cp_commit();
        asm volatile("cp.async.wait_group 0;" ::: "memory");
        __syncthreads();

        if (s0 > wrow + 15) continue;

        float S[8][4];
#pragma unroll
        for (int j = 0; j < 8; j++)
            S[j][0] = S[j][1] = S[j][2] = S[j][3] = 0.f;
#pragma unroll
        for (int p = 0; p < 4; p++) {
#pragma unroll
            for (int c = 0; c < 4; c++) {
                uint32_t bf[4];
                ldm4(bf, kb + (uint32_t)((p * 16 + lr) * AST * 2 + c * 32) + lc);
                mma_f16(S[2 * p],     qf[c], bf[0], bf[2]);
                mma_f16(S[2 * p + 1], qf[c], bf[1], bf[3]);
            }
        }

        const bool diag = (s0 + 63 > wrow);
        const int rg0 = wrow + g, rg1 = wrow + g + 8;
#pragma unroll
        for (int j = 0; j < 8; j++) {
            int cg = s0 + j * 8 + 2 * tg;
            S[j][0] *= scale; S[j][1] *= scale;
            S[j][2] *= scale; S[j][3] *= scale;
            if (diag) {
                if (cg     > rg0) S[j][0] = -1e30f;
                if (cg + 1 > rg0) S[j][1] = -1e30f;
                if (cg     > rg1) S[j][2] = -1e30f;
                if (cg + 1 > rg1) S[j][3] = -1e30f;
            }
        }

        float tm0 = -1e30f, tm1 = -1e30f;
#pragma unroll
        for (int j = 0; j < 8; j++) {
            tm0 = fmaxf(tm0, fmaxf(S[j][0], S[j][1]));
            tm1 = fmaxf(tm1, fmaxf(S[j][2], S[j][3]));
        }
        tm0 = fmaxf(tm0, __shfl_xor_sync(0xFFFFFFFFu, tm0, 1));
        tm0 = fmaxf(tm0, __shfl_xor_sync(0xFFFFFFFFu, tm0, 2));
        tm1 = fmaxf(tm1, __shfl_xor_sync(0xFFFFFFFFu, tm1, 1));
        tm1 = fmaxf(tm1, __shfl_xor_sync(0xFFFFFFFFu, tm1, 2));
        float nm0 = fmaxf(m0, tm0), nm1 = fmaxf(m1, tm1);
        float cor0 = __expf(m0 - nm0), cor1 = __expf(m1 - nm1);
        float ts0 = 0.f, ts1 = 0.f;
#pragma unroll
        for (int j = 0; j < 8; j++) {
            S[j][0] = __expf(S[j][0] - nm0); ts0 += S[j][0];
            S[j][1] = __expf(S[j][1] - nm0); ts0 += S[j][1];
            S[j][2] = __expf(S[j][2] - nm1); ts1 += S[j][2];
            S[j][3] = __expf(S[j][3] - nm1); ts1 += S[j][3];
        }
        ts0 += __shfl_xor_sync(0xFFFFFFFFu, ts0, 1);
        ts0 += __shfl_xor_sync(0xFFFFFFFFu, ts0, 2);
        ts1 += __shfl_xor_sync(0xFFFFFFFFu, ts1, 1);
        ts1 += __shfl_xor_sync(0xFFFFFFFFu, ts1, 2);
        l0 = l0 * cor0 + ts0;  l1 = l1 * cor1 + ts1;
        m0 = nm0;  m1 = nm1;
#pragma unroll
        for (int j = 0; j < 8; j++) {
            O[j][0] *= cor0; O[j][1] *= cor0;
            O[j][2] *= cor1; O[j][3] *= cor1;
        }

        uint32_t pf[4][4];
#pragma unroll
        for (int c = 0; c < 4; c++) {
            pf[c][0] = packh2(S[2 * c][0],     S[2 * c][1]);
            pf[c][1] = packh2(S[2 * c][2],     S[2 * c][3]);
            pf[c][2] = packh2(S[2 * c + 1][0], S[2 * c + 1][1]);
            pf[c][3] = packh2(S[2 * c + 1][2], S[2 * c + 1][3]);
        }

#pragma unroll
        for (int p = 0; p < 4; p++) {
#pragma unroll
            for (int c = 0; c < 4; c++) {
                uint32_t bf[4];
                ldm4(bf, vb + (uint32_t)((p * 16 + lr) * AST * 2 + c * 32) + lc);
                mma_f16(O[2 * p],     pf[c], bf[0], bf[2]);
                mma_f16(O[2 * p + 1], pf[c], bf[1], bf[3]);
            }
        }
    }

    float i0 = 1.f / l0, i1 = 1.f / l1;
    int qrow = qt * 128 + w * 16 + g;
    size_t ob0 = (size_t)(b * NT + qrow) * ND + h * NHD;
    size_t ob1 = ob0 + (size_t)8 * ND;
#pragma unroll
    for (int j = 0; j < 8; j++) {
        int cc = j * 8 + 2 * tg;
        *(__half2*)(out + ob0 + cc) = __floats2half2_rn(O[j][0] * i0, O[j][1] * i0);
        *(__half2*)(out + ob1 + cc) = __floats2half2_rn(O[j][2] * i1, O[j][3] * i1);
    }
}

// ---------------------------------------------------------------------------
extern "C" void kernel_launch(void* const* d_in, const int* in_sizes, int n_in,
                              void* d_out, int out_size)
{
    const int*   idx   = (const int*)  d_in[0];
    const float* tok   = (const float*)d_in[1];
    const float* pos   = (const float*)d_in[2];
    const float* Wq    = (const float*)d_in[3];
    const float* Wk    = (const float*)d_in[4];
    const float* Wv    = (const float*)d_in[5];
    const float* Wproj = (const float*)d_in[6];
    const float* bproj = (const float*)d_in[7];
    const float* W1    = (const float*)d_in[8];
    const float* b1    = (const float*)d_in[9];
    const float* W2    = (const float*)d_in[10];
    const float* b2    = (const float*)d_in[11];
    const float* ln1g  = (const float*)d_in[12];
    const float* ln1b  = (const float*)d_in[13];
    const float* ln2g  = (const float*)d_in[14];
    const float* ln2b  = (const float*)d_in[15];
    const float* lnfg  = (const float*)d_in[16];
    const float* lnfb  = (const float*)d_in[17];
    const float* Whead = (const float*)d_in[18];
    const float* bhead = (const float*)d_in[19];
    float* out = (float*)d_out;

    float  *px;
    __half *ph, *pqkv, *pvT, *pa, *pm, *pw;
    cudaGetSymbolAddress((void**)&px,   g_x);
    cudaGetSymbolAddress((void**)&ph,   g_h16);
    cudaGetSymbolAddress((void**)&pqkv, g_qkv);
    cudaGetSymbolAddress((void**)&pvT,  g_vT);
    cudaGetSymbolAddress((void**)&pa,   g_att);
    cudaGetSymbolAddress((void**)&pm,   g_hid);
    cudaGetSymbolAddress((void**)&pw,   g_wT);

    static int attr_done = 0;
    if (!attr_done) {
        cudaFuncSetAttribute(hgemm<false, true, true>,
                             cudaFuncAttributeMaxDynamicSharedMemorySize, SMB_G);
        cudaFuncSetAttribute(hgemm<true, true, false>,
                             cudaFuncAttributeMaxDynamicSharedMemorySize, SMB_G);
        cudaFuncSetAttribute(hgemm<false, false, false>,
                             cudaFuncAttributeMaxDynamicSharedMemorySize, SMB_G);
        cudaFuncSetAttribute(hgemm_ln,
                             cudaFuncAttributeMaxDynamicSharedMemorySize, SMB_F);
        attr_done = 1;
    }

    // Weight prep: tiled transpose -> K-major [N,K] fp16
    {
        dim3 blk(32, 8);
        dim3 gqv(NHD / 32, ND / 32, NL * NH);
        size_t ssA = (size_t)NH * ND * NHD, ssB = (size_t)ND * NHD;
        size_t dsA = (size_t)NQKV * ND,     dsB = (size_t)NHD * ND;
        transpose_kernel<<<gqv, blk>>>(Wq, pw + OFF_QKV,                       ND, NHD, NH, ssA, ssB, dsA, dsB);
        transpose_kernel<<<gqv, blk>>>(Wk, pw + OFF_QKV + (size_t)ND * ND,     ND, NHD, NH, ssA, ssB, dsA, dsB);
        transpose_kernel<<<gqv, blk>>>(Wv, pw + OFF_QKV + (size_t)2 * ND * ND, ND, NHD, NH, ssA, ssB, dsA, dsB);
        transpose_kernel<<<dim3(ND / 32, ND / 32, NL), blk>>>(
            Wproj, pw + OFF_PROJ, ND, ND, 1, (size_t)ND * ND, 0, (size_t)ND * ND, 0);
        transpose_kernel<<<dim3(ND4 / 32, ND / 32, NL), blk>>>(
            W1, pw + OFF_W1, ND, ND4, 1, (size_t)ND * ND4, 0, (size_t)ND * ND4, 0);
        transpose_kernel<<<dim3(ND / 32, ND4 / 32, NL), blk>>>(
            W2, pw + OFF_W2, ND4, ND, 1, (size_t)ND * ND4, 0, (size_t)ND * ND4, 0);
        transpose_kernel<<<dim3((NV + 31) / 32, ND / 32, 1), blk>>>(
            Whead, pw + OFF_HEAD, ND, NV, 1, 0, 0, 0, 0);
    }

    embed_kernel<<<(MT * ND) / 256, 256>>>(idx, tok, pos, px);
    ln_kernel<<<MT / 8, 256>>>(px, ln1g, ln1b, ph);   // layer-0 ln1

    dim3 gQKV(NQKV / 128, MT / 128);
    dim3 g4  (ND4  / 128, MT / 128);
    dim3 gH  (1, MT / 128);

    for (int l = 0; l < NL; l++) {
        hgemm<false, true, true><<<gQKV, 128, SMB_G>>>(
            ph, pw + OFF_QKV + (size_t)l * NQKV * ND,
            nullptr, (const float*)pvT, pqkv, NQKV, ND);

        fattn_kernel<<<dim3(NB * NH, NT / 128), 256>>>(pqkv, pvT, pa);

        // proj + residual + ln2 (fused)
        hgemm_ln<<<MT / 64, 256, SMB_F>>>(
            pa, pw + OFF_PROJ + (size_t)l * ND * ND,
            bproj + l * ND, ln2g + l * ND, ln2b + l * ND, px, ph, ND);

        hgemm<true, true, false><<<g4, 128, SMB_G>>>(
            ph, pw + OFF_W1 + (size_t)l * ND4 * ND,
            b1 + l * ND4, nullptr, pm, ND4, ND);

        // W2 + residual + next LN (ln1 of l+1, or lnf after last layer)
        const float* ng = (l + 1 < NL) ? (ln1g + (l + 1) * ND) : lnfg;
        const float* nb = (l + 1 < NL) ? (ln1b + (l + 1) * ND) : lnfb;
        hgemm_ln<<<MT / 64, 256, SMB_F>>>(
            pm, pw + OFF_W2 + (size_t)l * ND * ND4,
            b2 + l * ND, ng, nb, px, ph, ND4);
    }

    hgemm<false, false, false><<<gH, 128, SMB_G>>>(
        ph, pw + OFF_HEAD, bhead, nullptr, out, NV, ND);
}

// round 11
// speedup vs baseline: 1.0818x; 1.0818x over previous
#include <cuda_runtime.h>
#include <cuda_fp16.h>
#include <cstdint>
#include <math.h>

// ---------------------------------------------------------------------------
// Problem constants
// ---------------------------------------------------------------------------
constexpr int NV  = 65;
constexpr int ND  = 384;
constexpr int NH  = 6;
constexpr int NHD = 64;
constexpr int NL  = 6;
constexpr int NT  = 256;
constexpr int NB  = 64;
constexpr int MT  = NB * NT;       // 16384
constexpr int ND4 = 4 * ND;        // 1536
constexpr int NQKV = 3 * ND;       // 1152

// ---------------------------------------------------------------------------
// Scratch (__device__ globals; allocation-free)
// ---------------------------------------------------------------------------
__device__ float  g_x   [MT * ND];      // fp32 residual stream
__device__ __half g_h16 [MT * ND];      // LN output (GEMM A)
__device__ __half g_qkv [MT * NQKV];    // q|k packed (v region unused)
__device__ __half g_vT  [NB * NH * NHD * NT];  // V transposed per (b,h): [hd][t]
__device__ __half g_att [MT * ND];
__device__ __half g_hid [MT * ND4];

constexpr size_t OFF_QKV  = 0;
constexpr size_t OFF_PROJ = OFF_QKV  + (size_t)NL * NQKV * ND;
constexpr size_t OFF_W1   = OFF_PROJ + (size_t)NL * ND * ND;
constexpr size_t OFF_W2   = OFF_W1   + (size_t)NL * ND4 * ND;
constexpr size_t OFF_HEAD = OFF_W2   + (size_t)NL * ND * ND4;
constexpr size_t WT_TOTAL = OFF_HEAD + (size_t)NV * ND;
__device__ __half g_wT[WT_TOTAL];

// ---------------------------------------------------------------------------
// Helpers
// ---------------------------------------------------------------------------
__device__ __forceinline__ uint32_t smem_u32(const void* p) {
    uint32_t a;
    asm("{ .reg .u64 t; cvta.to.shared.u64 t, %1; cvt.u32.u64 %0, t; }"
        : "=r"(a) : "l"(p));
    return a;
}
__device__ __forceinline__ void cp16(uint32_t dst, const void* src, int srcsize) {
    asm volatile("cp.async.cg.shared.global [%0], [%1], 16, %2;"
                 :: "r"(dst), "l"(src), "r"(srcsize) : "memory");
}
__device__ __forceinline__ void cp_commit() {
    asm volatile("cp.async.commit_group;" ::: "memory");
}
__device__ __forceinline__ void ldm4(uint32_t* r, uint32_t a) {
    asm volatile("ldmatrix.sync.aligned.m8n8.x4.shared.b16 {%0,%1,%2,%3}, [%4];"
                 : "=r"(r[0]), "=r"(r[1]), "=r"(r[2]), "=r"(r[3]) : "r"(a));
}
__device__ __forceinline__ void mma_f16(float* c, const uint32_t* a,
                                        uint32_t b0, uint32_t b1) {
    asm volatile(
        "mma.sync.aligned.m16n8k16.row.col.f32.f16.f16.f32 "
        "{%0,%1,%2,%3}, {%4,%5,%6,%7}, {%8,%9}, {%0,%1,%2,%3};"
        : "+f"(c[0]), "+f"(c[1]), "+f"(c[2]), "+f"(c[3])
        : "r"(a[0]), "r"(a[1]), "r"(a[2]), "r"(a[3]), "r"(b0), "r"(b1));
}
__device__ __forceinline__ uint32_t packh2(float x, float y) {
    __half2 h = __floats2half2_rn(x, y);
    return *reinterpret_cast<uint32_t*>(&h);
}

// ---------------------------------------------------------------------------
// Fused embedding + LayerNorm (layer-0 ln1). Warp-per-row; writes fp32
// residual stream AND fp16 LN output. Values identical to embed->ln chain.
// ---------------------------------------------------------------------------
__global__ __launch_bounds__(256) void embed_ln_kernel(
    const int* __restrict__ idx,
    const float* __restrict__ tok,
    const float* __restrict__ pos,
    const float* __restrict__ g,
    const float* __restrict__ bb,
    float* __restrict__ px,
    __half* __restrict__ outh)
{
    int w = threadIdx.x >> 5, lane = threadIdx.x & 31;
    int row = blockIdx.x * 8 + w;
    int token = idx[row];
    const float* tr = tok + (size_t)token * ND;
    const float* pr = pos + (size_t)(row % NT) * ND;

    float4 xv[3];
    float s1 = 0.f, s2 = 0.f;
#pragma unroll
    for (int j = 0; j < 3; j++) {
        int c = lane * 4 + j * 128;
        float4 tv = *(const float4*)(tr + c);
        float4 pv = *(const float4*)(pr + c);
        float4 v = { tv.x + pv.x, tv.y + pv.y, tv.z + pv.z, tv.w + pv.w };
        xv[j] = v;
        *(float4*)(px + (size_t)row * ND + c) = v;
        s1 += v.x + v.y + v.z + v.w;
        s2 += v.x * v.x + v.y * v.y + v.z * v.z + v.w * v.w;
    }
#pragma unroll
    for (int o = 16; o > 0; o >>= 1) {
        s1 += __shfl_xor_sync(0xFFFFFFFFu, s1, o);
        s2 += __shfl_xor_sync(0xFFFFFFFFu, s2, o);
    }
    float mean = s1 * (1.f / ND);
    float var  = s2 * (1.f / ND) - mean * mean;
    float rstd = rsqrtf(var + 1e-3f);
#pragma unroll
    for (int j = 0; j < 3; j++) {
        int c = lane * 4 + j * 128;
        float4 gv = *(const float4*)(g + c);
        float4 bv = *(const float4*)(bb + c);
        __half2 h0 = __floats2half2_rn((xv[j].x - mean) * rstd * gv.x + bv.x,
                                       (xv[j].y - mean) * rstd * gv.y + bv.y);
        __half2 h1 = __floats2half2_rn((xv[j].z - mean) * rstd * gv.z + bv.z,
                                       (xv[j].w - mean) * rstd * gv.w + bv.w);
        *(__half2*)(outh + (size_t)row * ND + c)     = h0;
        *(__half2*)(outh + (size_t)row * ND + c + 2) = h1;
    }
}

// ---------------------------------------------------------------------------
// LayerNorm (eps 1e-3), warp-per-row, fp32 in -> fp16 out
// ---------------------------------------------------------------------------
__global__ __launch_bounds__(256) void ln_kernel(const float* __restrict__ x,
                                                 const float* __restrict__ g,
                                                 const float* __restrict__ bb,
                                                 __half* __restrict__ out)
{
    int w = threadIdx.x >> 5, lane = threadIdx.x & 31;
    int row = blockIdx.x * 8 + w;
    const float* xr = x + (size_t)row * ND;

    float4 xv[3];
    float s1 = 0.f, s2 = 0.f;
#pragma unroll
    for (int j = 0; j < 3; j++) {
        float4 v = *(const float4*)(xr + lane * 4 + j * 128);
        xv[j] = v;
        s1 += v.x + v.y + v.z + v.w;
        s2 += v.x * v.x + v.y * v.y + v.z * v.z + v.w * v.w;
    }
#pragma unroll
    for (int o = 16; o > 0; o >>= 1) {
        s1 += __shfl_xor_sync(0xFFFFFFFFu, s1, o);
        s2 += __shfl_xor_sync(0xFFFFFFFFu, s2, o);
    }
    float mean = s1 * (1.f / ND);
    float var  = s2 * (1.f / ND) - mean * mean;
    float rstd = rsqrtf(var + 1e-3f);
#pragma unroll
    for (int j = 0; j < 3; j++) {
        int c = lane * 4 + j * 128;
        float4 gv = *(const float4*)(g + c);
        float4 bv = *(const float4*)(bb + c);
        __half2 h0 = __floats2half2_rn((xv[j].x - mean) * rstd * gv.x + bv.x,
                                       (xv[j].y - mean) * rstd * gv.y + bv.y);
        __half2 h1 = __floats2half2_rn((xv[j].z - mean) * rstd * gv.z + bv.z,
                                       (xv[j].w - mean) * rstd * gv.w + bv.w);
        *(__half2*)(out + (size_t)row * ND + c)     = h0;
        *(__half2*)(out + (size_t)row * ND + c + 2) = h1;
    }
}

// ---------------------------------------------------------------------------
// Tiled transpose: src [R,C] fp32 (+batch offsets) -> dst [C,R] fp16.
// ---------------------------------------------------------------------------
__global__ void transpose_kernel(const float* __restrict__ src,
                                 __half* __restrict__ dst,
                                 int R, int C, int div,
                                 size_t ssA, size_t ssB,
                                 size_t dsA, size_t dsB)
{
    __shared__ float tile[32][33];
    int z = blockIdx.z;
    const float* s = src + (z / div) * ssA + (z % div) * ssB;
    __half* d = dst + (z / div) * dsA + (z % div) * dsB;
    int c0 = blockIdx.x * 32, r0 = blockIdx.y * 32;
#pragma unroll
    for (int j = 0; j < 4; j++) {
        int r = r0 + threadIdx.y + j * 8, c = c0 + threadIdx.x;
        if (r < R && c < C)
            tile[threadIdx.y + j * 8][threadIdx.x] = s[(size_t)r * C + c];
    }
    __syncthreads();
#pragma unroll
    for (int j = 0; j < 4; j++) {
        int c = c0 + threadIdx.y + j * 8, r = r0 + threadIdx.x;
        if (c < C && r < R)
            d[(size_t)c * R + r] = __float2half(tile[threadIdx.x][threadIdx.y + j * 8]);
    }
}

// ---------------------------------------------------------------------------
// fp16 mma.sync GEMM, templated block-M (round-8 proven config):
//   BM=128: 4 warps of 64x64.
//   BM=64 : 4 warps of 32x64, 3 blocks/SM (proj, W2, head).
// B is [N,K] K-major fp16; 4-stage cp.async ring; rows padded to 80B.
// VSPLIT (BM=128 only): QKV col blocks >= 768 stored transposed to vT.
// ---------------------------------------------------------------------------
constexpr int NSTAGE = 4;
constexpr int smbytes(int BM) { return NSTAGE * (BM + 128) * 80; }

template <int BM, bool RELU, bool RESID, bool OUTH, bool VSPLIT>
__global__ __launch_bounds__(128, BM == 64 ? 3 : 1) void hgemm(
    const __half* __restrict__ A, const __half* __restrict__ B,
    const float* __restrict__ bias, const float* __restrict__ resid,
    void* __restrict__ Cv, int N, int K)
{
    constexpr int AF = BM / 32;            // A fragments per warp
    extern __shared__ __half smh[];
    __shared__ float sbias[128];
    const int tid = threadIdx.x;
    const int row0 = blockIdx.y * BM;
    const int col0 = blockIdx.x * 128;

    const uint32_t base = smem_u32(smh);
    uint32_t aAu[NSTAGE], aBu[NSTAGE];
#pragma unroll
    for (int s = 0; s < NSTAGE; s++) {
        aAu[s] = base + s * BM * 80;
        aBu[s] = base + NSTAGE * BM * 80 + s * 128 * 80;
    }

    {
        int c = col0 + tid;
        sbias[tid] = (bias && c < N) ? bias[c] : 0.f;
    }

    const int KT = K / 32;

    auto prefetch = [&](int kt, int s) {
#pragma unroll
        for (int i = 0; i < BM / 32; i++) {
            int slot = tid + i * 128;
            int r = slot >> 2, c8 = slot & 3;
            cp16(aAu[s] + (uint32_t)(r * 80 + c8 * 16),
                 A + (size_t)(row0 + r) * K + kt * 32 + c8 * 8, 16);
        }
#pragma unroll
        for (int i = 0; i < 4; i++) {
            int slot = tid + i * 128;
            int r = slot >> 2, c8 = slot & 3;
            int n = col0 + r;
            cp16(aBu[s] + (uint32_t)(r * 80 + c8 * 16),
                 B + (size_t)(n < N ? n : N - 1) * K + kt * 32 + c8 * 8,
                 n < N ? 16 : 0);
        }
        cp_commit();
    };

    const int w = tid >> 5, lane = tid & 31;
    const int wm = (w & 1) * (BM / 2);
    const int wn = (w >> 1) * 64;
    const int g = lane >> 2, tg = lane & 3;
    const int lr = lane & 15, lc = (lane >> 4) * 16;

    float acc[AF][8][4];
#pragma unroll
    for (int i = 0; i < AF; i++)
#pragma unroll
        for (int j = 0; j < 8; j++)
#pragma unroll
            for (int q = 0; q < 4; q++) acc[i][j][q] = 0.f;

    prefetch(0, 0); prefetch(1, 1); prefetch(2, 2);

    for (int kt = 0; kt < KT; kt++) {
        int rem = KT - 1 - kt;
        if (rem >= 2)      asm volatile("cp.async.wait_group 2;" ::: "memory");
        else if (rem == 1) asm volatile("cp.async.wait_group 1;" ::: "memory");
        else               asm volatile("cp.async.wait_group 0;" ::: "memory");
        __syncthreads();

        if (kt + 3 < KT) prefetch(kt + 3, (kt + 3) & 3);

        uint32_t bA = aAu[kt & 3], bB = aBu[kt & 3];
#pragma unroll
        for (int ks = 0; ks < 2; ks++) {
            uint32_t a[AF][4];
#pragma unroll
            for (int i = 0; i < AF; i++)
                ldm4(a[i], bA + (uint32_t)((wm + 16 * i + lr) * 80 + ks * 32 + lc));
            uint32_t b[4][4];
#pragma unroll
            for (int p = 0; p < 4; p++)
                ldm4(b[p], bB + (uint32_t)((wn + 16 * p + lr) * 80 + ks * 32 + lc));
#pragma unroll
            for (int i = 0; i < AF; i++)
#pragma unroll
                for (int p = 0; p < 4; p++) {
                    mma_f16(acc[i][2 * p],     a[i], b[p][0], b[p][2]);
                    mma_f16(acc[i][2 * p + 1], a[i], b[p][1], b[p][3]);
                }
        }
    }

    // Epilogue
    const bool vec = (N & 127) == 0;
    float*  Cf = (float*)Cv;
    __half* Ch = (__half*)Cv;
    __half* vtp = (__half*)resid;   // vT buffer for VSPLIT
#pragma unroll
    for (int i = 0; i < AF; i++) {
#pragma unroll
        for (int half_ = 0; half_ < 2; half_++) {
            int r = row0 + wm + 16 * i + g + 8 * half_;
#pragma unroll
            for (int j = 0; j < 8; j++) {
                int cl = wn + 8 * j + 2 * tg;
                int c = col0 + cl;
                float2 v = { acc[i][j][half_ * 2], acc[i][j][half_ * 2 + 1] };
                v.x += sbias[cl]; v.y += sbias[cl + 1];
                if (RELU) { v.x = fmaxf(v.x, 0.f); v.y = fmaxf(v.y, 0.f); }
                if (OUTH) {
                    if (VSPLIT && col0 >= 2 * ND) {
                        int cc = c - 2 * ND;
                        int hh = cc >> 6, hd = cc & 63;
                        int bb2 = r >> 8, tt = r & 255;
                        size_t vbse = ((size_t)(bb2 * NH + hh) * NHD + hd) * NT + tt;
                        vtp[vbse]      = __float2half(v.x);
                        vtp[vbse + NT] = __float2half(v.y);
                    } else {
                        *(__half2*)&Ch[(size_t)r * N + c] = __floats2half2_rn(v.x, v.y);
                    }
                } else if (vec) {
                    if (RESID) {
                        float2 rv = *(const float2*)&resid[(size_t)r * N + c];
                        v.x += rv.x; v.y += rv.y;
                    }
                    *(float2*)&Cf[(size_t)r * N + c] = v;
                } else {
                    if (c < N)     Cf[(size_t)r * N + c]     = v.x;
                    if (c + 1 < N) Cf[(size_t)r * N + c + 1] = v.y;
                }
            }
        }
    }
}

// ---------------------------------------------------------------------------
// Flash attention (tensor cores). Block = (b*NH+h, qtile of 128); 8 warps,
// each warp 16 query rows. K/V tiles of 64 kv; V^T [hd][t] as K-major B.
// ---------------------------------------------------------------------------
constexpr int AST = 72;   // smem halves per row (144 B)

__global__ __launch_bounds__(256) void fattn_kernel(
    const __half* __restrict__ qkv, const __half* __restrict__ vT,
    __half* __restrict__ out)
{
    __shared__ __half sQ[128 * AST], sK[64 * AST], sV[64 * AST];
    const int bh = blockIdx.x, qt = blockIdx.y;
    const int b = bh / NH, h = bh - b * NH;
    const int tid = threadIdx.x, w = tid >> 5, lane = tid & 31;
    const int g = lane >> 2, tg = lane & 3;
    const int lr = lane & 15;
    const uint32_t lc = (lane >> 4) * 16;

    const uint32_t qb = smem_u32(sQ), kb = smem_u32(sK), vb = smem_u32(sV);

    for (int i = tid; i < 1024; i += 256) {
        int r = i >> 3, c8 = i & 7;
        cp16(qb + (uint32_t)(r * AST * 2 + c8 * 16),
             qkv + (size_t)(b * NT + qt * 128 + r) * NQKV + h * NHD + c8 * 8, 16);
    }
    cp_commit();
    asm volatile("cp.async.wait_group 0;" ::: "memory");
    __syncthreads();

    uint32_t qf[4][4];
#pragma unroll
    for (int c = 0; c < 4; c++)
        ldm4(qf[c], qb + (uint32_t)((w * 16 + lr) * AST * 2 + c * 32) + lc);

    float O[8][4];
#pragma unroll
    for (int j = 0; j < 8; j++)
#pragma unroll
        for (int q = 0; q < 4; q++) O[j][q] = 0.f;
    float m0 = -1e30f, m1 = -1e30f, l0 = 0.f, l1 = 0.f;
    const float scale = rsqrtf((float)ND);

    const int wrow = qt * 128 + w * 16;   // warp's first global query row
    const int smax = qt * 128 + 64;       // last kv tile start

    for (int s0 = 0; s0 <= smax; s0 += 64) {
        __syncthreads();   // previous tile's PV done before overwrite
        for (int i = tid; i < 512; i += 256) {
            int r = i >> 3, c8 = i & 7;
            cp16(kb + (uint32_t)(r * AST * 2 + c8 * 16),
                 qkv + (size_t)(b * NT + s0 + r) * NQKV + ND + h * NHD + c8 * 8, 16);
            cp16(vb + (uint32_t)(r * AST * 2 + c8 * 16),
                 vT + ((size_t)bh * NHD + r) * NT + s0 + c8 * 8, 16);
        }
        cp_commit();
        asm volatile("cp.async.wait_group 0;" ::: "memory");
        __syncthreads();

        if (s0 > wrow + 15) continue;   // warp fully masked: exact zero contrib

        float S[8][4];
#pragma unroll
        for (int j = 0; j < 8; j++)
            S[j][0] = S[j][1] = S[j][2] = S[j][3] = 0.f;
#pragma unroll
        for (int p = 0; p < 4; p++) {
#pragma unroll
            for (int c = 0; c < 4; c++) {
                uint32_t bf[4];
                ldm4(bf, kb + (uint32_t)((p * 16 + lr) * AST * 2 + c * 32) + lc);
                mma_f16(S[2 * p],     qf[c], bf[0], bf[2]);
                mma_f16(S[2 * p + 1], qf[c], bf[1], bf[3]);
            }
        }

        const bool diag = (s0 + 63 > wrow);
        const int rg0 = wrow + g, rg1 = wrow + g + 8;
#pragma unroll
        for (int j = 0; j < 8; j++) {
            int cg = s0 + j * 8 + 2 * tg;
            S[j][0] *= scale; S[j][1] *= scale;
            S[j][2] *= scale; S[j][3] *= scale;
            if (diag) {
                if (cg     > rg0) S[j][0] = -1e30f;
                if (cg + 1 > rg0) S[j][1] = -1e30f;
                if (cg     > rg1) S[j][2] = -1e30f;
                if (cg + 1 > rg1) S[j][3] = -1e30f;
            }
        }

        float tm0 = -1e30f, tm1 = -1e30f;
#pragma unroll
        for (int j = 0; j < 8; j++) {
            tm0 = fmaxf(tm0, fmaxf(S[j][0], S[j][1]));
            tm1 = fmaxf(tm1, fmaxf(S[j][2], S[j][3]));
        }
        tm0 = fmaxf(tm0, __shfl_xor_sync(0xFFFFFFFFu, tm0, 1));
        tm0 = fmaxf(tm0, __shfl_xor_sync(0xFFFFFFFFu, tm0, 2));
        tm1 = fmaxf(tm1, __shfl_xor_sync(0xFFFFFFFFu, tm1, 1));
        tm1 = fmaxf(tm1, __shfl_xor_sync(0xFFFFFFFFu, tm1, 2));
        float nm0 = fmaxf(m0, tm0), nm1 = fmaxf(m1, tm1);
        float cor0 = __expf(m0 - nm0), cor1 = __expf(m1 - nm1);
        float ts0 = 0.f, ts1 = 0.f;
#pragma unroll
        for (int j = 0; j < 8; j++) {
            S[j][0] = __expf(S[j][0] - nm0); ts0 += S[j][0];
            S[j][1] = __expf(S[j][1] - nm0); ts0 += S[j][1];
            S[j][2] = __expf(S[j][2] - nm1); ts1 += S[j][2];
            S[j][3] = __expf(S[j][3] - nm1); ts1 += S[j][3];
        }
        ts0 += __shfl_xor_sync(0xFFFFFFFFu, ts0, 1);
        ts0 += __shfl_xor_sync(0xFFFFFFFFu, ts0, 2);
        ts1 += __shfl_xor_sync(0xFFFFFFFFu, ts1, 1);
        ts1 += __shfl_xor_sync(0xFFFFFFFFu, ts1, 2);
        l0 = l0 * cor0 + ts0;  l1 = l1 * cor1 + ts1;
        m0 = nm0;  m1 = nm1;
#pragma unroll
        for (int j = 0; j < 8; j++) {
            O[j][0] *= cor0; O[j][1] *= cor0;
            O[j][2] *= cor1; O[j][3] *= cor1;
        }

        uint32_t pf[4][4];
#pragma unroll
        for (int c = 0; c < 4; c++) {
            pf[c][0] = packh2(S[2 * c][0],     S[2 * c][1]);
            pf[c][1] = packh2(S[2 * c][2],     S[2 * c][3]);
            pf[c][2] = packh2(S[2 * c + 1][0], S[2 * c + 1][1]);
            pf[c][3] = packh2(S[2 * c + 1][2], S[2 * c + 1][3]);
        }

#pragma unroll
        for (int p = 0; p < 4; p++) {
#pragma unroll
            for (int c = 0; c < 4; c++) {
                uint32_t bf[4];
                ldm4(bf, vb + (uint32_t)((p * 16 + lr) * AST * 2 + c * 32) + lc);
                mma_f16(O[2 * p],     pf[c], bf[0], bf[2]);
                mma_f16(O[2 * p + 1], pf[c], bf[1], bf[3]);
            }
        }
    }

    float i0 = 1.f / l0, i1 = 1.f / l1;
    int qrow = qt * 128 + w * 16 + g;
    size_t ob0 = (size_t)(b * NT + qrow) * ND + h * NHD;
    size_t ob1 = ob0 + (size_t)8 * ND;
#pragma unroll
    for (int j = 0; j < 8; j++) {
        int cc = j * 8 + 2 * tg;
        *(__half2*)(out + ob0 + cc) = __floats2half2_rn(O[j][0] * i0, O[j][1] * i0);
        *(__half2*)(out + ob1 + cc) = __floats2half2_rn(O[j][2] * i1, O[j][3] * i1);
    }
}

// ---------------------------------------------------------------------------
extern "C" void kernel_launch(void* const* d_in, const int* in_sizes, int n_in,
                              void* d_out, int out_size)
{
    const int*   idx   = (const int*)  d_in[0];
    const float* tok   = (const float*)d_in[1];
    const float* pos   = (const float*)d_in[2];
    const float* Wq    = (const float*)d_in[3];
    const float* Wk    = (const float*)d_in[4];
    const float* Wv    = (const float*)d_in[5];
    const float* Wproj = (const float*)d_in[6];
    const float* bproj = (const float*)d_in[7];
    const float* W1    = (const float*)d_in[8];
    const float* b1    = (const float*)d_in[9];
    const float* W2    = (const float*)d_in[10];
    const float* b2    = (const float*)d_in[11];
    const float* ln1g  = (const float*)d_in[12];
    const float* ln1b  = (const float*)d_in[13];
    const float* ln2g  = (const float*)d_in[14];
    const float* ln2b  = (const float*)d_in[15];
    const float* lnfg  = (const float*)d_in[16];
    const float* lnfb  = (const float*)d_in[17];
    const float* Whead = (const float*)d_in[18];
    const float* bhead = (const float*)d_in[19];
    float* out = (float*)d_out;

    float  *px;
    __half *ph, *pqkv, *pvT, *pa, *pm, *pw;
    cudaGetSymbolAddress((void**)&px,   g_x);
    cudaGetSymbolAddress((void**)&ph,   g_h16);
    cudaGetSymbolAddress((void**)&pqkv, g_qkv);
    cudaGetSymbolAddress((void**)&pvT,  g_vT);
    cudaGetSymbolAddress((void**)&pa,   g_att);
    cudaGetSymbolAddress((void**)&pm,   g_hid);
    cudaGetSymbolAddress((void**)&pw,   g_wT);

    static int attr_done = 0;
    if (!attr_done) {
        cudaFuncSetAttribute(hgemm<128, false, false, true, true>,
                             cudaFuncAttributeMaxDynamicSharedMemorySize, smbytes(128));
        cudaFuncSetAttribute(hgemm<64, false, true, false, false>,
                             cudaFuncAttributeMaxDynamicSharedMemorySize, smbytes(64));
        cudaFuncSetAttribute(hgemm<128, true, false, true, false>,
                             cudaFuncAttributeMaxDynamicSharedMemorySize, smbytes(128));
        cudaFuncSetAttribute(hgemm<64, false, false, false, false>,
                             cudaFuncAttributeMaxDynamicSharedMemorySize, smbytes(64));
        attr_done = 1;
    }

    // Weight prep: tiled transpose -> K-major [N,K] fp16
    {
        dim3 blk(32, 8);
        dim3 gqv(NHD / 32, ND / 32, NL * NH);
        size_t ssA = (size_t)NH * ND * NHD, ssB = (size_t)ND * NHD;
        size_t dsA = (size_t)NQKV * ND,     dsB = (size_t)NHD * ND;
        transpose_kernel<<<gqv, blk>>>(Wq, pw + OFF_QKV,                       ND, NHD, NH, ssA, ssB, dsA, dsB);
        transpose_kernel<<<gqv, blk>>>(Wk, pw + OFF_QKV + (size_t)ND * ND,     ND, NHD, NH, ssA, ssB, dsA, dsB);
        transpose_kernel<<<gqv, blk>>>(Wv, pw + OFF_QKV + (size_t)2 * ND * ND, ND, NHD, NH, ssA, ssB, dsA, dsB);
        transpose_kernel<<<dim3(ND / 32, ND / 32, NL), blk>>>(
            Wproj, pw + OFF_PROJ, ND, ND, 1, (size_t)ND * ND, 0, (size_t)ND * ND, 0);
        transpose_kernel<<<dim3(ND4 / 32, ND / 32, NL), blk>>>(
            W1, pw + OFF_W1, ND, ND4, 1, (size_t)ND * ND4, 0, (size_t)ND * ND4, 0);
        transpose_kernel<<<dim3(ND / 32, ND4 / 32, NL), blk>>>(
            W2, pw + OFF_W2, ND4, ND, 1, (size_t)ND * ND4, 0, (size_t)ND * ND4, 0);
        transpose_kernel<<<dim3((NV + 31) / 32, ND / 32, 1), blk>>>(
            Whead, pw + OFF_HEAD, ND, NV, 1, 0, 0, 0, 0);
    }

    // Fused embedding + layer-0 ln1
    embed_ln_kernel<<<MT / 8, 256>>>(idx, tok, pos, ln1g, ln1b, px, ph);

    dim3 gQKV(NQKV / 128, MT / 128);
    dim3 gP  (ND   / 128, MT / 64);     // BM=64 grids (proj, W2)
    dim3 g4  (ND4  / 128, MT / 128);
    dim3 gH  (1, MT / 64);              // head at BM=64

    for (int l = 0; l < NL; l++) {
        if (l > 0)
            ln_kernel<<<MT / 8, 256>>>(px, ln1g + l * ND, ln1b + l * ND, ph);

        hgemm<128, false, false, true, true><<<gQKV, 128, smbytes(128)>>>(
            ph, pw + OFF_QKV + (size_t)l * NQKV * ND,
            nullptr, (const float*)pvT, pqkv, NQKV, ND);

        fattn_kernel<<<dim3(NB * NH, NT / 128), 256>>>(pqkv, pvT, pa);

        hgemm<64, false, true, false, false><<<gP, 128, smbytes(64)>>>(
            pa, pw + OFF_PROJ + (size_t)l * ND * ND,
            bproj + l * ND, px, px, ND, ND);

        ln_kernel<<<MT / 8, 256>>>(px, ln2g + l * ND, ln2b + l * ND, ph);

        hgemm<128, true, false, true, false><<<g4, 128, smbytes(128)>>>(
            ph, pw + OFF_W1 + (size_t)l * ND4 * ND,
            b1 + l * ND4, nullptr, pm, ND4, ND);

        hgemm<64, false, true, false, false><<<gP, 128, smbytes(64)>>>(
            pm, pw + OFF_W2 + (size_t)l * ND * ND4,
            b2 + l * ND, px, px, ND, ND4);
    }

    ln_kernel<<<MT / 8, 256>>>(px, lnfg, lnfb, ph);
    hgemm<64, false, false, false, false><<<gH, 128, smbytes(64)>>>(
        ph, pw + OFF_HEAD, bhead, nullptr, out, NV, ND);
}

// round 13
// speedup vs baseline: 1.1386x; 1.0525x over previous
#include <cuda_runtime.h>
#include <cuda_fp16.h>
#include <cstdint>
#include <math.h>

// ---------------------------------------------------------------------------
// Problem constants
// ---------------------------------------------------------------------------
constexpr int NV  = 65;
constexpr int ND  = 384;
constexpr int NH  = 6;
constexpr int NHD = 64;
constexpr int NL  = 6;
constexpr int NT  = 256;
constexpr int NB  = 64;
constexpr int MT  = NB * NT;       // 16384
constexpr int ND4 = 4 * ND;        // 1536
constexpr int NQKV = 3 * ND;       // 1152

// ---------------------------------------------------------------------------
// Scratch (__device__ globals; allocation-free)
// ---------------------------------------------------------------------------
__device__ float  g_x   [MT * ND];      // fp32 residual stream
__device__ __half g_h16 [MT * ND];      // LN output (GEMM A)
__device__ __half g_qkv [MT * NQKV];    // q|k packed (v region unused)
__device__ __half g_vT  [NB * NH * NHD * NT];  // V transposed per (b,h): [hd][t]
__device__ __half g_att [MT * ND];
__device__ __half g_hid [MT * ND4];

constexpr size_t OFF_QKV  = 0;
constexpr size_t OFF_PROJ = OFF_QKV  + (size_t)NL * NQKV * ND;
constexpr size_t OFF_W1   = OFF_PROJ + (size_t)NL * ND * ND;
constexpr size_t OFF_W2   = OFF_W1   + (size_t)NL * ND4 * ND;
constexpr size_t OFF_HEAD = OFF_W2   + (size_t)NL * ND * ND4;
constexpr size_t WT_TOTAL = OFF_HEAD + (size_t)NV * ND;
__device__ __half g_wT[WT_TOTAL];

// ---------------------------------------------------------------------------
// Helpers
// ---------------------------------------------------------------------------
__device__ __forceinline__ uint32_t smem_u32(const void* p) {
    uint32_t a;
    asm("{ .reg .u64 t; cvta.to.shared.u64 t, %1; cvt.u32.u64 %0, t; }"
        : "=r"(a) : "l"(p));
    return a;
}
__device__ __forceinline__ void cp16(uint32_t dst, const void* src, int srcsize) {
    asm volatile("cp.async.cg.shared.global [%0], [%1], 16, %2;"
                 :: "r"(dst), "l"(src), "r"(srcsize) : "memory");
}
__device__ __forceinline__ void cp16f(uint32_t dst, const void* src) {
    asm volatile("cp.async.cg.shared.global [%0], [%1], 16;"
                 :: "r"(dst), "l"(src) : "memory");
}
__device__ __forceinline__ void cp_commit() {
    asm volatile("cp.async.commit_group;" ::: "memory");
}
__device__ __forceinline__ void ldm4(uint32_t* r, uint32_t a) {
    asm volatile("ldmatrix.sync.aligned.m8n8.x4.shared.b16 {%0,%1,%2,%3}, [%4];"
                 : "=r"(r[0]), "=r"(r[1]), "=r"(r[2]), "=r"(r[3]) : "r"(a));
}
__device__ __forceinline__ void mma_f16(float* c, const uint32_t* a,
                                        uint32_t b0, uint32_t b1) {
    asm volatile(
        "mma.sync.aligned.m16n8k16.row.col.f32.f16.f16.f32 "
        "{%0,%1,%2,%3}, {%4,%5,%6,%7}, {%8,%9}, {%0,%1,%2,%3};"
        : "+f"(c[0]), "+f"(c[1]), "+f"(c[2]), "+f"(c[3])
        : "r"(a[0]), "r"(a[1]), "r"(a[2]), "r"(a[3]), "r"(b0), "r"(b1));
}
__device__ __forceinline__ uint32_t packh2(float x, float y) {
    __half2 h = __floats2half2_rn(x, y);
    return *reinterpret_cast<uint32_t*>(&h);
}

// ---------------------------------------------------------------------------
// Fused embedding + LayerNorm (layer-0 ln1)
// ---------------------------------------------------------------------------
__global__ __launch_bounds__(256) void embed_ln_kernel(
    const int* __restrict__ idx,
    const float* __restrict__ tok,
    const float* __restrict__ pos,
    const float* __restrict__ g,
    const float* __restrict__ bb,
    float* __restrict__ px,
    __half* __restrict__ outh)
{
    int w = threadIdx.x >> 5, lane = threadIdx.x & 31;
    int row = blockIdx.x * 8 + w;
    int token = idx[row];
    const float* tr = tok + (size_t)token * ND;
    const float* pr = pos + (size_t)(row % NT) * ND;

    float4 xv[3];
    float s1 = 0.f, s2 = 0.f;
#pragma unroll
    for (int j = 0; j < 3; j++) {
        int c = lane * 4 + j * 128;
        float4 tv = *(const float4*)(tr + c);
        float4 pv = *(const float4*)(pr + c);
        float4 v = { tv.x + pv.x, tv.y + pv.y, tv.z + pv.z, tv.w + pv.w };
        xv[j] = v;
        *(float4*)(px + (size_t)row * ND + c) = v;
        s1 += v.x + v.y + v.z + v.w;
        s2 += v.x * v.x + v.y * v.y + v.z * v.z + v.w * v.w;
    }
#pragma unroll
    for (int o = 16; o > 0; o >>= 1) {
        s1 += __shfl_xor_sync(0xFFFFFFFFu, s1, o);
        s2 += __shfl_xor_sync(0xFFFFFFFFu, s2, o);
    }
    float mean = s1 * (1.f / ND);
    float var  = s2 * (1.f / ND) - mean * mean;
    float rstd = rsqrtf(var + 1e-3f);
#pragma unroll
    for (int j = 0; j < 3; j++) {
        int c = lane * 4 + j * 128;
        float4 gv = *(const float4*)(g + c);
        float4 bv = *(const float4*)(bb + c);
        __half2 h0 = __floats2half2_rn((xv[j].x - mean) * rstd * gv.x + bv.x,
                                       (xv[j].y - mean) * rstd * gv.y + bv.y);
        __half2 h1 = __floats2half2_rn((xv[j].z - mean) * rstd * gv.z + bv.z,
                                       (xv[j].w - mean) * rstd * gv.w + bv.w);
        *(__half2*)(outh + (size_t)row * ND + c)     = h0;
        *(__half2*)(outh + (size_t)row * ND + c + 2) = h1;
    }
}

// ---------------------------------------------------------------------------
// LayerNorm (eps 1e-3), warp-per-row, fp32 in -> fp16 out
// ---------------------------------------------------------------------------
__global__ __launch_bounds__(256) void ln_kernel(const float* __restrict__ x,
                                                 const float* __restrict__ g,
                                                 const float* __restrict__ bb,
                                                 __half* __restrict__ out)
{
    int w = threadIdx.x >> 5, lane = threadIdx.x & 31;
    int row = blockIdx.x * 8 + w;
    const float* xr = x + (size_t)row * ND;

    float4 xv[3];
    float s1 = 0.f, s2 = 0.f;
#pragma unroll
    for (int j = 0; j < 3; j++) {
        float4 v = *(const float4*)(xr + lane * 4 + j * 128);
        xv[j] = v;
        s1 += v.x + v.y + v.z + v.w;
        s2 += v.x * v.x + v.y * v.y + v.z * v.z + v.w * v.w;
    }
#pragma unroll
    for (int o = 16; o > 0; o >>= 1) {
        s1 += __shfl_xor_sync(0xFFFFFFFFu, s1, o);
        s2 += __shfl_xor_sync(0xFFFFFFFFu, s2, o);
    }
    float mean = s1 * (1.f / ND);
    float var  = s2 * (1.f / ND) - mean * mean;
    float rstd = rsqrtf(var + 1e-3f);
#pragma unroll
    for (int j = 0; j < 3; j++) {
        int c = lane * 4 + j * 128;
        float4 gv = *(const float4*)(g + c);
        float4 bv = *(const float4*)(bb + c);
        __half2 h0 = __floats2half2_rn((xv[j].x - mean) * rstd * gv.x + bv.x,
                                       (xv[j].y - mean) * rstd * gv.y + bv.y);
        __half2 h1 = __floats2half2_rn((xv[j].z - mean) * rstd * gv.z + bv.z,
                                       (xv[j].w - mean) * rstd * gv.w + bv.w);
        *(__half2*)(out + (size_t)row * ND + c)     = h0;
        *(__half2*)(out + (size_t)row * ND + c + 2) = h1;
    }
}

// ---------------------------------------------------------------------------
// Tiled transpose: src [R,C] fp32 (+batch offsets) -> dst [C,R] fp16.
// ---------------------------------------------------------------------------
__global__ void transpose_kernel(const float* __restrict__ src,
                                 __half* __restrict__ dst,
                                 int R, int C, int div,
                                 size_t ssA, size_t ssB,
                                 size_t dsA, size_t dsB)
{
    __shared__ float tile[32][33];
    int z = blockIdx.z;
    const float* s = src + (z / div) * ssA + (z % div) * ssB;
    __half* d = dst + (z / div) * dsA + (z % div) * dsB;
    int c0 = blockIdx.x * 32, r0 = blockIdx.y * 32;
#pragma unroll
    for (int j = 0; j < 4; j++) {
        int r = r0 + threadIdx.y + j * 8, c = c0 + threadIdx.x;
        if (r < R && c < C)
            tile[threadIdx.y + j * 8][threadIdx.x] = s[(size_t)r * C + c];
    }
    __syncthreads();
#pragma unroll
    for (int j = 0; j < 4; j++) {
        int c = c0 + threadIdx.y + j * 8, r = r0 + threadIdx.x;
        if (c < C && r < R)
            d[(size_t)c * R + r] = __float2half(tile[threadIdx.x][threadIdx.y + j * 8]);
    }
}

// ---------------------------------------------------------------------------
// hgemm (TK=32, round-8 proven): BM=64 (proj/W2/head).
// ---------------------------------------------------------------------------
constexpr int NSTAGE = 4;
constexpr int smbytes(int BM) { return NSTAGE * (BM + 128) * 80; }

template <int BM, bool RELU, bool RESID, bool OUTH>
__global__ __launch_bounds__(128, BM == 64 ? 3 : 1) void hgemm(
    const __half* __restrict__ A, const __half* __restrict__ B,
    const float* __restrict__ bias, const float* __restrict__ resid,
    void* __restrict__ Cv, int N, int K)
{
    constexpr int AF = BM / 32;
    extern __shared__ __half smh[];
    __shared__ float sbias[128];
    const int tid = threadIdx.x;
    const int row0 = blockIdx.y * BM;
    const int col0 = blockIdx.x * 128;

    const uint32_t base = smem_u32(smh);
    uint32_t aAu[NSTAGE], aBu[NSTAGE];
#pragma unroll
    for (int s = 0; s < NSTAGE; s++) {
        aAu[s] = base + s * BM * 80;
        aBu[s] = base + NSTAGE * BM * 80 + s * 128 * 80;
    }

    {
        int c = col0 + tid;
        sbias[tid] = (bias && c < N) ? bias[c] : 0.f;
    }

    const int KT = K / 32;

    auto prefetch = [&](int kt, int s) {
#pragma unroll
        for (int i = 0; i < BM / 32; i++) {
            int slot = tid + i * 128;
            int r = slot >> 2, c8 = slot & 3;
            cp16(aAu[s] + (uint32_t)(r * 80 + c8 * 16),
                 A + (size_t)(row0 + r) * K + kt * 32 + c8 * 8, 16);
        }
#pragma unroll
        for (int i = 0; i < 4; i++) {
            int slot = tid + i * 128;
            int r = slot >> 2, c8 = slot & 3;
            int n = col0 + r;
            cp16(aBu[s] + (uint32_t)(r * 80 + c8 * 16),
                 B + (size_t)(n < N ? n : N - 1) * K + kt * 32 + c8 * 8,
                 n < N ? 16 : 0);
        }
        cp_commit();
    };

    const int w = tid >> 5, lane = tid & 31;
    const int wm = (w & 1) * (BM / 2);
    const int wn = (w >> 1) * 64;
    const int g = lane >> 2, tg = lane & 3;
    const int lr = lane & 15, lc = (lane >> 4) * 16;

    float acc[AF][8][4];
#pragma unroll
    for (int i = 0; i < AF; i++)
#pragma unroll
        for (int j = 0; j < 8; j++)
#pragma unroll
            for (int q = 0; q < 4; q++) acc[i][j][q] = 0.f;

    prefetch(0, 0); prefetch(1, 1); prefetch(2, 2);

    for (int kt = 0; kt < KT; kt++) {
        int rem = KT - 1 - kt;
        if (rem >= 2)      asm volatile("cp.async.wait_group 2;" ::: "memory");
        else if (rem == 1) asm volatile("cp.async.wait_group 1;" ::: "memory");
        else               asm volatile("cp.async.wait_group 0;" ::: "memory");
        __syncthreads();

        if (kt + 3 < KT) prefetch(kt + 3, (kt + 3) & 3);

        uint32_t bA = aAu[kt & 3], bB = aBu[kt & 3];
#pragma unroll
        for (int ks = 0; ks < 2; ks++) {
            uint32_t a[AF][4];
#pragma unroll
            for (int i = 0; i < AF; i++)
                ldm4(a[i], bA + (uint32_t)((wm + 16 * i + lr) * 80 + ks * 32 + lc));
            uint32_t b[4][4];
#pragma unroll
            for (int p = 0; p < 4; p++)
                ldm4(b[p], bB + (uint32_t)((wn + 16 * p + lr) * 80 + ks * 32 + lc));
#pragma unroll
            for (int i = 0; i < AF; i++)
#pragma unroll
                for (int p = 0; p < 4; p++) {
                    mma_f16(acc[i][2 * p],     a[i], b[p][0], b[p][2]);
                    mma_f16(acc[i][2 * p + 1], a[i], b[p][1], b[p][3]);
                }
        }
    }

    const bool vec = (N & 127) == 0;
    float*  Cf = (float*)Cv;
    __half* Ch = (__half*)Cv;
#pragma unroll
    for (int i = 0; i < AF; i++) {
#pragma unroll
        for (int half_ = 0; half_ < 2; half_++) {
            int r = row0 + wm + 16 * i + g + 8 * half_;
#pragma unroll
            for (int j = 0; j < 8; j++) {
                int cl = wn + 8 * j + 2 * tg;
                int c = col0 + cl;
                float2 v = { acc[i][j][half_ * 2], acc[i][j][half_ * 2 + 1] };
                v.x += sbias[cl]; v.y += sbias[cl + 1];
                if (RELU) { v.x = fmaxf(v.x, 0.f); v.y = fmaxf(v.y, 0.f); }
                if (OUTH) {
                    *(__half2*)&Ch[(size_t)r * N + c] = __floats2half2_rn(v.x, v.y);
                } else if (vec) {
                    if (RESID) {
                        float2 rv = *(const float2*)&resid[(size_t)r * N + c];
                        v.x += rv.x; v.y += rv.y;
                    }
                    *(float2*)&Cf[(size_t)r * N + c] = v;
                } else {
                    if (c < N)     Cf[(size_t)r * N + c]     = v.x;
                    if (c + 1 < N) Cf[(size_t)r * N + c + 1] = v.y;
                }
            }
        }
    }
}

// ---------------------------------------------------------------------------
// hgemm2 (TK=64, 3-stage): BM=128, N multiple of 128 (QKV, W1).
// 144B padded rows; 6 mainloop iterations for K=384.
// VSPLIT: QKV col blocks >= 768 stored transposed to vT.
// ---------------------------------------------------------------------------
constexpr int SMB_G2 = 3 * 256 * 144;   // 110592

template <bool RELU, bool VSPLIT>
__global__ __launch_bounds__(128) void hgemm2(
    const __half* __restrict__ A, const __half* __restrict__ B,
    const float* __restrict__ bias, __half* __restrict__ vtp,
    __half* __restrict__ Ch, int N, int K)
{
    extern __shared__ __half smh[];
    __shared__ float sbias[128];
    const int tid = threadIdx.x;
    const int row0 = blockIdx.y * 128;
    const int col0 = blockIdx.x * 128;

    const uint32_t base = smem_u32(smh);
    uint32_t aAu[3], aBu[3];
#pragma unroll
    for (int s = 0; s < 3; s++) {
        aAu[s] = base + s * 128 * 144;
        aBu[s] = base + 3 * 128 * 144 + s * 128 * 144;
    }

    sbias[tid] = bias ? bias[col0 + tid] : 0.f;

    const int KT = K / 64;

    auto prefetch = [&](int kt, int s) {
#pragma unroll
        for (int i = 0; i < 8; i++) {
            int slot = tid + i * 128;          // 0..1023
            int r = slot >> 3, c8 = slot & 7;
            cp16f(aAu[s] + (uint32_t)(r * 144 + c8 * 16),
                  A + (size_t)(row0 + r) * K + kt * 64 + c8 * 8);
        }
#pragma unroll
        for (int i = 0; i < 8; i++) {
            int slot = tid + i * 128;
            int r = slot >> 3, c8 = slot & 7;
            cp16f(aBu[s] + (uint32_t)(r * 144 + c8 * 16),
                  B + (size_t)(col0 + r) * K + kt * 64 + c8 * 8);
        }
        cp_commit();
    };

    const int w = tid >> 5, lane = tid & 31;
    const int wm = (w & 1) * 64;
    const int wn = (w >> 1) * 64;
    const int g = lane >> 2, tg = lane & 3;
    const int lr = lane & 15, lc = (lane >> 4) * 16;

    float acc[4][8][4];
#pragma unroll
    for (int i = 0; i < 4; i++)
#pragma unroll
        for (int j = 0; j < 8; j++)
#pragma unroll
            for (int q = 0; q < 4; q++) acc[i][j][q] = 0.f;

    prefetch(0, 0); prefetch(1, 1);

    for (int kt = 0; kt < KT; kt++) {
        if (kt + 1 < KT) asm volatile("cp.async.wait_group 1;" ::: "memory");
        else             asm volatile("cp.async.wait_group 0;" ::: "memory");
        __syncthreads();

        if (kt + 2 < KT) {
            int s = (kt + 2) % 3;
            prefetch(kt + 2, s);
        }

        uint32_t bA = aAu[kt % 3], bB = aBu[kt % 3];
#pragma unroll
        for (int ks = 0; ks < 4; ks++) {
            uint32_t a[4][4];
#pragma unroll
            for (int i = 0; i < 4; i++)
                ldm4(a[i], bA + (uint32_t)((wm + 16 * i + lr) * 144 + ks * 32 + lc));
            uint32_t b[4][4];
#pragma unroll
            for (int p = 0; p < 4; p++)
                ldm4(b[p], bB + (uint32_t)((wn + 16 * p + lr) * 144 + ks * 32 + lc));
#pragma unroll
            for (int i = 0; i < 4; i++)
#pragma unroll
                for (int p = 0; p < 4; p++) {
                    mma_f16(acc[i][2 * p],     a[i], b[p][0], b[p][2]);
                    mma_f16(acc[i][2 * p + 1], a[i], b[p][1], b[p][3]);
                }
        }
    }

#pragma unroll
    for (int i = 0; i < 4; i++) {
#pragma unroll
        for (int half_ = 0; half_ < 2; half_++) {
            int r = row0 + wm + 16 * i + g + 8 * half_;
#pragma unroll
            for (int j = 0; j < 8; j++) {
                int cl = wn + 8 * j + 2 * tg;
                int c = col0 + cl;
                float2 v = { acc[i][j][half_ * 2], acc[i][j][half_ * 2 + 1] };
                v.x += sbias[cl]; v.y += sbias[cl + 1];
                if (RELU) { v.x = fmaxf(v.x, 0.f); v.y = fmaxf(v.y, 0.f); }
                if (VSPLIT && col0 >= 2 * ND) {
                    int cc = c - 2 * ND;
                    int hh = cc >> 6, hd = cc & 63;
                    int bb2 = r >> 8, tt = r & 255;
                    size_t vbse = ((size_t)(bb2 * NH + hh) * NHD + hd) * NT + tt;
                    vtp[vbse]      = __float2half(v.x);
                    vtp[vbse + NT] = __float2half(v.y);
                } else {
                    *(__half2*)&Ch[(size_t)r * N + c] = __floats2half2_rn(v.x, v.y);
                }
            }
        }
    }
}

// ---------------------------------------------------------------------------
// Flash attention. Block = (b*NH+h, qtile of 128); 8 warps x 16 rows.
// KV tile 128 (two 64-wide inner passes, same update order as before).
// ---------------------------------------------------------------------------
constexpr int AST = 72;    // K/Q row stride (halves)
constexpr int VST = 136;   // V row stride (halves): 128 data + 8 pad (272 B)

__global__ __launch_bounds__(256) void fattn_kernel(
    const __half* __restrict__ qkv, const __half* __restrict__ vT,
    __half* __restrict__ out)
{
    __shared__ __half sQ[128 * AST], sK[128 * AST], sV[64 * VST];
    const int bh = blockIdx.x, qt = blockIdx.y;
    const int b = bh / NH, h = bh - b * NH;
    const int tid = threadIdx.x, w = tid >> 5, lane = tid & 31;
    const int g = lane >> 2, tg = lane & 3;
    const int lr = lane & 15;
    const uint32_t lc = (lane >> 4) * 16;

    const uint32_t qb = smem_u32(sQ), kb = smem_u32(sK), vb = smem_u32(sV);

    // Load Q tile [128 q][64 hd]
    for (int i = tid; i < 1024; i += 256) {
        int r = i >> 3, c8 = i & 7;
        cp16f(qb + (uint32_t)(r * AST * 2 + c8 * 16),
              qkv + (size_t)(b * NT + qt * 128 + r) * NQKV + h * NHD + c8 * 8);
    }
    cp_commit();
    asm volatile("cp.async.wait_group 0;" ::: "memory");
    __syncthreads();

    uint32_t qf[4][4];
#pragma unroll
    for (int c = 0; c < 4; c++)
        ldm4(qf[c], qb + (uint32_t)((w * 16 + lr) * AST * 2 + c * 32) + lc);

    float O[8][4];
#pragma unroll
    for (int j = 0; j < 8; j++)
#pragma unroll
        for (int q = 0; q < 4; q++) O[j][q] = 0.f;
    float m0 = -1e30f, m1 = -1e30f, l0 = 0.f, l1 = 0.f;
    const float scale = rsqrtf((float)ND);

    const int wrow = qt * 128 + w * 16;

    for (int s0 = 0; s0 <= qt * 128; s0 += 128) {
        __syncthreads();
        // K: 128 rows x 64 hd; V^T: 64 hd rows x 128 t cols
        for (int i = tid; i < 1024; i += 256) {
            int r = i >> 3, c8 = i & 7;
            cp16f(kb + (uint32_t)(r * AST * 2 + c8 * 16),
                  qkv + (size_t)(b * NT + s0 + r) * NQKV + ND + h * NHD + c8 * 8);
        }
        for (int i = tid; i < 1024; i += 256) {
            int r = i >> 4, c16 = i & 15;
            cp16f(vb + (uint32_t)(r * VST * 2 + c16 * 16),
                  vT + ((size_t)bh * NHD + r) * NT + s0 + c16 * 8);
        }
        cp_commit();
        asm volatile("cp.async.wait_group 0;" ::: "memory");
        __syncthreads();

#pragma unroll
        for (int hh = 0; hh < 2; hh++) {
            const int s0h = s0 + hh * 64;
            if (s0h > wrow + 15) continue;   // fully masked for this warp

            float S[8][4];
#pragma unroll
            for (int j = 0; j < 8; j++)
                S[j][0] = S[j][1] = S[j][2] = S[j][3] = 0.f;
#pragma unroll
            for (int p = 0; p < 4; p++) {
#pragma unroll
                for (int c = 0; c < 4; c++) {
                    uint32_t bf[4];
                    ldm4(bf, kb + (uint32_t)((hh * 64 + p * 16 + lr) * AST * 2 + c * 32) + lc);
                    mma_f16(S[2 * p],     qf[c], bf[0], bf[2]);
                    mma_f16(S[2 * p + 1], qf[c], bf[1], bf[3]);
                }
            }

            const bool diag = (s0h + 63 > wrow);
            const int rg0 = wrow + g, rg1 = wrow + g + 8;
#pragma unroll
            for (int j = 0; j < 8; j++) {
                int cg = s0h + j * 8 + 2 * tg;
                S[j][0] *= scale; S[j][1] *= scale;
                S[j][2] *= scale; S[j][3] *= scale;
                if (diag) {
                    if (cg     > rg0) S[j][0] = -1e30f;
                    if (cg + 1 > rg0) S[j][1] = -1e30f;
                    if (cg     > rg1) S[j][2] = -1e30f;
                    if (cg + 1 > rg1) S[j][3] = -1e30f;
                }
            }

            float tm0 = -1e30f, tm1 = -1e30f;
#pragma unroll
            for (int j = 0; j < 8; j++) {
                tm0 = fmaxf(tm0, fmaxf(S[j][0], S[j][1]));
                tm1 = fmaxf(tm1, fmaxf(S[j][2], S[j][3]));
            }
            tm0 = fmaxf(tm0, __shfl_xor_sync(0xFFFFFFFFu, tm0, 1));
            tm0 = fmaxf(tm0, __shfl_xor_sync(0xFFFFFFFFu, tm0, 2));
            tm1 = fmaxf(tm1, __shfl_xor_sync(0xFFFFFFFFu, tm1, 1));
            tm1 = fmaxf(tm1, __shfl_xor_sync(0xFFFFFFFFu, tm1, 2));
            float nm0 = fmaxf(m0, tm0), nm1 = fmaxf(m1, tm1);
            float cor0 = __expf(m0 - nm0), cor1 = __expf(m1 - nm1);
            float ts0 = 0.f, ts1 = 0.f;
#pragma unroll
            for (int j = 0; j < 8; j++) {
                S[j][0] = __expf(S[j][0] - nm0); ts0 += S[j][0];
                S[j][1] = __expf(S[j][1] - nm0); ts0 += S[j][1];
                S[j][2] = __expf(S[j][2] - nm1); ts1 += S[j][2];
                S[j][3] = __expf(S[j][3] - nm1); ts1 += S[j][3];
            }
            ts0 += __shfl_xor_sync(0xFFFFFFFFu, ts0, 1);
            ts0 += __shfl_xor_sync(0xFFFFFFFFu, ts0, 2);
            ts1 += __shfl_xor_sync(0xFFFFFFFFu, ts1, 1);
            ts1 += __shfl_xor_sync(0xFFFFFFFFu, ts1, 2);
            l0 = l0 * cor0 + ts0;  l1 = l1 * cor1 + ts1;
            m0 = nm0;  m1 = nm1;
#pragma unroll
            for (int j = 0; j < 8; j++) {
                O[j][0] *= cor0; O[j][1] *= cor0;
                O[j][2] *= cor1; O[j][3] *= cor1;
            }

            uint32_t pf[4][4];
#pragma unroll
            for (int c = 0; c < 4; c++) {
                pf[c][0] = packh2(S[2 * c][0],     S[2 * c][1]);
                pf[c][1] = packh2(S[2 * c][2],     S[2 * c][3]);
                pf[c][2] = packh2(S[2 * c + 1][0], S[2 * c + 1][1]);
                pf[c][3] = packh2(S[2 * c + 1][2], S[2 * c + 1][3]);
            }

#pragma unroll
            for (int p = 0; p < 4; p++) {
#pragma unroll
                for (int c = 0; c < 4; c++) {
                    uint32_t bf[4];
                    ldm4(bf, vb + (uint32_t)((p * 16 + lr) * VST * 2 + hh * 128 + c * 32) + lc);
                    mma_f16(O[2 * p],     pf[c], bf[0], bf[2]);
                    mma_f16(O[2 * p + 1], pf[c], bf[1], bf[3]);
                }
            }
        }
    }

    float i0 = 1.f / l0, i1 = 1.f / l1;
    int qrow = qt * 128 + w * 16 + g;
    size_t ob0 = (size_t)(b * NT + qrow) * ND + h * NHD;
    size_t ob1 = ob0 + (size_t)8 * ND;
#pragma unroll
    for (int j = 0; j < 8; j++) {
        int cc = j * 8 + 2 * tg;
        *(__half2*)(out + ob0 + cc) = __floats2half2_rn(O[j][0] * i0, O[j][1] * i0);
        *(__half2*)(out + ob1 + cc) = __floats2half2_rn(O[j][2] * i1, O[j][3] * i1);
    }
}

// ---------------------------------------------------------------------------
extern "C" void kernel_launch(void* const* d_in, const int* in_sizes, int n_in,
                              void* d_out, int out_size)
{
    const int*   idx   = (const int*)  d_in[0];
    const float* tok   = (const float*)d_in[1];
    const float* pos   = (const float*)d_in[2];
    const float* Wq    = (const float*)d_in[3];
    const float* Wk    = (const float*)d_in[4];
    const float* Wv    = (const float*)d_in[5];
    const float* Wproj = (const float*)d_in[6];
    const float* bproj = (const float*)d_in[7];
    const float* W1    = (const float*)d_in[8];
    const float* b1    = (const float*)d_in[9];
    const float* W2    = (const float*)d_in[10];
    const float* b2    = (const float*)d_in[11];
    const float* ln1g  = (const float*)d_in[12];
    const float* ln1b  = (const float*)d_in[13];
    const float* ln2g  = (const float*)d_in[14];
    const float* ln2b  = (const float*)d_in[15];
    const float* lnfg  = (const float*)d_in[16];
    const float* lnfb  = (const float*)d_in[17];
    const float* Whead = (const float*)d_in[18];
    const float* bhead = (const float*)d_in[19];
    float* out = (float*)d_out;

    float  *px;
    __half *ph, *pqkv, *pvT, *pa, *pm, *pw;
    cudaGetSymbolAddress((void**)&px,   g_x);
    cudaGetSymbolAddress((void**)&ph,   g_h16);
    cudaGetSymbolAddress((void**)&pqkv, g_qkv);
    cudaGetSymbolAddress((void**)&pvT,  g_vT);
    cudaGetSymbolAddress((void**)&pa,   g_att);
    cudaGetSymbolAddress((void**)&pm,   g_hid);
    cudaGetSymbolAddress((void**)&pw,   g_wT);

    static int attr_done = 0;
    if (!attr_done) {
        cudaFuncSetAttribute(hgemm2<false, true>,
                             cudaFuncAttributeMaxDynamicSharedMemorySize, SMB_G2);
        cudaFuncSetAttribute(hgemm2<true, false>,
                             cudaFuncAttributeMaxDynamicSharedMemorySize, SMB_G2);
        cudaFuncSetAttribute(hgemm<64, false, true, false>,
                             cudaFuncAttributeMaxDynamicSharedMemorySize, smbytes(64));
        cudaFuncSetAttribute(hgemm<64, false, false, false>,
                             cudaFuncAttributeMaxDynamicSharedMemorySize, smbytes(64));
        attr_done = 1;
    }

    // Weight prep: tiled transpose -> K-major [N,K] fp16
    {
        dim3 blk(32, 8);
        dim3 gqv(NHD / 32, ND / 32, NL * NH);
        size_t ssA = (size_t)NH * ND * NHD, ssB = (size_t)ND * NHD;
        size_t dsA = (size_t)NQKV * ND,     dsB = (size_t)NHD * ND;
        transpose_kernel<<<gqv, blk>>>(Wq, pw + OFF_QKV,                       ND, NHD, NH, ssA, ssB, dsA, dsB);
        transpose_kernel<<<gqv, blk>>>(Wk, pw + OFF_QKV + (size_t)ND * ND,     ND, NHD, NH, ssA, ssB, dsA, dsB);
        transpose_kernel<<<gqv, blk>>>(Wv, pw + OFF_QKV + (size_t)2 * ND * ND, ND, NHD, NH, ssA, ssB, dsA, dsB);
        transpose_kernel<<<dim3(ND / 32, ND / 32, NL), blk>>>(
            Wproj, pw + OFF_PROJ, ND, ND, 1, (size_t)ND * ND, 0, (size_t)ND * ND, 0);
        transpose_kernel<<<dim3(ND4 / 32, ND / 32, NL), blk>>>(
            W1, pw + OFF_W1, ND, ND4, 1, (size_t)ND * ND4, 0, (size_t)ND * ND4, 0);
        transpose_kernel<<<dim3(ND / 32, ND4 / 32, NL), blk>>>(
            W2, pw + OFF_W2, ND4, ND, 1, (size_t)ND * ND4, 0, (size_t)ND * ND4, 0);
        transpose_kernel<<<dim3((NV + 31) / 32, ND / 32, 1), blk>>>(
            Whead, pw + OFF_HEAD, ND, NV, 1, 0, 0, 0, 0);
    }

    // Fused embedding + layer-0 ln1
    embed_ln_kernel<<<MT / 8, 256>>>(idx, tok, pos, ln1g, ln1b, px, ph);

    dim3 gQKV(NQKV / 128, MT / 128);
    dim3 gP  (ND   / 128, MT / 64);     // BM=64 grids (proj, W2)
    dim3 g4  (ND4  / 128, MT / 128);
    dim3 gH  (1, MT / 64);              // head at BM=64

    for (int l = 0; l < NL; l++) {
        if (l > 0)
            ln_kernel<<<MT / 8, 256>>>(px, ln1g + l * ND, ln1b + l * ND, ph);

        hgemm2<false, true><<<gQKV, 128, SMB_G2>>>(
            ph, pw + OFF_QKV + (size_t)l * NQKV * ND,
            nullptr, pvT, pqkv, NQKV, ND);

        fattn_kernel<<<dim3(NB * NH, NT / 128), 256>>>(pqkv, pvT, pa);

        hgemm<64, false, true, false><<<gP, 128, smbytes(64)>>>(
            pa, pw + OFF_PROJ + (size_t)l * ND * ND,
            bproj + l * ND, px, px, ND, ND);

        ln_kernel<<<MT / 8, 256>>>(px, ln2g + l * ND, ln2b + l * ND, ph);

        hgemm2<true, false><<<g4, 128, SMB_G2>>>(
            ph, pw + OFF_W1 + (size_t)l * ND4 * ND,
            b1 + l * ND4, nullptr, pm, ND4, ND);

        hgemm<64, false, true, false><<<gP, 128, smbytes(64)>>>(
            pm, pw + OFF_W2 + (size_t)l * ND * ND4,
            b2 + l * ND, px, px, ND, ND4);
    }

    ln_kernel<<<MT / 8, 256>>>(px, lnfg, lnfb, ph);
    hgemm<64, false, false, false><<<gH, 128, smbytes(64)>>>(
        ph, pw + OFF_HEAD, bhead, nullptr, out, NV, ND);
}

// round 15
// speedup vs baseline: 1.1467x; 1.0071x over previous
#include <cuda_runtime.h>
#include <cuda_fp16.h>
#include <cstdint>
#include <math.h>

// ---------------------------------------------------------------------------
// Problem constants
// ---------------------------------------------------------------------------
constexpr int NV  = 65;
constexpr int ND  = 384;
constexpr int NH  = 6;
constexpr int NHD = 64;
constexpr int NL  = 6;
constexpr int NT  = 256;
constexpr int NB  = 64;
constexpr int MT  = NB * NT;       // 16384
constexpr int ND4 = 4 * ND;        // 1536
constexpr int NQKV = 3 * ND;       // 1152

// ---------------------------------------------------------------------------
// Scratch (__device__ globals; allocation-free)
// ---------------------------------------------------------------------------
__device__ float  g_x   [MT * ND];      // fp32 residual stream
__device__ __half g_h16 [MT * ND];      // LN output (GEMM A)
__device__ __half g_qkv [MT * NQKV];    // q|k packed (v region unused)
__device__ __half g_vT  [NB * NH * NHD * NT];  // V transposed per (b,h): [hd][t]
__device__ __half g_att [MT * ND];
__device__ __half g_hid [MT * ND4];

constexpr size_t OFF_QKV  = 0;
constexpr size_t OFF_PROJ = OFF_QKV  + (size_t)NL * NQKV * ND;
constexpr size_t OFF_W1   = OFF_PROJ + (size_t)NL * ND * ND;
constexpr size_t OFF_W2   = OFF_W1   + (size_t)NL * ND4 * ND;
constexpr size_t OFF_HEAD = OFF_W2   + (size_t)NL * ND * ND4;
constexpr size_t WT_TOTAL = OFF_HEAD + (size_t)NV * ND;
__device__ __half g_wT[WT_TOTAL];

// ---------------------------------------------------------------------------
// Helpers
// ---------------------------------------------------------------------------
__device__ __forceinline__ uint32_t smem_u32(const void* p) {
    uint32_t a;
    asm("{ .reg .u64 t; cvta.to.shared.u64 t, %1; cvt.u32.u64 %0, t; }"
        : "=r"(a) : "l"(p));
    return a;
}
__device__ __forceinline__ void cp16(uint32_t dst, const void* src, int srcsize) {
    asm volatile("cp.async.cg.shared.global [%0], [%1], 16, %2;"
                 :: "r"(dst), "l"(src), "r"(srcsize) : "memory");
}
__device__ __forceinline__ void cp16f(uint32_t dst, const void* src) {
    asm volatile("cp.async.cg.shared.global [%0], [%1], 16;"
                 :: "r"(dst), "l"(src) : "memory");
}
__device__ __forceinline__ void cp_commit() {
    asm volatile("cp.async.commit_group;" ::: "memory");
}
__device__ __forceinline__ void ldm4(uint32_t* r, uint32_t a) {
    asm volatile("ldmatrix.sync.aligned.m8n8.x4.shared.b16 {%0,%1,%2,%3}, [%4];"
                 : "=r"(r[0]), "=r"(r[1]), "=r"(r[2]), "=r"(r[3]) : "r"(a));
}
__device__ __forceinline__ void mma_f16(float* c, const uint32_t* a,
                                        uint32_t b0, uint32_t b1) {
    asm volatile(
        "mma.sync.aligned.m16n8k16.row.col.f32.f16.f16.f32 "
        "{%0,%1,%2,%3}, {%4,%5,%6,%7}, {%8,%9}, {%0,%1,%2,%3};"
        : "+f"(c[0]), "+f"(c[1]), "+f"(c[2]), "+f"(c[3])
        : "r"(a[0]), "r"(a[1]), "r"(a[2]), "r"(a[3]), "r"(b0), "r"(b1));
}
__device__ __forceinline__ uint32_t packh2(float x, float y) {
    __half2 h = __floats2half2_rn(x, y);
    return *reinterpret_cast<uint32_t*>(&h);
}

// ---------------------------------------------------------------------------
// Fused embedding + LayerNorm (layer-0 ln1)
// ---------------------------------------------------------------------------
__global__ __launch_bounds__(256) void embed_ln_kernel(
    const int* __restrict__ idx,
    const float* __restrict__ tok,
    const float* __restrict__ pos,
    const float* __restrict__ g,
    const float* __restrict__ bb,
    float* __restrict__ px,
    __half* __restrict__ outh)
{
    int w = threadIdx.x >> 5, lane = threadIdx.x & 31;
    int row = blockIdx.x * 8 + w;
    int token = idx[row];
    const float* tr = tok + (size_t)token * ND;
    const float* pr = pos + (size_t)(row % NT) * ND;

    float4 xv[3];
    float s1 = 0.f, s2 = 0.f;
#pragma unroll
    for (int j = 0; j < 3; j++) {
        int c = lane * 4 + j * 128;
        float4 tv = *(const float4*)(tr + c);
        float4 pv = *(const float4*)(pr + c);
        float4 v = { tv.x + pv.x, tv.y + pv.y, tv.z + pv.z, tv.w + pv.w };
        xv[j] = v;
        *(float4*)(px + (size_t)row * ND + c) = v;
        s1 += v.x + v.y + v.z + v.w;
        s2 += v.x * v.x + v.y * v.y + v.z * v.z + v.w * v.w;
    }
#pragma unroll
    for (int o = 16; o > 0; o >>= 1) {
        s1 += __shfl_xor_sync(0xFFFFFFFFu, s1, o);
        s2 += __shfl_xor_sync(0xFFFFFFFFu, s2, o);
    }
    float mean = s1 * (1.f / ND);
    float var  = s2 * (1.f / ND) - mean * mean;
    float rstd = rsqrtf(var + 1e-3f);
#pragma unroll
    for (int j = 0; j < 3; j++) {
        int c = lane * 4 + j * 128;
        float4 gv = *(const float4*)(g + c);
        float4 bv = *(const float4*)(bb + c);
        __half2 h0 = __floats2half2_rn((xv[j].x - mean) * rstd * gv.x + bv.x,
                                       (xv[j].y - mean) * rstd * gv.y + bv.y);
        __half2 h1 = __floats2half2_rn((xv[j].z - mean) * rstd * gv.z + bv.z,
                                       (xv[j].w - mean) * rstd * gv.w + bv.w);
        *(__half2*)(outh + (size_t)row * ND + c)     = h0;
        *(__half2*)(outh + (size_t)row * ND + c + 2) = h1;
    }
}

// ---------------------------------------------------------------------------
// LayerNorm (eps 1e-3), warp-per-row, fp32 in -> fp16 out
// ---------------------------------------------------------------------------
__global__ __launch_bounds__(256) void ln_kernel(const float* __restrict__ x,
                                                 const float* __restrict__ g,
                                                 const float* __restrict__ bb,
                                                 __half* __restrict__ out)
{
    int w = threadIdx.x >> 5, lane = threadIdx.x & 31;
    int row = blockIdx.x * 8 + w;
    const float* xr = x + (size_t)row * ND;

    float4 xv[3];
    float s1 = 0.f, s2 = 0.f;
#pragma unroll
    for (int j = 0; j < 3; j++) {
        float4 v = *(const float4*)(xr + lane * 4 + j * 128);
        xv[j] = v;
        s1 += v.x + v.y + v.z + v.w;
        s2 += v.x * v.x + v.y * v.y + v.z * v.z + v.w * v.w;
    }
#pragma unroll
    for (int o = 16; o > 0; o >>= 1) {
        s1 += __shfl_xor_sync(0xFFFFFFFFu, s1, o);
        s2 += __shfl_xor_sync(0xFFFFFFFFu, s2, o);
    }
    float mean = s1 * (1.f / ND);
    float var  = s2 * (1.f / ND) - mean * mean;
    float rstd = rsqrtf(var + 1e-3f);
#pragma unroll
    for (int j = 0; j < 3; j++) {
        int c = lane * 4 + j * 128;
        float4 gv = *(const float4*)(g + c);
        float4 bv = *(const float4*)(bb + c);
        __half2 h0 = __floats2half2_rn((xv[j].x - mean) * rstd * gv.x + bv.x,
                                       (xv[j].y - mean) * rstd * gv.y + bv.y);
        __half2 h1 = __floats2half2_rn((xv[j].z - mean) * rstd * gv.z + bv.z,
                                       (xv[j].w - mean) * rstd * gv.w + bv.w);
        *(__half2*)(out + (size_t)row * ND + c)     = h0;
        *(__half2*)(out + (size_t)row * ND + c + 2) = h1;
    }
}

// ---------------------------------------------------------------------------
// Tiled transpose: src [R,C] fp32 (+batch offsets) -> dst [C,R] fp16.
// ---------------------------------------------------------------------------
__global__ void transpose_kernel(const float* __restrict__ src,
                                 __half* __restrict__ dst,
                                 int R, int C, int div,
                                 size_t ssA, size_t ssB,
                                 size_t dsA, size_t dsB)
{
    __shared__ float tile[32][33];
    int z = blockIdx.z;
    const float* s = src + (z / div) * ssA + (z % div) * ssB;
    __half* d = dst + (z / div) * dsA + (z % div) * dsB;
    int c0 = blockIdx.x * 32, r0 = blockIdx.y * 32;
#pragma unroll
    for (int j = 0; j < 4; j++) {
        int r = r0 + threadIdx.y + j * 8, c = c0 + threadIdx.x;
        if (r < R && c < C)
            tile[threadIdx.y + j * 8][threadIdx.x] = s[(size_t)r * C + c];
    }
    __syncthreads();
#pragma unroll
    for (int j = 0; j < 4; j++) {
        int c = c0 + threadIdx.y + j * 8, r = r0 + threadIdx.x;
        if (c < C && r < R)
            d[(size_t)c * R + r] = __float2half(tile[threadIdx.x][threadIdx.y + j * 8]);
    }
}

// ---------------------------------------------------------------------------
// hgemm (TK=32, 4-stage): BM=64 (proj, head).
// ---------------------------------------------------------------------------
constexpr int NSTAGE = 4;
constexpr int smbytes(int BM) { return NSTAGE * (BM + 128) * 80; }

template <int BM, bool RELU, bool RESID, bool OUTH>
__global__ __launch_bounds__(128, BM == 64 ? 3 : 1) void hgemm(
    const __half* __restrict__ A, const __half* __restrict__ B,
    const float* __restrict__ bias, const float* __restrict__ resid,
    void* __restrict__ Cv, int N, int K)
{
    constexpr int AF = BM / 32;
    extern __shared__ __half smh[];
    __shared__ float sbias[128];
    const int tid = threadIdx.x;
    const int row0 = blockIdx.y * BM;
    const int col0 = blockIdx.x * 128;

    const uint32_t base = smem_u32(smh);
    uint32_t aAu[NSTAGE], aBu[NSTAGE];
#pragma unroll
    for (int s = 0; s < NSTAGE; s++) {
        aAu[s] = base + s * BM * 80;
        aBu[s] = base + NSTAGE * BM * 80 + s * 128 * 80;
    }

    {
        int c = col0 + tid;
        sbias[tid] = (bias && c < N) ? bias[c] : 0.f;
    }

    const int KT = K / 32;

    auto prefetch = [&](int kt, int s) {
#pragma unroll
        for (int i = 0; i < BM / 32; i++) {
            int slot = tid + i * 128;
            int r = slot >> 2, c8 = slot & 3;
            cp16(aAu[s] + (uint32_t)(r * 80 + c8 * 16),
                 A + (size_t)(row0 + r) * K + kt * 32 + c8 * 8, 16);
        }
#pragma unroll
        for (int i = 0; i < 4; i++) {
            int slot = tid + i * 128;
            int r = slot >> 2, c8 = slot & 3;
            int n = col0 + r;
            cp16(aBu[s] + (uint32_t)(r * 80 + c8 * 16),
                 B + (size_t)(n < N ? n : N - 1) * K + kt * 32 + c8 * 8,
                 n < N ? 16 : 0);
        }
        cp_commit();
    };

    const int w = tid >> 5, lane = tid & 31;
    const int wm = (w & 1) * (BM / 2);
    const int wn = (w >> 1) * 64;
    const int g = lane >> 2, tg = lane & 3;
    const int lr = lane & 15, lc = (lane >> 4) * 16;

    float acc[AF][8][4];
#pragma unroll
    for (int i = 0; i < AF; i++)
#pragma unroll
        for (int j = 0; j < 8; j++)
#pragma unroll
            for (int q = 0; q < 4; q++) acc[i][j][q] = 0.f;

    prefetch(0, 0); prefetch(1, 1); prefetch(2, 2);

    for (int kt = 0; kt < KT; kt++) {
        int rem = KT - 1 - kt;
        if (rem >= 2)      asm volatile("cp.async.wait_group 2;" ::: "memory");
        else if (rem == 1) asm volatile("cp.async.wait_group 1;" ::: "memory");
        else               asm volatile("cp.async.wait_group 0;" ::: "memory");
        __syncthreads();

        if (kt + 3 < KT) prefetch(kt + 3, (kt + 3) & 3);

        uint32_t bA = aAu[kt & 3], bB = aBu[kt & 3];
#pragma unroll
        for (int ks = 0; ks < 2; ks++) {
            uint32_t a[AF][4];
#pragma unroll
            for (int i = 0; i < AF; i++)
                ldm4(a[i], bA + (uint32_t)((wm + 16 * i + lr) * 80 + ks * 32 + lc));
            uint32_t b[4][4];
#pragma unroll
            for (int p = 0; p < 4; p++)
                ldm4(b[p], bB + (uint32_t)((wn + 16 * p + lr) * 80 + ks * 32 + lc));
#pragma unroll
            for (int i = 0; i < AF; i++)
#pragma unroll
                for (int p = 0; p < 4; p++) {
                    mma_f16(acc[i][2 * p],     a[i], b[p][0], b[p][2]);
                    mma_f16(acc[i][2 * p + 1], a[i], b[p][1], b[p][3]);
                }
        }
    }

    const bool vec = (N & 127) == 0;
    float*  Cf = (float*)Cv;
    __half* Ch = (__half*)Cv;
#pragma unroll
    for (int i = 0; i < AF; i++) {
#pragma unroll
        for (int half_ = 0; half_ < 2; half_++) {
            int r = row0 + wm + 16 * i + g + 8 * half_;
#pragma unroll
            for (int j = 0; j < 8; j++) {
                int cl = wn + 8 * j + 2 * tg;
                int c = col0 + cl;
                float2 v = { acc[i][j][half_ * 2], acc[i][j][half_ * 2 + 1] };
                v.x += sbias[cl]; v.y += sbias[cl + 1];
                if (RELU) { v.x = fmaxf(v.x, 0.f); v.y = fmaxf(v.y, 0.f); }
                if (OUTH) {
                    *(__half2*)&Ch[(size_t)r * N + c] = __floats2half2_rn(v.x, v.y);
                } else if (vec) {
                    if (RESID) {
                        float2 rv = *(const float2*)&resid[(size_t)r * N + c];
                        v.x += rv.x; v.y += rv.y;
                    }
                    *(float2*)&Cf[(size_t)r * N + c] = v;
                } else {
                    if (c < N)     Cf[(size_t)r * N + c]     = v.x;
                    if (c + 1 < N) Cf[(size_t)r * N + c + 1] = v.y;
                }
            }
        }
    }
}

// ---------------------------------------------------------------------------
// hgemm2 (TK=64, 3-stage): BM=128, N multiple of 128 (QKV, W1).
// ---------------------------------------------------------------------------
constexpr int SMB_G2 = 3 * 256 * 144;   // 110592

template <bool RELU, bool VSPLIT>
__global__ __launch_bounds__(128) void hgemm2(
    const __half* __restrict__ A, const __half* __restrict__ B,
    const float* __restrict__ bias, __half* __restrict__ vtp,
    __half* __restrict__ Ch, int N, int K)
{
    extern __shared__ __half smh[];
    __shared__ float sbias[128];
    const int tid = threadIdx.x;
    const int row0 = blockIdx.y * 128;
    const int col0 = blockIdx.x * 128;

    const uint32_t base = smem_u32(smh);
    uint32_t aAu[3], aBu[3];
#pragma unroll
    for (int s = 0; s < 3; s++) {
        aAu[s] = base + s * 128 * 144;
        aBu[s] = base + 3 * 128 * 144 + s * 128 * 144;
    }

    sbias[tid] = bias ? bias[col0 + tid] : 0.f;

    const int KT = K / 64;

    auto prefetch = [&](int kt, int s) {
#pragma unroll
        for (int i = 0; i < 8; i++) {
            int slot = tid + i * 128;
            int r = slot >> 3, c8 = slot & 7;
            cp16f(aAu[s] + (uint32_t)(r * 144 + c8 * 16),
                  A + (size_t)(row0 + r) * K + kt * 64 + c8 * 8);
        }
#pragma unroll
        for (int i = 0; i < 8; i++) {
            int slot = tid + i * 128;
            int r = slot >> 3, c8 = slot & 7;
            cp16f(aBu[s] + (uint32_t)(r * 144 + c8 * 16),
                  B + (size_t)(col0 + r) * K + kt * 64 + c8 * 8);
        }
        cp_commit();
    };

    const int w = tid >> 5, lane = tid & 31;
    const int wm = (w & 1) * 64;
    const int wn = (w >> 1) * 64;
    const int g = lane >> 2, tg = lane & 3;
    const int lr = lane & 15, lc = (lane >> 4) * 16;

    float acc[4][8][4];
#pragma unroll
    for (int i = 0; i < 4; i++)
#pragma unroll
        for (int j = 0; j < 8; j++)
#pragma unroll
            for (int q = 0; q < 4; q++) acc[i][j][q] = 0.f;

    prefetch(0, 0); prefetch(1, 1);

    for (int kt = 0; kt < KT; kt++) {
        if (kt + 1 < KT) asm volatile("cp.async.wait_group 1;" ::: "memory");
        else             asm volatile("cp.async.wait_group 0;" ::: "memory");
        __syncthreads();

        if (kt + 2 < KT) prefetch(kt + 2, (kt + 2) % 3);

        uint32_t bA = aAu[kt % 3], bB = aBu[kt % 3];
#pragma unroll
        for (int ks = 0; ks < 4; ks++) {
            uint32_t a[4][4];
#pragma unroll
            for (int i = 0; i < 4; i++)
                ldm4(a[i], bA + (uint32_t)((wm + 16 * i + lr) * 144 + ks * 32 + lc));
            uint32_t b[4][4];
#pragma unroll
            for (int p = 0; p < 4; p++)
                ldm4(b[p], bB + (uint32_t)((wn + 16 * p + lr) * 144 + ks * 32 + lc));
#pragma unroll
            for (int i = 0; i < 4; i++)
#pragma unroll
                for (int p = 0; p < 4; p++) {
                    mma_f16(acc[i][2 * p],     a[i], b[p][0], b[p][2]);
                    mma_f16(acc[i][2 * p + 1], a[i], b[p][1], b[p][3]);
                }
        }
    }

#pragma unroll
    for (int i = 0; i < 4; i++) {
#pragma unroll
        for (int half_ = 0; half_ < 2; half_++) {
            int r = row0 + wm + 16 * i + g + 8 * half_;
#pragma unroll
            for (int j = 0; j < 8; j++) {
                int cl = wn + 8 * j + 2 * tg;
                int c = col0 + cl;
                float2 v = { acc[i][j][half_ * 2], acc[i][j][half_ * 2 + 1] };
                v.x += sbias[cl]; v.y += sbias[cl + 1];
                if (RELU) { v.x = fmaxf(v.x, 0.f); v.y = fmaxf(v.y, 0.f); }
                if (VSPLIT && col0 >= 2 * ND) {
                    int cc = c - 2 * ND;
                    int hh = cc >> 6, hd = cc & 63;
                    int bb2 = r >> 8, tt = r & 255;
                    size_t vbse = ((size_t)(bb2 * NH + hh) * NHD + hd) * NT + tt;
                    vtp[vbse]      = __float2half(v.x);
                    vtp[vbse + NT] = __float2half(v.y);
                } else {
                    *(__half2*)&Ch[(size_t)r * N + c] = __floats2half2_rn(v.x, v.y);
                }
            }
        }
    }
}

// ---------------------------------------------------------------------------
// hgemm3 (TK=64, 3-stage): BM=64, N=384 exact, fp32 out + residual (W2).
// Same k-order as two TK=32 tiles -> bitwise-identical accumulation.
// ---------------------------------------------------------------------------
constexpr int SMB_G3 = 3 * (64 + 128) * 144;   // 82944

__global__ __launch_bounds__(128, 2) void hgemm3(
    const __half* __restrict__ A, const __half* __restrict__ B,
    const float* __restrict__ bias, const float* __restrict__ resid,
    float* __restrict__ Cf, int N, int K)
{
    extern __shared__ __half smh[];
    __shared__ float sbias[128];
    const int tid = threadIdx.x;
    const int row0 = blockIdx.y * 64;
    const int col0 = blockIdx.x * 128;

    const uint32_t base = smem_u32(smh);
    uint32_t aAu[3], aBu[3];
#pragma unroll
    for (int s = 0; s < 3; s++) {
        aAu[s] = base + s * 64 * 144;
        aBu[s] = base + 3 * 64 * 144 + s * 128 * 144;
    }

    sbias[tid] = bias ? bias[col0 + tid] : 0.f;

    const int KT = K / 64;

    auto prefetch = [&](int kt, int s) {
#pragma unroll
        for (int i = 0; i < 4; i++) {            // A: 64 rows x 8 chunks = 512
            int slot = tid + i * 128;
            int r = slot >> 3, c8 = slot & 7;
            cp16f(aAu[s] + (uint32_t)(r * 144 + c8 * 16),
                  A + (size_t)(row0 + r) * K + kt * 64 + c8 * 8);
        }
#pragma unroll
        for (int i = 0; i < 8; i++) {            // B: 128 rows x 8 chunks = 1024
            int slot = tid + i * 128;
            int r = slot >> 3, c8 = slot & 7;
            cp16f(aBu[s] + (uint32_t)(r * 144 + c8 * 16),
                  B + (size_t)(col0 + r) * K + kt * 64 + c8 * 8);
        }
        cp_commit();
    };

    const int w = tid >> 5, lane = tid & 31;
    const int wm = (w & 1) * 32;
    const int wn = (w >> 1) * 64;
    const int g = lane >> 2, tg = lane & 3;
    const int lr = lane & 15, lc = (lane >> 4) * 16;

    float acc[2][8][4];
#pragma unroll
    for (int i = 0; i < 2; i++)
#pragma unroll
        for (int j = 0; j < 8; j++)
#pragma unroll
            for (int q = 0; q < 4; q++) acc[i][j][q] = 0.f;

    prefetch(0, 0); prefetch(1, 1);

    for (int kt = 0; kt < KT; kt++) {
        if (kt + 1 < KT) asm volatile("cp.async.wait_group 1;" ::: "memory");
        else             asm volatile("cp.async.wait_group 0;" ::: "memory");
        __syncthreads();

        if (kt + 2 < KT) prefetch(kt + 2, (kt + 2) % 3);

        uint32_t bA = aAu[kt % 3], bB = aBu[kt % 3];
#pragma unroll
        for (int ks = 0; ks < 4; ks++) {
            uint32_t a[2][4];
#pragma unroll
            for (int i = 0; i < 2; i++)
                ldm4(a[i], bA + (uint32_t)((wm + 16 * i + lr) * 144 + ks * 32 + lc));
            uint32_t b[4][4];
#pragma unroll
            for (int p = 0; p < 4; p++)
                ldm4(b[p], bB + (uint32_t)((wn + 16 * p + lr) * 144 + ks * 32 + lc));
#pragma unroll
            for (int i = 0; i < 2; i++)
#pragma unroll
                for (int p = 0; p < 4; p++) {
                    mma_f16(acc[i][2 * p],     a[i], b[p][0], b[p][2]);
                    mma_f16(acc[i][2 * p + 1], a[i], b[p][1], b[p][3]);
                }
        }
    }

#pragma unroll
    for (int i = 0; i < 2; i++) {
#pragma unroll
        for (int half_ = 0; half_ < 2; half_++) {
            int r = row0 + wm + 16 * i + g + 8 * half_;
#pragma unroll
            for (int j = 0; j < 8; j++) {
                int cl = wn + 8 * j + 2 * tg;
                int c = col0 + cl;
                float2 v = { acc[i][j][half_ * 2], acc[i][j][half_ * 2 + 1] };
                v.x += sbias[cl]; v.y += sbias[cl + 1];
                float2 rv = *(const float2*)&resid[(size_t)r * N + c];
                v.x += rv.x; v.y += rv.y;
                *(float2*)&Cf[(size_t)r * N + c] = v;
            }
        }
    }
}

// ---------------------------------------------------------------------------
// Flash attention. Block = (b*NH+h, qtile of 128); 8 warps x 16 rows.
// KV tile 128 (two 64-wide inner passes).
// ---------------------------------------------------------------------------
constexpr int AST = 72;
constexpr int VST = 136;

__global__ __launch_bounds__(256) void fattn_kernel(
    const __half* __restrict__ qkv, const __half* __restrict__ vT,
    __half* __restrict__ out)
{
    __shared__ __half sQ[128 * AST], sK[128 * AST], sV[64 * VST];
    const int bh = blockIdx.x, qt = blockIdx.y;
    const int b = bh / NH, h = bh - b * NH;
    const int tid = threadIdx.x, w = tid >> 5, lane = tid & 31;
    const int g = lane >> 2, tg = lane & 3;
    const int lr = lane & 15;
    const uint32_t lc = (lane >> 4) * 16;

    const uint32_t qb = smem_u32(sQ), kb = smem_u32(sK), vb = smem_u32(sV);

    for (int i = tid; i < 1024; i += 256) {
        int r = i >> 3, c8 = i & 7;
        cp16f(qb + (uint32_t)(r * AST * 2 + c8 * 16),
              qkv + (size_t)(b * NT + qt * 128 + r) * NQKV + h * NHD + c8 * 8);
    }
    cp_commit();
    asm volatile("cp.async.wait_group 0;" ::: "memory");
    __syncthreads();

    uint32_t qf[4][4];
#pragma unroll
    for (int c = 0; c < 4; c++)
        ldm4(qf[c], qb + (uint32_t)((w * 16 + lr) * AST * 2 + c * 32) + lc);

    float O[8][4];
#pragma unroll
    for (int j = 0; j < 8; j++)
#pragma unroll
        for (int q = 0; q < 4; q++) O[j][q] = 0.f;
    float m0 = -1e30f, m1 = -1e30f, l0 = 0.f, l1 = 0.f;
    const float scale = rsqrtf((float)ND);

    const int wrow = qt * 128 + w * 16;

    for (int s0 = 0; s0 <= qt * 128; s0 += 128) {
        __syncthreads();
        for (int i = tid; i < 1024; i += 256) {
            int r = i >> 3, c8 = i & 7;
            cp16f(kb + (uint32_t)(r * AST * 2 + c8 * 16),
                  qkv + (size_t)(b * NT + s0 + r) * NQKV + ND + h * NHD + c8 * 8);
        }
        for (int i = tid; i < 1024; i += 256) {
            int r = i >> 4, c16 = i & 15;
            cp16f(vb + (uint32_t)(r * VST * 2 + c16 * 16),
                  vT + ((size_t)bh * NHD + r) * NT + s0 + c16 * 8);
        }
        cp_commit();
        asm volatile("cp.async.wait_group 0;" ::: "memory");
        __syncthreads();

#pragma unroll
        for (int hh = 0; hh < 2; hh++) {
            const int s0h = s0 + hh * 64;
            if (s0h > wrow + 15) continue;

            float S[8][4];
#pragma unroll
            for (int j = 0; j < 8; j++)
                S[j][0] = S[j][1] = S[j][2] = S[j][3] = 0.f;
#pragma unroll
            for (int p = 0; p < 4; p++) {
#pragma unroll
                for (int c = 0; c < 4; c++) {
                    uint32_t bf[4];
                    ldm4(bf, kb + (uint32_t)((hh * 64 + p * 16 + lr) * AST * 2 + c * 32) + lc);
                    mma_f16(S[2 * p],     qf[c], bf[0], bf[2]);
                    mma_f16(S[2 * p + 1], qf[c], bf[1], bf[3]);
                }
            }

            const bool diag = (s0h + 63 > wrow);
            const int rg0 = wrow + g, rg1 = wrow + g + 8;
#pragma unroll
            for (int j = 0; j < 8; j++) {
                int cg = s0h + j * 8 + 2 * tg;
                S[j][0] *= scale; S[j][1] *= scale;
                S[j][2] *= scale; S[j][3] *= scale;
                if (diag) {
                    if (cg     > rg0) S[j][0] = -1e30f;
                    if (cg + 1 > rg0) S[j][1] = -1e30f;
                    if (cg     > rg1) S[j][2] = -1e30f;
                    if (cg + 1 > rg1) S[j][3] = -1e30f;
                }
            }

            float tm0 = -1e30f, tm1 = -1e30f;
#pragma unroll
            for (int j = 0; j < 8; j++) {
                tm0 = fmaxf(tm0, fmaxf(S[j][0], S[j][1]));
                tm1 = fmaxf(tm1, fmaxf(S[j][2], S[j][3]));
            }
            tm0 = fmaxf(tm0, __shfl_xor_sync(0xFFFFFFFFu, tm0, 1));
            tm0 = fmaxf(tm0, __shfl_xor_sync(0xFFFFFFFFu, tm0, 2));
            tm1 = fmaxf(tm1, __shfl_xor_sync(0xFFFFFFFFu, tm1, 1));
            tm1 = fmaxf(tm1, __shfl_xor_sync(0xFFFFFFFFu, tm1, 2));
            float nm0 = fmaxf(m0, tm0), nm1 = fmaxf(m1, tm1);
            float cor0 = __expf(m0 - nm0), cor1 = __expf(m1 - nm1);
            float ts0 = 0.f, ts1 = 0.f;
#pragma unroll
            for (int j = 0; j < 8; j++) {
                S[j][0] = __expf(S[j][0] - nm0); ts0 += S[j][0];
                S[j][1] = __expf(S[j][1] - nm0); ts0 += S[j][1];
                S[j][2] = __expf(S[j][2] - nm1); ts1 += S[j][2];
                S[j][3] = __expf(S[j][3] - nm1); ts1 += S[j][3];
            }
            ts0 += __shfl_xor_sync(0xFFFFFFFFu, ts0, 1);
            ts0 += __shfl_xor_sync(0xFFFFFFFFu, ts0, 2);
            ts1 += __shfl_xor_sync(0xFFFFFFFFu, ts1, 1);
            ts1 += __shfl_xor_sync(0xFFFFFFFFu, ts1, 2);
            l0 = l0 * cor0 + ts0;  l1 = l1 * cor1 + ts1;
            m0 = nm0;  m1 = nm1;
#pragma unroll
            for (int j = 0; j < 8; j++) {
                O[j][0] *= cor0; O[j][1] *= cor0;
                O[j][2] *= cor1; O[j][3] *= cor1;
            }

            uint32_t pf[4][4];
#pragma unroll
            for (int c = 0; c < 4; c++) {
                pf[c][0] = packh2(S[2 * c][0],     S[2 * c][1]);
                pf[c][1] = packh2(S[2 * c][2],     S[2 * c][3]);
                pf[c][2] = packh2(S[2 * c + 1][0], S[2 * c + 1][1]);
                pf[c][3] = packh2(S[2 * c + 1][2], S[2 * c + 1][3]);
            }

#pragma unroll
            for (int p = 0; p < 4; p++) {
#pragma unroll
                for (int c = 0; c < 4; c++) {
                    uint32_t bf[4];
                    ldm4(bf, vb + (uint32_t)((p * 16 + lr) * VST * 2 + hh * 128 + c * 32) + lc);
                    mma_f16(O[2 * p],     pf[c], bf[0], bf[2]);
                    mma_f16(O[2 * p + 1], pf[c], bf[1], bf[3]);
                }
            }
        }
    }

    float i0 = 1.f / l0, i1 = 1.f / l1;
    int qrow = qt * 128 + w * 16 + g;
    size_t ob0 = (size_t)(b * NT + qrow) * ND + h * NHD;
    size_t ob1 = ob0 + (size_t)8 * ND;
#pragma unroll
    for (int j = 0; j < 8; j++) {
        int cc = j * 8 + 2 * tg;
        *(__half2*)(out + ob0 + cc) = __floats2half2_rn(O[j][0] * i0, O[j][1] * i0);
        *(__half2*)(out + ob1 + cc) = __floats2half2_rn(O[j][2] * i1, O[j][3] * i1);
    }
}

// ---------------------------------------------------------------------------
extern "C" void kernel_launch(void* const* d_in, const int* in_sizes, int n_in,
                              void* d_out, int out_size)
{
    const int*   idx   = (const int*)  d_in[0];
    const float* tok   = (const float*)d_in[1];
    const float* pos   = (const float*)d_in[2];
    const float* Wq    = (const float*)d_in[3];
    const float* Wk    = (const float*)d_in[4];
    const float* Wv    = (const float*)d_in[5];
    const float* Wproj = (const float*)d_in[6];
    const float* bproj = (const float*)d_in[7];
    const float* W1    = (const float*)d_in[8];
    const float* b1    = (const float*)d_in[9];
    const float* W2    = (const float*)d_in[10];
    const float* b2    = (const float*)d_in[11];
    const float* ln1g  = (const float*)d_in[12];
    const float* ln1b  = (const float*)d_in[13];
    const float* ln2g  = (const float*)d_in[14];
    const float* ln2b  = (const float*)d_in[15];
    const float* lnfg  = (const float*)d_in[16];
    const float* lnfb  = (const float*)d_in[17];
    const float* Whead = (const float*)d_in[18];
    const float* bhead = (const float*)d_in[19];
    float* out = (float*)d_out;

    float  *px;
    __half *ph, *pqkv, *pvT, *pa, *pm, *pw;
    cudaGetSymbolAddress((void**)&px,   g_x);
    cudaGetSymbolAddress((void**)&ph,   g_h16);
    cudaGetSymbolAddress((void**)&pqkv, g_qkv);
    cudaGetSymbolAddress((void**)&pvT,  g_vT);
    cudaGetSymbolAddress((void**)&pa,   g_att);
    cudaGetSymbolAddress((void**)&pm,   g_hid);
    cudaGetSymbolAddress((void**)&pw,   g_wT);

    static int attr_done = 0;
    if (!attr_done) {
        cudaFuncSetAttribute(hgemm2<false, true>,
                             cudaFuncAttributeMaxDynamicSharedMemorySize, SMB_G2);
        cudaFuncSetAttribute(hgemm2<true, false>,
                             cudaFuncAttributeMaxDynamicSharedMemorySize, SMB_G2);
        cudaFuncSetAttribute(hgemm3,
                             cudaFuncAttributeMaxDynamicSharedMemorySize, SMB_G3);
        cudaFuncSetAttribute(hgemm<64, false, true, false>,
                             cudaFuncAttributeMaxDynamicSharedMemorySize, smbytes(64));
        cudaFuncSetAttribute(hgemm<64, false, false, false>,
                             cudaFuncAttributeMaxDynamicSharedMemorySize, smbytes(64));
        attr_done = 1;
    }

    // Weight prep: tiled transpose -> K-major [N,K] fp16
    {
        dim3 blk(32, 8);
        dim3 gqv(NHD / 32, ND / 32, NL * NH);
        size_t ssA = (size_t)NH * ND * NHD, ssB = (size_t)ND * NHD;
        size_t dsA = (size_t)NQKV * ND,     dsB = (size_t)NHD * ND;
        transpose_kernel<<<gqv, blk>>>(Wq, pw + OFF_QKV,                       ND, NHD, NH, ssA, ssB, dsA, dsB);
        transpose_kernel<<<gqv, blk>>>(Wk, pw + OFF_QKV + (size_t)ND * ND,     ND, NHD, NH, ssA, ssB, dsA, dsB);
        transpose_kernel<<<gqv, blk>>>(Wv, pw + OFF_QKV + (size_t)2 * ND * ND, ND, NHD, NH, ssA, ssB, dsA, dsB);
        transpose_kernel<<<dim3(ND / 32, ND / 32, NL), blk>>>(
            Wproj, pw + OFF_PROJ, ND, ND, 1, (size_t)ND * ND, 0, (size_t)ND * ND, 0);
        transpose_kernel<<<dim3(ND4 / 32, ND / 32, NL), blk>>>(
            W1, pw + OFF_W1, ND, ND4, 1, (size_t)ND * ND4, 0, (size_t)ND * ND4, 0);
        transpose_kernel<<<dim3(ND / 32, ND4 / 32, NL), blk>>>(
            W2, pw + OFF_W2, ND4, ND, 1, (size_t)ND * ND4, 0, (size_t)ND * ND4, 0);
        transpose_kernel<<<dim3((NV + 31) / 32, ND / 32, 1), blk>>>(
            Whead, pw + OFF_HEAD, ND, NV, 1, 0, 0, 0, 0);
    }

    // Fused embedding + layer-0 ln1
    embed_ln_kernel<<<MT / 8, 256>>>(idx, tok, pos, ln1g, ln1b, px, ph);

    dim3 gQKV(NQKV / 128, MT / 128);
    dim3 gP  (ND   / 128, MT / 64);     // BM=64 grids (proj, W2)
    dim3 g4  (ND4  / 128, MT / 128);
    dim3 gH  (1, MT / 64);              // head at BM=64

    for (int l = 0; l < NL; l++) {
        if (l > 0)
            ln_kernel<<<MT / 8, 256>>>(px, ln1g + l * ND, ln1b + l * ND, ph);

        hgemm2<false, true><<<gQKV, 128, SMB_G2>>>(
            ph, pw + OFF_QKV + (size_t)l * NQKV * ND,
            nullptr, pvT, pqkv, NQKV, ND);

        fattn_kernel<<<dim3(NB * NH, NT / 128), 256>>>(pqkv, pvT, pa);

        hgemm<64, false, true, false><<<gP, 128, smbytes(64)>>>(
            pa, pw + OFF_PROJ + (size_t)l * ND * ND,
            bproj + l * ND, px, px, ND, ND);

        ln_kernel<<<MT / 8, 256>>>(px, ln2g + l * ND, ln2b + l * ND, ph);

        hgemm2<true, false><<<g4, 128, SMB_G2>>>(
            ph, pw + OFF_W1 + (size_t)l * ND4 * ND,
            b1 + l * ND4, nullptr, pm, ND4, ND);

        hgemm3<<<gP, 128, SMB_G3>>>(
            pm, pw + OFF_W2 + (size_t)l * ND * ND4,
            b2 + l * ND, px, px, ND, ND4);
    }

    ln_kernel<<<MT / 8, 256>>>(px, lnfg, lnfb, ph);
    hgemm<64, false, false, false><<<gH, 128, smbytes(64)>>>(
        ph, pw + OFF_HEAD, bhead, nullptr, out, NV, ND);
}

// round 16
// speedup vs baseline: 1.1628x; 1.0140x over previous
#include <cuda_runtime.h>
#include <cuda_fp16.h>
#include <cstdint>
#include <math.h>

// ---------------------------------------------------------------------------
// Problem constants
// ---------------------------------------------------------------------------
constexpr int NV  = 65;
constexpr int ND  = 384;
constexpr int NH  = 6;
constexpr int NHD = 64;
constexpr int NL  = 6;
constexpr int NT  = 256;
constexpr int NB  = 64;
constexpr int MT  = NB * NT;       // 16384
constexpr int ND4 = 4 * ND;        // 1536
constexpr int NQKV = 3 * ND;       // 1152

// ---------------------------------------------------------------------------
// Scratch (__device__ globals; allocation-free)
// ---------------------------------------------------------------------------
__device__ float  g_x   [MT * ND];      // fp32 residual stream
__device__ __half g_h16 [MT * ND];      // LN output (GEMM A)
__device__ __half g_qkv [MT * NQKV];    // q|k packed (v region unused)
__device__ __half g_vT  [NB * NH * NHD * NT];  // V transposed per (b,h): [hd][t]
__device__ __half g_att [MT * ND];
__device__ __half g_hid [MT * ND4];

constexpr size_t OFF_QKV  = 0;
constexpr size_t OFF_PROJ = OFF_QKV  + (size_t)NL * NQKV * ND;
constexpr size_t OFF_W1   = OFF_PROJ + (size_t)NL * ND * ND;
constexpr size_t OFF_W2   = OFF_W1   + (size_t)NL * ND4 * ND;
constexpr size_t OFF_HEAD = OFF_W2   + (size_t)NL * ND * ND4;
constexpr size_t WT_TOTAL = OFF_HEAD + (size_t)NV * ND;
__device__ __half g_wT[WT_TOTAL];

// ---------------------------------------------------------------------------
// Helpers
// ---------------------------------------------------------------------------
__device__ __forceinline__ uint32_t smem_u32(const void* p) {
    uint32_t a;
    asm("{ .reg .u64 t; cvta.to.shared.u64 t, %1; cvt.u32.u64 %0, t; }"
        : "=r"(a) : "l"(p));
    return a;
}
__device__ __forceinline__ void cp16(uint32_t dst, const void* src, int srcsize) {
    asm volatile("cp.async.cg.shared.global [%0], [%1], 16, %2;"
                 :: "r"(dst), "l"(src), "r"(srcsize) : "memory");
}
__device__ __forceinline__ void cp16f(uint32_t dst, const void* src) {
    asm volatile("cp.async.cg.shared.global [%0], [%1], 16;"
                 :: "r"(dst), "l"(src) : "memory");
}
__device__ __forceinline__ void cp_commit() {
    asm volatile("cp.async.commit_group;" ::: "memory");
}
__device__ __forceinline__ void ldm4(uint32_t* r, uint32_t a) {
    asm volatile("ldmatrix.sync.aligned.m8n8.x4.shared.b16 {%0,%1,%2,%3}, [%4];"
                 : "=r"(r[0]), "=r"(r[1]), "=r"(r[2]), "=r"(r[3]) : "r"(a));
}
__device__ __forceinline__ void mma_f16(float* c, const uint32_t* a,
                                        uint32_t b0, uint32_t b1) {
    asm volatile(
        "mma.sync.aligned.m16n8k16.row.col.f32.f16.f16.f32 "
        "{%0,%1,%2,%3}, {%4,%5,%6,%7}, {%8,%9}, {%0,%1,%2,%3};"
        : "+f"(c[0]), "+f"(c[1]), "+f"(c[2]), "+f"(c[3])
        : "r"(a[0]), "r"(a[1]), "r"(a[2]), "r"(a[3]), "r"(b0), "r"(b1));
}
__device__ __forceinline__ uint32_t packh2(float x, float y) {
    __half2 h = __floats2half2_rn(x, y);
    return *reinterpret_cast<uint32_t*>(&h);
}

// ---------------------------------------------------------------------------
// Fused embedding + LayerNorm (layer-0 ln1)
// ---------------------------------------------------------------------------
__global__ __launch_bounds__(256) void embed_ln_kernel(
    const int* __restrict__ idx,
    const float* __restrict__ tok,
    const float* __restrict__ pos,
    const float* __restrict__ g,
    const float* __restrict__ bb,
    float* __restrict__ px,
    __half* __restrict__ outh)
{
    int w = threadIdx.x >> 5, lane = threadIdx.x & 31;
    int row = blockIdx.x * 8 + w;
    int token = idx[row];
    const float* tr = tok + (size_t)token * ND;
    const float* pr = pos + (size_t)(row % NT) * ND;

    float4 xv[3];
    float s1 = 0.f, s2 = 0.f;
#pragma unroll
    for (int j = 0; j < 3; j++) {
        int c = lane * 4 + j * 128;
        float4 tv = *(const float4*)(tr + c);
        float4 pv = *(const float4*)(pr + c);
        float4 v = { tv.x + pv.x, tv.y + pv.y, tv.z + pv.z, tv.w + pv.w };
        xv[j] = v;
        *(float4*)(px + (size_t)row * ND + c) = v;
        s1 += v.x + v.y + v.z + v.w;
        s2 += v.x * v.x + v.y * v.y + v.z * v.z + v.w * v.w;
    }
#pragma unroll
    for (int o = 16; o > 0; o >>= 1) {
        s1 += __shfl_xor_sync(0xFFFFFFFFu, s1, o);
        s2 += __shfl_xor_sync(0xFFFFFFFFu, s2, o);
    }
    float mean = s1 * (1.f / ND);
    float var  = s2 * (1.f / ND) - mean * mean;
    float rstd = rsqrtf(var + 1e-3f);
#pragma unroll
    for (int j = 0; j < 3; j++) {
        int c = lane * 4 + j * 128;
        float4 gv = *(const float4*)(g + c);
        float4 bv = *(const float4*)(bb + c);
        __half2 h0 = __floats2half2_rn((xv[j].x - mean) * rstd * gv.x + bv.x,
                                       (xv[j].y - mean) * rstd * gv.y + bv.y);
        __half2 h1 = __floats2half2_rn((xv[j].z - mean) * rstd * gv.z + bv.z,
                                       (xv[j].w - mean) * rstd * gv.w + bv.w);
        *(__half2*)(outh + (size_t)row * ND + c)     = h0;
        *(__half2*)(outh + (size_t)row * ND + c + 2) = h1;
    }
}

// ---------------------------------------------------------------------------
// LayerNorm (eps 1e-3), warp-per-row, fp32 in -> fp16 out
// ---------------------------------------------------------------------------
__global__ __launch_bounds__(256) void ln_kernel(const float* __restrict__ x,
                                                 const float* __restrict__ g,
                                                 const float* __restrict__ bb,
                                                 __half* __restrict__ out)
{
    int w = threadIdx.x >> 5, lane = threadIdx.x & 31;
    int row = blockIdx.x * 8 + w;
    const float* xr = x + (size_t)row * ND;

    float4 xv[3];
    float s1 = 0.f, s2 = 0.f;
#pragma unroll
    for (int j = 0; j < 3; j++) {
        float4 v = *(const float4*)(xr + lane * 4 + j * 128);
        xv[j] = v;
        s1 += v.x + v.y + v.z + v.w;
        s2 += v.x * v.x + v.y * v.y + v.z * v.z + v.w * v.w;
    }
#pragma unroll
    for (int o = 16; o > 0; o >>= 1) {
        s1 += __shfl_xor_sync(0xFFFFFFFFu, s1, o);
        s2 += __shfl_xor_sync(0xFFFFFFFFu, s2, o);
    }
    float mean = s1 * (1.f / ND);
    float var  = s2 * (1.f / ND) - mean * mean;
    float rstd = rsqrtf(var + 1e-3f);
#pragma unroll
    for (int j = 0; j < 3; j++) {
        int c = lane * 4 + j * 128;
        float4 gv = *(const float4*)(g + c);
        float4 bv = *(const float4*)(bb + c);
        __half2 h0 = __floats2half2_rn((xv[j].x - mean) * rstd * gv.x + bv.x,
                                       (xv[j].y - mean) * rstd * gv.y + bv.y);
        __half2 h1 = __floats2half2_rn((xv[j].z - mean) * rstd * gv.z + bv.z,
                                       (xv[j].w - mean) * rstd * gv.w + bv.w);
        *(__half2*)(out + (size_t)row * ND + c)     = h0;
        *(__half2*)(out + (size_t)row * ND + c + 2) = h1;
    }
}

// ---------------------------------------------------------------------------
// Tiled transpose: src [R,C] fp32 (+batch offsets) -> dst [C,R] fp16.
// ---------------------------------------------------------------------------
__global__ void transpose_kernel(const float* __restrict__ src,
                                 __half* __restrict__ dst,
                                 int R, int C, int div,
                                 size_t ssA, size_t ssB,
                                 size_t dsA, size_t dsB)
{
    __shared__ float tile[32][33];
    int z = blockIdx.z;
    const float* s = src + (z / div) * ssA + (z % div) * ssB;
    __half* d = dst + (z / div) * dsA + (z % div) * dsB;
    int c0 = blockIdx.x * 32, r0 = blockIdx.y * 32;
#pragma unroll
    for (int j = 0; j < 4; j++) {
        int r = r0 + threadIdx.y + j * 8, c = c0 + threadIdx.x;
        if (r < R && c < C)
            tile[threadIdx.y + j * 8][threadIdx.x] = s[(size_t)r * C + c];
    }
    __syncthreads();
#pragma unroll
    for (int j = 0; j < 4; j++) {
        int c = c0 + threadIdx.y + j * 8, r = r0 + threadIdx.x;
        if (c < C && r < R)
            d[(size_t)c * R + r] = __float2half(tile[threadIdx.x][threadIdx.y + j * 8]);
    }
}

// ---------------------------------------------------------------------------
// hgemm (TK=32, 4-stage): BM=64 (head gemm only).
// ---------------------------------------------------------------------------
constexpr int NSTAGE = 4;
constexpr int smbytes(int BM) { return NSTAGE * (BM + 128) * 80; }

template <int BM, bool RELU, bool RESID, bool OUTH>
__global__ __launch_bounds__(128, BM == 64 ? 3 : 1) void hgemm(
    const __half* __restrict__ A, const __half* __restrict__ B,
    const float* __restrict__ bias, const float* __restrict__ resid,
    void* __restrict__ Cv, int N, int K)
{
    constexpr int AF = BM / 32;
    extern __shared__ __half smh[];
    __shared__ float sbias[128];
    const int tid = threadIdx.x;
    const int row0 = blockIdx.y * BM;
    const int col0 = blockIdx.x * 128;

    const uint32_t base = smem_u32(smh);
    uint32_t aAu[NSTAGE], aBu[NSTAGE];
#pragma unroll
    for (int s = 0; s < NSTAGE; s++) {
        aAu[s] = base + s * BM * 80;
        aBu[s] = base + NSTAGE * BM * 80 + s * 128 * 80;
    }

    {
        int c = col0 + tid;
        sbias[tid] = (bias && c < N) ? bias[c] : 0.f;
    }

    const int KT = K / 32;

    auto prefetch = [&](int kt, int s) {
#pragma unroll
        for (int i = 0; i < BM / 32; i++) {
            int slot = tid + i * 128;
            int r = slot >> 2, c8 = slot & 3;
            cp16(aAu[s] + (uint32_t)(r * 80 + c8 * 16),
                 A + (size_t)(row0 + r) * K + kt * 32 + c8 * 8, 16);
        }
#pragma unroll
        for (int i = 0; i < 4; i++) {
            int slot = tid + i * 128;
            int r = slot >> 2, c8 = slot & 3;
            int n = col0 + r;
            cp16(aBu[s] + (uint32_t)(r * 80 + c8 * 16),
                 B + (size_t)(n < N ? n : N - 1) * K + kt * 32 + c8 * 8,
                 n < N ? 16 : 0);
        }
        cp_commit();
    };

    const int w = tid >> 5, lane = tid & 31;
    const int wm = (w & 1) * (BM / 2);
    const int wn = (w >> 1) * 64;
    const int g = lane >> 2, tg = lane & 3;
    const int lr = lane & 15, lc = (lane >> 4) * 16;

    float acc[AF][8][4];
#pragma unroll
    for (int i = 0; i < AF; i++)
#pragma unroll
        for (int j = 0; j < 8; j++)
#pragma unroll
            for (int q = 0; q < 4; q++) acc[i][j][q] = 0.f;

    prefetch(0, 0); prefetch(1, 1); prefetch(2, 2);

    for (int kt = 0; kt < KT; kt++) {
        int rem = KT - 1 - kt;
        if (rem >= 2)      asm volatile("cp.async.wait_group 2;" ::: "memory");
        else if (rem == 1) asm volatile("cp.async.wait_group 1;" ::: "memory");
        else               asm volatile("cp.async.wait_group 0;" ::: "memory");
        __syncthreads();

        if (kt + 3 < KT) prefetch(kt + 3, (kt + 3) & 3);

        uint32_t bA = aAu[kt & 3], bB = aBu[kt & 3];
#pragma unroll
        for (int ks = 0; ks < 2; ks++) {
            uint32_t a[AF][4];
#pragma unroll
            for (int i = 0; i < AF; i++)
                ldm4(a[i], bA + (uint32_t)((wm + 16 * i + lr) * 80 + ks * 32 + lc));
            uint32_t b[4][4];
#pragma unroll
            for (int p = 0; p < 4; p++)
                ldm4(b[p], bB + (uint32_t)((wn + 16 * p + lr) * 80 + ks * 32 + lc));
#pragma unroll
            for (int i = 0; i < AF; i++)
#pragma unroll
                for (int p = 0; p < 4; p++) {
                    mma_f16(acc[i][2 * p],     a[i], b[p][0], b[p][2]);
                    mma_f16(acc[i][2 * p + 1], a[i], b[p][1], b[p][3]);
                }
        }
    }

    const bool vec = (N & 127) == 0;
    float*  Cf = (float*)Cv;
    __half* Ch = (__half*)Cv;
#pragma unroll
    for (int i = 0; i < AF; i++) {
#pragma unroll
        for (int half_ = 0; half_ < 2; half_++) {
            int r = row0 + wm + 16 * i + g + 8 * half_;
#pragma unroll
            for (int j = 0; j < 8; j++) {
                int cl = wn + 8 * j + 2 * tg;
                int c = col0 + cl;
                float2 v = { acc[i][j][half_ * 2], acc[i][j][half_ * 2 + 1] };
                v.x += sbias[cl]; v.y += sbias[cl + 1];
                if (RELU) { v.x = fmaxf(v.x, 0.f); v.y = fmaxf(v.y, 0.f); }
                if (OUTH) {
                    *(__half2*)&Ch[(size_t)r * N + c] = __floats2half2_rn(v.x, v.y);
                } else if (vec) {
                    if (RESID) {
                        float2 rv = *(const float2*)&resid[(size_t)r * N + c];
                        v.x += rv.x; v.y += rv.y;
                    }
                    *(float2*)&Cf[(size_t)r * N + c] = v;
                } else {
                    if (c < N)     Cf[(size_t)r * N + c]     = v.x;
                    if (c + 1 < N) Cf[(size_t)r * N + c + 1] = v.y;
                }
            }
        }
    }
}

// ---------------------------------------------------------------------------
// hgemm2 (TK=64, 3-stage): BM=128, N multiple of 128 (QKV, W1).
// ---------------------------------------------------------------------------
constexpr int SMB_G2 = 3 * 256 * 144;   // 110592

template <bool RELU, bool VSPLIT>
__global__ __launch_bounds__(128) void hgemm2(
    const __half* __restrict__ A, const __half* __restrict__ B,
    const float* __restrict__ bias, __half* __restrict__ vtp,
    __half* __restrict__ Ch, int N, int K)
{
    extern __shared__ __half smh[];
    __shared__ float sbias[128];
    const int tid = threadIdx.x;
    const int row0 = blockIdx.y * 128;
    const int col0 = blockIdx.x * 128;

    const uint32_t base = smem_u32(smh);
    uint32_t aAu[3], aBu[3];
#pragma unroll
    for (int s = 0; s < 3; s++) {
        aAu[s] = base + s * 128 * 144;
        aBu[s] = base + 3 * 128 * 144 + s * 128 * 144;
    }

    sbias[tid] = bias ? bias[col0 + tid] : 0.f;

    const int KT = K / 64;

    auto prefetch = [&](int kt, int s) {
#pragma unroll
        for (int i = 0; i < 8; i++) {
            int slot = tid + i * 128;
            int r = slot >> 3, c8 = slot & 7;
            cp16f(aAu[s] + (uint32_t)(r * 144 + c8 * 16),
                  A + (size_t)(row0 + r) * K + kt * 64 + c8 * 8);
        }
#pragma unroll
        for (int i = 0; i < 8; i++) {
            int slot = tid + i * 128;
            int r = slot >> 3, c8 = slot & 7;
            cp16f(aBu[s] + (uint32_t)(r * 144 + c8 * 16),
                  B + (size_t)(col0 + r) * K + kt * 64 + c8 * 8);
        }
        cp_commit();
    };

    const int w = tid >> 5, lane = tid & 31;
    const int wm = (w & 1) * 64;
    const int wn = (w >> 1) * 64;
    const int g = lane >> 2, tg = lane & 3;
    const int lr = lane & 15, lc = (lane >> 4) * 16;

    float acc[4][8][4];
#pragma unroll
    for (int i = 0; i < 4; i++)
#pragma unroll
        for (int j = 0; j < 8; j++)
#pragma unroll
            for (int q = 0; q < 4; q++) acc[i][j][q] = 0.f;

    prefetch(0, 0); prefetch(1, 1);

    for (int kt = 0; kt < KT; kt++) {
        if (kt + 1 < KT) asm volatile("cp.async.wait_group 1;" ::: "memory");
        else             asm volatile("cp.async.wait_group 0;" ::: "memory");
        __syncthreads();

        if (kt + 2 < KT) prefetch(kt + 2, (kt + 2) % 3);

        uint32_t bA = aAu[kt % 3], bB = aBu[kt % 3];
#pragma unroll
        for (int ks = 0; ks < 4; ks++) {
            uint32_t a[4][4];
#pragma unroll
            for (int i = 0; i < 4; i++)
                ldm4(a[i], bA + (uint32_t)((wm + 16 * i + lr) * 144 + ks * 32 + lc));
            uint32_t b[4][4];
#pragma unroll
            for (int p = 0; p < 4; p++)
                ldm4(b[p], bB + (uint32_t)((wn + 16 * p + lr) * 144 + ks * 32 + lc));
#pragma unroll
            for (int i = 0; i < 4; i++)
#pragma unroll
                for (int p = 0; p < 4; p++) {
                    mma_f16(acc[i][2 * p],     a[i], b[p][0], b[p][2]);
                    mma_f16(acc[i][2 * p + 1], a[i], b[p][1], b[p][3]);
                }
        }
    }

#pragma unroll
    for (int i = 0; i < 4; i++) {
#pragma unroll
        for (int half_ = 0; half_ < 2; half_++) {
            int r = row0 + wm + 16 * i + g + 8 * half_;
#pragma unroll
            for (int j = 0; j < 8; j++) {
                int cl = wn + 8 * j + 2 * tg;
                int c = col0 + cl;
                float2 v = { acc[i][j][half_ * 2], acc[i][j][half_ * 2 + 1] };
                v.x += sbias[cl]; v.y += sbias[cl + 1];
                if (RELU) { v.x = fmaxf(v.x, 0.f); v.y = fmaxf(v.y, 0.f); }
                if (VSPLIT && col0 >= 2 * ND) {
                    int cc = c - 2 * ND;
                    int hh = cc >> 6, hd = cc & 63;
                    int bb2 = r >> 8, tt = r & 255;
                    size_t vbse = ((size_t)(bb2 * NH + hh) * NHD + hd) * NT + tt;
                    vtp[vbse]      = __float2half(v.x);
                    vtp[vbse + NT] = __float2half(v.y);
                } else {
                    *(__half2*)&Ch[(size_t)r * N + c] = __floats2half2_rn(v.x, v.y);
                }
            }
        }
    }
}

// ---------------------------------------------------------------------------
// hgemm3 (TK=64, 3-stage): BM=64, N=384 exact, fp32 out + residual
// (proj AND W2). Same k-order as TK=32 pairs -> bitwise-identical.
// ---------------------------------------------------------------------------
constexpr int SMB_G3 = 3 * (64 + 128) * 144;   // 82944

__global__ __launch_bounds__(128, 2) void hgemm3(
    const __half* __restrict__ A, const __half* __restrict__ B,
    const float* __restrict__ bias, const float* __restrict__ resid,
    float* __restrict__ Cf, int N, int K)
{
    extern __shared__ __half smh[];
    __shared__ float sbias[128];
    const int tid = threadIdx.x;
    const int row0 = blockIdx.y * 64;
    const int col0 = blockIdx.x * 128;

    const uint32_t base = smem_u32(smh);
    uint32_t aAu[3], aBu[3];
#pragma unroll
    for (int s = 0; s < 3; s++) {
        aAu[s] = base + s * 64 * 144;
        aBu[s] = base + 3 * 64 * 144 + s * 128 * 144;
    }

    sbias[tid] = bias ? bias[col0 + tid] : 0.f;

    const int KT = K / 64;

    auto prefetch = [&](int kt, int s) {
#pragma unroll
        for (int i = 0; i < 4; i++) {
            int slot = tid + i * 128;
            int r = slot >> 3, c8 = slot & 7;
            cp16f(aAu[s] + (uint32_t)(r * 144 + c8 * 16),
                  A + (size_t)(row0 + r) * K + kt * 64 + c8 * 8);
        }
#pragma unroll
        for (int i = 0; i < 8; i++) {
            int slot = tid + i * 128;
            int r = slot >> 3, c8 = slot & 7;
            cp16f(aBu[s] + (uint32_t)(r * 144 + c8 * 16),
                  B + (size_t)(col0 + r) * K + kt * 64 + c8 * 8);
        }
        cp_commit();
    };

    const int w = tid >> 5, lane = tid & 31;
    const int wm = (w & 1) * 32;
    const int wn = (w >> 1) * 64;
    const int g = lane >> 2, tg = lane & 3;
    const int lr = lane & 15, lc = (lane >> 4) * 16;

    float acc[2][8][4];
#pragma unroll
    for (int i = 0; i < 2; i++)
#pragma unroll
        for (int j = 0; j < 8; j++)
#pragma unroll
            for (int q = 0; q < 4; q++) acc[i][j][q] = 0.f;

    prefetch(0, 0); prefetch(1, 1);

    for (int kt = 0; kt < KT; kt++) {
        if (kt + 1 < KT) asm volatile("cp.async.wait_group 1;" ::: "memory");
        else             asm volatile("cp.async.wait_group 0;" ::: "memory");
        __syncthreads();

        if (kt + 2 < KT) prefetch(kt + 2, (kt + 2) % 3);

        uint32_t bA = aAu[kt % 3], bB = aBu[kt % 3];
#pragma unroll
        for (int ks = 0; ks < 4; ks++) {
            uint32_t a[2][4];
#pragma unroll
            for (int i = 0; i < 2; i++)
                ldm4(a[i], bA + (uint32_t)((wm + 16 * i + lr) * 144 + ks * 32 + lc));
            uint32_t b[4][4];
#pragma unroll
            for (int p = 0; p < 4; p++)
                ldm4(b[p], bB + (uint32_t)((wn + 16 * p + lr) * 144 + ks * 32 + lc));
#pragma unroll
            for (int i = 0; i < 2; i++)
#pragma unroll
                for (int p = 0; p < 4; p++) {
                    mma_f16(acc[i][2 * p],     a[i], b[p][0], b[p][2]);
                    mma_f16(acc[i][2 * p + 1], a[i], b[p][1], b[p][3]);
                }
        }
    }

#pragma unroll
    for (int i = 0; i < 2; i++) {
#pragma unroll
        for (int half_ = 0; half_ < 2; half_++) {
            int r = row0 + wm + 16 * i + g + 8 * half_;
#pragma unroll
            for (int j = 0; j < 8; j++) {
                int cl = wn + 8 * j + 2 * tg;
                int c = col0 + cl;
                float2 v = { acc[i][j][half_ * 2], acc[i][j][half_ * 2 + 1] };
                v.x += sbias[cl]; v.y += sbias[cl + 1];
                float2 rv = *(const float2*)&resid[(size_t)r * N + c];
                v.x += rv.x; v.y += rv.y;
                *(float2*)&Cf[(size_t)r * N + c] = v;
            }
        }
    }
}

// ---------------------------------------------------------------------------
// Flash attention. Block = (b*NH+h, qtile of 128); 8 warps x 16 rows.
// KV tile 128 (two 64-wide inner passes). Heavy q-tiles scheduled FIRST
// (qt = 1 - blockIdx.y) for better wave packing.
// ---------------------------------------------------------------------------
constexpr int AST = 72;
constexpr int VST = 136;

__global__ __launch_bounds__(256) void fattn_kernel(
    const __half* __restrict__ qkv, const __half* __restrict__ vT,
    __half* __restrict__ out)
{
    __shared__ __half sQ[128 * AST], sK[128 * AST], sV[64 * VST];
    const int bh = blockIdx.x;
    const int qt = (int)(gridDim.y - 1) - (int)blockIdx.y;   // heavy tiles first
    const int b = bh / NH, h = bh - b * NH;
    const int tid = threadIdx.x, w = tid >> 5, lane = tid & 31;
    const int g = lane >> 2, tg = lane & 3;
    const int lr = lane & 15;
    const uint32_t lc = (lane >> 4) * 16;

    const uint32_t qb = smem_u32(sQ), kb = smem_u32(sK), vb = smem_u32(sV);

    for (int i = tid; i < 1024; i += 256) {
        int r = i >> 3, c8 = i & 7;
        cp16f(qb + (uint32_t)(r * AST * 2 + c8 * 16),
              qkv + (size_t)(b * NT + qt * 128 + r) * NQKV + h * NHD + c8 * 8);
    }
    cp_commit();
    asm volatile("cp.async.wait_group 0;" ::: "memory");
    __syncthreads();

    uint32_t qf[4][4];
#pragma unroll
    for (int c = 0; c < 4; c++)
        ldm4(qf[c], qb + (uint32_t)((w * 16 + lr) * AST * 2 + c * 32) + lc);

    float O[8][4];
#pragma unroll
    for (int j = 0; j < 8; j++)
#pragma unroll
        for (int q = 0; q < 4; q++) O[j][q] = 0.f;
    float m0 = -1e30f, m1 = -1e30f, l0 = 0.f, l1 = 0.f;
    const float scale = rsqrtf((float)ND);

    const int wrow = qt * 128 + w * 16;

    for (int s0 = 0; s0 <= qt * 128; s0 += 128) {
        __syncthreads();
        for (int i = tid; i < 1024; i += 256) {
            int r = i >> 3, c8 = i & 7;
            cp16f(kb + (uint32_t)(r * AST * 2 + c8 * 16),
                  qkv + (size_t)(b * NT + s0 + r) * NQKV + ND + h * NHD + c8 * 8);
        }
        for (int i = tid; i < 1024; i += 256) {
            int r = i >> 4, c16 = i & 15;
            cp16f(vb + (uint32_t)(r * VST * 2 + c16 * 16),
                  vT + ((size_t)bh * NHD + r) * NT + s0 + c16 * 8);
        }
        cp_commit();
        asm volatile("cp.async.wait_group 0;" ::: "memory");
        __syncthreads();

#pragma unroll
        for (int hh = 0; hh < 2; hh++) {
            const int s0h = s0 + hh * 64;
            if (s0h > wrow + 15) continue;

            float S[8][4];
#pragma unroll
            for (int j = 0; j < 8; j++)
                S[j][0] = S[j][1] = S[j][2] = S[j][3] = 0.f;
#pragma unroll
            for (int p = 0; p < 4; p++) {
#pragma unroll
                for (int c = 0; c < 4; c++) {
                    uint32_t bf[4];
                    ldm4(bf, kb + (uint32_t)((hh * 64 + p * 16 + lr) * AST * 2 + c * 32) + lc);
                    mma_f16(S[2 * p],     qf[c], bf[0], bf[2]);
                    mma_f16(S[2 * p + 1], qf[c], bf[1], bf[3]);
                }
            }

            const bool diag = (s0h + 63 > wrow);
            const int rg0 = wrow + g, rg1 = wrow + g + 8;
#pragma unroll
            for (int j = 0; j < 8; j++) {
                int cg = s0h + j * 8 + 2 * tg;
                S[j][0] *= scale; S[j][1] *= scale;
                S[j][2] *= scale; S[j][3] *= scale;
                if (diag) {
                    if (cg     > rg0) S[j][0] = -1e30f;
                    if (cg + 1 > rg0) S[j][1] = -1e30f;
                    if (cg     > rg1) S[j][2] = -1e30f;
                    if (cg + 1 > rg1) S[j][3] = -1e30f;
                }
            }

            float tm0 = -1e30f, tm1 = -1e30f;
#pragma unroll
            for (int j = 0; j < 8; j++) {
                tm0 = fmaxf(tm0, fmaxf(S[j][0], S[j][1]));
                tm1 = fmaxf(tm1, fmaxf(S[j][2], S[j][3]));
            }
            tm0 = fmaxf(tm0, __shfl_xor_sync(0xFFFFFFFFu, tm0, 1));
            tm0 = fmaxf(tm0, __shfl_xor_sync(0xFFFFFFFFu, tm0, 2));
            tm1 = fmaxf(tm1, __shfl_xor_sync(0xFFFFFFFFu, tm1, 1));
            tm1 = fmaxf(tm1, __shfl_xor_sync(0xFFFFFFFFu, tm1, 2));
            float nm0 = fmaxf(m0, tm0), nm1 = fmaxf(m1, tm1);
            float cor0 = __expf(m0 - nm0), cor1 = __expf(m1 - nm1);
            float ts0 = 0.f, ts1 = 0.f;
#pragma unroll
            for (int j = 0; j < 8; j++) {
                S[j][0] = __expf(S[j][0] - nm0); ts0 += S[j][0];
                S[j][1] = __expf(S[j][1] - nm0); ts0 += S[j][1];
                S[j][2] = __expf(S[j][2] - nm1); ts1 += S[j][2];
                S[j][3] = __expf(S[j][3] - nm1); ts1 += S[j][3];
            }
            ts0 += __shfl_xor_sync(0xFFFFFFFFu, ts0, 1);
            ts0 += __shfl_xor_sync(0xFFFFFFFFu, ts0, 2);
            ts1 += __shfl_xor_sync(0xFFFFFFFFu, ts1, 1);
            ts1 += __shfl_xor_sync(0xFFFFFFFFu, ts1, 2);
            l0 = l0 * cor0 + ts0;  l1 = l1 * cor1 + ts1;
            m0 = nm0;  m1 = nm1;
#pragma unroll
            for (int j = 0; j < 8; j++) {
                O[j][0] *= cor0; O[j][1] *= cor0;
                O[j][2] *= cor1; O[j][3] *= cor1;
            }

            uint32_t pf[4][4];
#pragma unroll
            for (int c = 0; c < 4; c++) {
                pf[c][0] = packh2(S[2 * c][0],     S[2 * c][1]);
                pf[c][1] = packh2(S[2 * c][2],     S[2 * c][3]);
                pf[c][2] = packh2(S[2 * c + 1][0], S[2 * c + 1][1]);
                pf[c][3] = packh2(S[2 * c + 1][2], S[2 * c + 1][3]);
            }

#pragma unroll
            for (int p = 0; p < 4; p++) {
#pragma unroll
                for (int c = 0; c < 4; c++) {
                    uint32_t bf[4];
                    ldm4(bf, vb + (uint32_t)((p * 16 + lr) * VST * 2 + hh * 128 + c * 32) + lc);
                    mma_f16(O[2 * p],     pf[c], bf[0], bf[2]);
                    mma_f16(O[2 * p + 1], pf[c], bf[1], bf[3]);
                }
            }
        }
    }

    float i0 = 1.f / l0, i1 = 1.f / l1;
    int qrow = qt * 128 + w * 16 + g;
    size_t ob0 = (size_t)(b * NT + qrow) * ND + h * NHD;
    size_t ob1 = ob0 + (size_t)8 * ND;
#pragma unroll
    for (int j = 0; j < 8; j++) {
        int cc = j * 8 + 2 * tg;
        *(__half2*)(out + ob0 + cc) = __floats2half2_rn(O[j][0] * i0, O[j][1] * i0);
        *(__half2*)(out + ob1 + cc) = __floats2half2_rn(O[j][2] * i1, O[j][3] * i1);
    }
}

// ---------------------------------------------------------------------------
extern "C" void kernel_launch(void* const* d_in, const int* in_sizes, int n_in,
                              void* d_out, int out_size)
{
    const int*   idx   = (const int*)  d_in[0];
    const float* tok   = (const float*)d_in[1];
    const float* pos   = (const float*)d_in[2];
    const float* Wq    = (const float*)d_in[3];
    const float* Wk    = (const float*)d_in[4];
    const float* Wv    = (const float*)d_in[5];
    const float* Wproj = (const float*)d_in[6];
    const float* bproj = (const float*)d_in[7];
    const float* W1    = (const float*)d_in[8];
    const float* b1    = (const float*)d_in[9];
    const float* W2    = (const float*)d_in[10];
    const float* b2    = (const float*)d_in[11];
    const float* ln1g  = (const float*)d_in[12];
    const float* ln1b  = (const float*)d_in[13];
    const float* ln2g  = (const float*)d_in[14];
    const float* ln2b  = (const float*)d_in[15];
    const float* lnfg  = (const float*)d_in[16];
    const float* lnfb  = (const float*)d_in[17];
    const float* Whead = (const float*)d_in[18];
    const float* bhead = (const float*)d_in[19];
    float* out = (float*)d_out;

    float  *px;
    __half *ph, *pqkv, *pvT, *pa, *pm, *pw;
    cudaGetSymbolAddress((void**)&px,   g_x);
    cudaGetSymbolAddress((void**)&ph,   g_h16);
    cudaGetSymbolAddress((void**)&pqkv, g_qkv);
    cudaGetSymbolAddress((void**)&pvT,  g_vT);
    cudaGetSymbolAddress((void**)&pa,   g_att);
    cudaGetSymbolAddress((void**)&pm,   g_hid);
    cudaGetSymbolAddress((void**)&pw,   g_wT);

    static int attr_done = 0;
    if (!attr_done) {
        cudaFuncSetAttribute(hgemm2<false, true>,
                             cudaFuncAttributeMaxDynamicSharedMemorySize, SMB_G2);
        cudaFuncSetAttribute(hgemm2<true, false>,
                             cudaFuncAttributeMaxDynamicSharedMemorySize, SMB_G2);
        cudaFuncSetAttribute(hgemm3,
                             cudaFuncAttributeMaxDynamicSharedMemorySize, SMB_G3);
        cudaFuncSetAttribute(hgemm<64, false, false, false>,
                             cudaFuncAttributeMaxDynamicSharedMemorySize, smbytes(64));
        attr_done = 1;
    }

    // Weight prep: tiled transpose -> K-major [N,K] fp16
    {
        dim3 blk(32, 8);
        dim3 gqv(NHD / 32, ND / 32, NL * NH);
        size_t ssA = (size_t)NH * ND * NHD, ssB = (size_t)ND * NHD;
        size_t dsA = (size_t)NQKV * ND,     dsB = (size_t)NHD * ND;
        transpose_kernel<<<gqv, blk>>>(Wq, pw + OFF_QKV,                       ND, NHD, NH, ssA, ssB, dsA, dsB);
        transpose_kernel<<<gqv, blk>>>(Wk, pw + OFF_QKV + (size_t)ND * ND,     ND, NHD, NH, ssA, ssB, dsA, dsB);
        transpose_kernel<<<gqv, blk>>>(Wv, pw + OFF_QKV + (size_t)2 * ND * ND, ND, NHD, NH, ssA, ssB, dsA, dsB);
        transpose_kernel<<<dim3(ND / 32, ND / 32, NL), blk>>>(
            Wproj, pw + OFF_PROJ, ND, ND, 1, (size_t)ND * ND, 0, (size_t)ND * ND, 0);
        transpose_kernel<<<dim3(ND4 / 32, ND / 32, NL), blk>>>(
            W1, pw + OFF_W1, ND, ND4, 1, (size_t)ND * ND4, 0, (size_t)ND * ND4, 0);
        transpose_kernel<<<dim3(ND / 32, ND4 / 32, NL), blk>>>(
            W2, pw + OFF_W2, ND4, ND, 1, (size_t)ND * ND4, 0, (size_t)ND * ND4, 0);
        transpose_kernel<<<dim3((NV + 31) / 32, ND / 32, 1), blk>>>(
            Whead, pw + OFF_HEAD, ND, NV, 1, 0, 0, 0, 0);
    }

    // Fused embedding + layer-0 ln1
    embed_ln_kernel<<<MT / 8, 256>>>(idx, tok, pos, ln1g, ln1b, px, ph);

    dim3 gQKV(NQKV / 128, MT / 128);
    dim3 gP  (ND   / 128, MT / 64);     // BM=64 grids (proj, W2 via hgemm3)
    dim3 g4  (ND4  / 128, MT / 128);
    dim3 gH  (1, MT / 64);              // head at BM=64

    for (int l = 0; l < NL; l++) {
        if (l > 0)
            ln_kernel<<<MT / 8, 256>>>(px, ln1g + l * ND, ln1b + l * ND, ph);

        hgemm2<false, true><<<gQKV, 128, SMB_G2>>>(
            ph, pw + OFF_QKV + (size_t)l * NQKV * ND,
            nullptr, pvT, pqkv, NQKV, ND);

        fattn_kernel<<<dim3(NB * NH, NT / 128), 256>>>(pqkv, pvT, pa);

        hgemm3<<<gP, 128, SMB_G3>>>(
            pa, pw + OFF_PROJ + (size_t)l * ND * ND,
            bproj + l * ND, px, px, ND, ND);

        ln_kernel<<<MT / 8, 256>>>(px, ln2g + l * ND, ln2b + l * ND, ph);

        hgemm2<true, false><<<g4, 128, SMB_G2>>>(
            ph, pw + OFF_W1 + (size_t)l * ND4 * ND,
            b1 + l * ND4, nullptr, pm, ND4, ND);

        hgemm3<<<gP, 128, SMB_G3>>>(
            pm, pw + OFF_W2 + (size_t)l * ND * ND4,
            b2 + l * ND, px, px, ND, ND4);
    }

    ln_kernel<<<MT / 8, 256>>>(px, lnfg, lnfb, ph);
    hgemm<64, false, false, false><<<gH, 128, smbytes(64)>>>(
        ph, pw + OFF_HEAD, bhead, nullptr, out, NV, ND);
}

// round 17
// speedup vs baseline: 1.1724x; 1.0083x over previous
#include <cuda_runtime.h>
#include <cuda_fp16.h>
#include <cstdint>
#include <math.h>

// ---------------------------------------------------------------------------
// Problem constants
// ---------------------------------------------------------------------------
constexpr int NV  = 65;
constexpr int ND  = 384;
constexpr int NH  = 6;
constexpr int NHD = 64;
constexpr int NL  = 6;
constexpr int NT  = 256;
constexpr int NB  = 64;
constexpr int MT  = NB * NT;       // 16384
constexpr int ND4 = 4 * ND;        // 1536
constexpr int NQKV = 3 * ND;       // 1152

// ---------------------------------------------------------------------------
// Scratch (__device__ globals; allocation-free)
// ---------------------------------------------------------------------------
__device__ float  g_x   [MT * ND];      // fp32 residual stream
__device__ __half g_h16 [MT * ND];      // LN output (GEMM A)
__device__ __half g_qkv [MT * NQKV];    // q|k packed (v region unused)
__device__ __half g_vT  [NB * NH * NHD * NT];  // V transposed per (b,h): [hd][t]
__device__ __half g_att [MT * ND];
__device__ __half g_hid [MT * ND4];

constexpr size_t OFF_QKV  = 0;
constexpr size_t OFF_PROJ = OFF_QKV  + (size_t)NL * NQKV * ND;
constexpr size_t OFF_W1   = OFF_PROJ + (size_t)NL * ND * ND;
constexpr size_t OFF_W2   = OFF_W1   + (size_t)NL * ND4 * ND;
constexpr size_t OFF_HEAD = OFF_W2   + (size_t)NL * ND * ND4;
constexpr size_t WT_TOTAL = OFF_HEAD + (size_t)NV * ND;
__device__ __half g_wT[WT_TOTAL];

// ---------------------------------------------------------------------------
// Helpers
// ---------------------------------------------------------------------------
__device__ __forceinline__ uint32_t smem_u32(const void* p) {
    uint32_t a;
    asm("{ .reg .u64 t; cvta.to.shared.u64 t, %1; cvt.u32.u64 %0, t; }"
        : "=r"(a) : "l"(p));
    return a;
}
__device__ __forceinline__ void cp16(uint32_t dst, const void* src, int srcsize) {
    asm volatile("cp.async.cg.shared.global [%0], [%1], 16, %2;"
                 :: "r"(dst), "l"(src), "r"(srcsize) : "memory");
}
__device__ __forceinline__ void cp16f(uint32_t dst, const void* src) {
    asm volatile("cp.async.cg.shared.global [%0], [%1], 16;"
                 :: "r"(dst), "l"(src) : "memory");
}
__device__ __forceinline__ void cp_commit() {
    asm volatile("cp.async.commit_group;" ::: "memory");
}
__device__ __forceinline__ void ldm4(uint32_t* r, uint32_t a) {
    asm volatile("ldmatrix.sync.aligned.m8n8.x4.shared.b16 {%0,%1,%2,%3}, [%4];"
                 : "=r"(r[0]), "=r"(r[1]), "=r"(r[2]), "=r"(r[3]) : "r"(a));
}
__device__ __forceinline__ void mma_f16(float* c, const uint32_t* a,
                                        uint32_t b0, uint32_t b1) {
    asm volatile(
        "mma.sync.aligned.m16n8k16.row.col.f32.f16.f16.f32 "
        "{%0,%1,%2,%3}, {%4,%5,%6,%7}, {%8,%9}, {%0,%1,%2,%3};"
        : "+f"(c[0]), "+f"(c[1]), "+f"(c[2]), "+f"(c[3])
        : "r"(a[0]), "r"(a[1]), "r"(a[2]), "r"(a[3]), "r"(b0), "r"(b1));
}
__device__ __forceinline__ uint32_t packh2(float x, float y) {
    __half2 h = __floats2half2_rn(x, y);
    return *reinterpret_cast<uint32_t*>(&h);
}

// ---------------------------------------------------------------------------
// Fused embedding + LayerNorm (layer-0 ln1)
// ---------------------------------------------------------------------------
__global__ __launch_bounds__(256) void embed_ln_kernel(
    const int* __restrict__ idx,
    const float* __restrict__ tok,
    const float* __restrict__ pos,
    const float* __restrict__ g,
    const float* __restrict__ bb,
    float* __restrict__ px,
    __half* __restrict__ outh)
{
    int w = threadIdx.x >> 5, lane = threadIdx.x & 31;
    int row = blockIdx.x * 8 + w;
    int token = idx[row];
    const float* tr = tok + (size_t)token * ND;
    const float* pr = pos + (size_t)(row % NT) * ND;

    float4 xv[3];
    float s1 = 0.f, s2 = 0.f;
#pragma unroll
    for (int j = 0; j < 3; j++) {
        int c = lane * 4 + j * 128;
        float4 tv = *(const float4*)(tr + c);
        float4 pv = *(const float4*)(pr + c);
        float4 v = { tv.x + pv.x, tv.y + pv.y, tv.z + pv.z, tv.w + pv.w };
        xv[j] = v;
        *(float4*)(px + (size_t)row * ND + c) = v;
        s1 += v.x + v.y + v.z + v.w;
        s2 += v.x * v.x + v.y * v.y + v.z * v.z + v.w * v.w;
    }
#pragma unroll
    for (int o = 16; o > 0; o >>= 1) {
        s1 += __shfl_xor_sync(0xFFFFFFFFu, s1, o);
        s2 += __shfl_xor_sync(0xFFFFFFFFu, s2, o);
    }
    float mean = s1 * (1.f / ND);
    float var  = s2 * (1.f / ND) - mean * mean;
    float rstd = rsqrtf(var + 1e-3f);
#pragma unroll
    for (int j = 0; j < 3; j++) {
        int c = lane * 4 + j * 128;
        float4 gv = *(const float4*)(g + c);
        float4 bv = *(const float4*)(bb + c);
        __half2 h0 = __floats2half2_rn((xv[j].x - mean) * rstd * gv.x + bv.x,
                                       (xv[j].y - mean) * rstd * gv.y + bv.y);
        __half2 h1 = __floats2half2_rn((xv[j].z - mean) * rstd * gv.z + bv.z,
                                       (xv[j].w - mean) * rstd * gv.w + bv.w);
        *(__half2*)(outh + (size_t)row * ND + c)     = h0;
        *(__half2*)(outh + (size_t)row * ND + c + 2) = h1;
    }
}

// ---------------------------------------------------------------------------
// LayerNorm (eps 1e-3), warp-per-row, fp32 in -> fp16 out
// ---------------------------------------------------------------------------
__global__ __launch_bounds__(256) void ln_kernel(const float* __restrict__ x,
                                                 const float* __restrict__ g,
                                                 const float* __restrict__ bb,
                                                 __half* __restrict__ out)
{
    int w = threadIdx.x >> 5, lane = threadIdx.x & 31;
    int row = blockIdx.x * 8 + w;
    const float* xr = x + (size_t)row * ND;

    float4 xv[3];
    float s1 = 0.f, s2 = 0.f;
#pragma unroll
    for (int j = 0; j < 3; j++) {
        float4 v = *(const float4*)(xr + lane * 4 + j * 128);
        xv[j] = v;
        s1 += v.x + v.y + v.z + v.w;
        s2 += v.x * v.x + v.y * v.y + v.z * v.z + v.w * v.w;
    }
#pragma unroll
    for (int o = 16; o > 0; o >>= 1) {
        s1 += __shfl_xor_sync(0xFFFFFFFFu, s1, o);
        s2 += __shfl_xor_sync(0xFFFFFFFFu, s2, o);
    }
    float mean = s1 * (1.f / ND);
    float var  = s2 * (1.f / ND) - mean * mean;
    float rstd = rsqrtf(var + 1e-3f);
#pragma unroll
    for (int j = 0; j < 3; j++) {
        int c = lane * 4 + j * 128;
        float4 gv = *(const float4*)(g + c);
        float4 bv = *(const float4*)(bb + c);
        __half2 h0 = __floats2half2_rn((xv[j].x - mean) * rstd * gv.x + bv.x,
                                       (xv[j].y - mean) * rstd * gv.y + bv.y);
        __half2 h1 = __floats2half2_rn((xv[j].z - mean) * rstd * gv.z + bv.z,
                                       (xv[j].w - mean) * rstd * gv.w + bv.w);
        *(__half2*)(out + (size_t)row * ND + c)     = h0;
        *(__half2*)(out + (size_t)row * ND + c + 2) = h1;
    }
}

// ---------------------------------------------------------------------------
// Tiled transpose: src [R,C] fp32 (+batch offsets) -> dst [C,R] fp16.
// ---------------------------------------------------------------------------
__global__ void transpose_kernel(const float* __restrict__ src,
                                 __half* __restrict__ dst,
                                 int R, int C, int div,
                                 size_t ssA, size_t ssB,
                                 size_t dsA, size_t dsB)
{
    __shared__ float tile[32][33];
    int z = blockIdx.z;
    const float* s = src + (z / div) * ssA + (z % div) * ssB;
    __half* d = dst + (z / div) * dsA + (z % div) * dsB;
    int c0 = blockIdx.x * 32, r0 = blockIdx.y * 32;
#pragma unroll
    for (int j = 0; j < 4; j++) {
        int r = r0 + threadIdx.y + j * 8, c = c0 + threadIdx.x;
        if (r < R && c < C)
            tile[threadIdx.y + j * 8][threadIdx.x] = s[(size_t)r * C + c];
    }
    __syncthreads();
#pragma unroll
    for (int j = 0; j < 4; j++) {
        int c = c0 + threadIdx.y + j * 8, r = r0 + threadIdx.x;
        if (c < C && r < R)
            d[(size_t)c * R + r] = __float2half(tile[threadIdx.x][threadIdx.y + j * 8]);
    }
}

// ---------------------------------------------------------------------------
// hgemm2 (TK=64, 3-stage): BM=128, N multiple of 128 (QKV, W1).
// ---------------------------------------------------------------------------
constexpr int SMB_G2 = 3 * 256 * 144;   // 110592

template <bool RELU, bool VSPLIT>
__global__ __launch_bounds__(128) void hgemm2(
    const __half* __restrict__ A, const __half* __restrict__ B,
    const float* __restrict__ bias, __half* __restrict__ vtp,
    __half* __restrict__ Ch, int N, int K)
{
    extern __shared__ __half smh[];
    __shared__ float sbias[128];
    const int tid = threadIdx.x;
    const int row0 = blockIdx.y * 128;
    const int col0 = blockIdx.x * 128;

    const uint32_t base = smem_u32(smh);
    uint32_t aAu[3], aBu[3];
#pragma unroll
    for (int s = 0; s < 3; s++) {
        aAu[s] = base + s * 128 * 144;
        aBu[s] = base + 3 * 128 * 144 + s * 128 * 144;
    }

    sbias[tid] = bias ? bias[col0 + tid] : 0.f;

    const int KT = K / 64;

    auto prefetch = [&](int kt, int s) {
#pragma unroll
        for (int i = 0; i < 8; i++) {
            int slot = tid + i * 128;
            int r = slot >> 3, c8 = slot & 7;
            cp16f(aAu[s] + (uint32_t)(r * 144 + c8 * 16),
                  A + (size_t)(row0 + r) * K + kt * 64 + c8 * 8);
        }
#pragma unroll
        for (int i = 0; i < 8; i++) {
            int slot = tid + i * 128;
            int r = slot >> 3, c8 = slot & 7;
            cp16f(aBu[s] + (uint32_t)(r * 144 + c8 * 16),
                  B + (size_t)(col0 + r) * K + kt * 64 + c8 * 8);
        }
        cp_commit();
    };

    const int w = tid >> 5, lane = tid & 31;
    const int wm = (w & 1) * 64;
    const int wn = (w >> 1) * 64;
    const int g = lane >> 2, tg = lane & 3;
    const int lr = lane & 15, lc = (lane >> 4) * 16;

    float acc[4][8][4];
#pragma unroll
    for (int i = 0; i < 4; i++)
#pragma unroll
        for (int j = 0; j < 8; j++)
#pragma unroll
            for (int q = 0; q < 4; q++) acc[i][j][q] = 0.f;

    prefetch(0, 0); prefetch(1, 1);

    for (int kt = 0; kt < KT; kt++) {
        if (kt + 1 < KT) asm volatile("cp.async.wait_group 1;" ::: "memory");
        else             asm volatile("cp.async.wait_group 0;" ::: "memory");
        __syncthreads();

        if (kt + 2 < KT) prefetch(kt + 2, (kt + 2) % 3);

        uint32_t bA = aAu[kt % 3], bB = aBu[kt % 3];
#pragma unroll
        for (int ks = 0; ks < 4; ks++) {
            uint32_t a[4][4];
#pragma unroll
            for (int i = 0; i < 4; i++)
                ldm4(a[i], bA + (uint32_t)((wm + 16 * i + lr) * 144 + ks * 32 + lc));
            uint32_t b[4][4];
#pragma unroll
            for (int p = 0; p < 4; p++)
                ldm4(b[p], bB + (uint32_t)((wn + 16 * p + lr) * 144 + ks * 32 + lc));
#pragma unroll
            for (int i = 0; i < 4; i++)
#pragma unroll
                for (int p = 0; p < 4; p++) {
                    mma_f16(acc[i][2 * p],     a[i], b[p][0], b[p][2]);
                    mma_f16(acc[i][2 * p + 1], a[i], b[p][1], b[p][3]);
                }
        }
    }

#pragma unroll
    for (int i = 0; i < 4; i++) {
#pragma unroll
        for (int half_ = 0; half_ < 2; half_++) {
            int r = row0 + wm + 16 * i + g + 8 * half_;
#pragma unroll
            for (int j = 0; j < 8; j++) {
                int cl = wn + 8 * j + 2 * tg;
                int c = col0 + cl;
                float2 v = { acc[i][j][half_ * 2], acc[i][j][half_ * 2 + 1] };
                v.x += sbias[cl]; v.y += sbias[cl + 1];
                if (RELU) { v.x = fmaxf(v.x, 0.f); v.y = fmaxf(v.y, 0.f); }
                if (VSPLIT && col0 >= 2 * ND) {
                    int cc = c - 2 * ND;
                    int hh = cc >> 6, hd = cc & 63;
                    int bb2 = r >> 8, tt = r & 255;
                    size_t vbse = ((size_t)(bb2 * NH + hh) * NHD + hd) * NT + tt;
                    vtp[vbse]      = __float2half(v.x);
                    vtp[vbse + NT] = __float2half(v.y);
                } else {
                    *(__half2*)&Ch[(size_t)r * N + c] = __floats2half2_rn(v.x, v.y);
                }
            }
        }
    }
}

// ---------------------------------------------------------------------------
// hgemm3 (TK=64, 3-stage): BM=64.
//   HEAD=false: N=384 exact, fp32 out + residual (proj, W2).
//   HEAD=true : N=65 ragged, fp32 out, no residual (lm head).
// Same k-order as TK=32 pairs -> bitwise-identical.
// ---------------------------------------------------------------------------
constexpr int SMB_G3 = 3 * (64 + 128) * 144;   // 82944

template <bool HEAD>
__global__ __launch_bounds__(128, 2) void hgemm3(
    const __half* __restrict__ A, const __half* __restrict__ B,
    const float* __restrict__ bias, const float* __restrict__ resid,
    float* __restrict__ Cf, int N, int K)
{
    extern __shared__ __half smh[];
    __shared__ float sbias[128];
    const int tid = threadIdx.x;
    const int row0 = blockIdx.y * 64;
    const int col0 = blockIdx.x * 128;

    const uint32_t base = smem_u32(smh);
    uint32_t aAu[3], aBu[3];
#pragma unroll
    for (int s = 0; s < 3; s++) {
        aAu[s] = base + s * 64 * 144;
        aBu[s] = base + 3 * 64 * 144 + s * 128 * 144;
    }

    {
        int c = col0 + tid;
        sbias[tid] = (bias && (!HEAD || c < N)) ? bias[c] : 0.f;
    }

    const int KT = K / 64;

    auto prefetch = [&](int kt, int s) {
#pragma unroll
        for (int i = 0; i < 4; i++) {
            int slot = tid + i * 128;
            int r = slot >> 3, c8 = slot & 7;
            cp16f(aAu[s] + (uint32_t)(r * 144 + c8 * 16),
                  A + (size_t)(row0 + r) * K + kt * 64 + c8 * 8);
        }
#pragma unroll
        for (int i = 0; i < 8; i++) {
            int slot = tid + i * 128;
            int r = slot >> 3, c8 = slot & 7;
            if (HEAD) {
                int n = col0 + r;
                cp16(aBu[s] + (uint32_t)(r * 144 + c8 * 16),
                     B + (size_t)(n < N ? n : N - 1) * K + kt * 64 + c8 * 8,
                     n < N ? 16 : 0);
            } else {
                cp16f(aBu[s] + (uint32_t)(r * 144 + c8 * 16),
                      B + (size_t)(col0 + r) * K + kt * 64 + c8 * 8);
            }
        }
        cp_commit();
    };

    const int w = tid >> 5, lane = tid & 31;
    const int wm = (w & 1) * 32;
    const int wn = (w >> 1) * 64;
    const int g = lane >> 2, tg = lane & 3;
    const int lr = lane & 15, lc = (lane >> 4) * 16;

    float acc[2][8][4];
#pragma unroll
    for (int i = 0; i < 2; i++)
#pragma unroll
        for (int j = 0; j < 8; j++)
#pragma unroll
            for (int q = 0; q < 4; q++) acc[i][j][q] = 0.f;

    prefetch(0, 0); prefetch(1, 1);

    for (int kt = 0; kt < KT; kt++) {
        if (kt + 1 < KT) asm volatile("cp.async.wait_group 1;" ::: "memory");
        else             asm volatile("cp.async.wait_group 0;" ::: "memory");
        __syncthreads();

        if (kt + 2 < KT) prefetch(kt + 2, (kt + 2) % 3);

        uint32_t bA = aAu[kt % 3], bB = aBu[kt % 3];
#pragma unroll
        for (int ks = 0; ks < 4; ks++) {
            uint32_t a[2][4];
#pragma unroll
            for (int i = 0; i < 2; i++)
                ldm4(a[i], bA + (uint32_t)((wm + 16 * i + lr) * 144 + ks * 32 + lc));
            uint32_t b[4][4];
#pragma unroll
            for (int p = 0; p < 4; p++)
                ldm4(b[p], bB + (uint32_t)((wn + 16 * p + lr) * 144 + ks * 32 + lc));
#pragma unroll
            for (int i = 0; i < 2; i++)
#pragma unroll
                for (int p = 0; p < 4; p++) {
                    mma_f16(acc[i][2 * p],     a[i], b[p][0], b[p][2]);
                    mma_f16(acc[i][2 * p + 1], a[i], b[p][1], b[p][3]);
                }
        }
    }

#pragma unroll
    for (int i = 0; i < 2; i++) {
#pragma unroll
        for (int half_ = 0; half_ < 2; half_++) {
            int r = row0 + wm + 16 * i + g + 8 * half_;
#pragma unroll
            for (int j = 0; j < 8; j++) {
                int cl = wn + 8 * j + 2 * tg;
                int c = col0 + cl;
                float2 v = { acc[i][j][half_ * 2], acc[i][j][half_ * 2 + 1] };
                v.x += sbias[cl]; v.y += sbias[cl + 1];
                if (HEAD) {
                    if (c < N)     Cf[(size_t)r * N + c]     = v.x;
                    if (c + 1 < N) Cf[(size_t)r * N + c + 1] = v.y;
                } else {
                    float2 rv = *(const float2*)&resid[(size_t)r * N + c];
                    v.x += rv.x; v.y += rv.y;
                    *(float2*)&Cf[(size_t)r * N + c] = v;
                }
            }
        }
    }
}

// ---------------------------------------------------------------------------
// Flash attention. Block = (b*NH+h, qtile of 128); 8 warps x 16 rows.
// KV tile 128 (two 64-wide inner passes). Heavy q-tiles first.
// First KV tile prefetched concurrently with Q-wait/qf-build.
// ---------------------------------------------------------------------------
constexpr int AST = 72;
constexpr int VST = 136;

__global__ __launch_bounds__(256) void fattn_kernel(
    const __half* __restrict__ qkv, const __half* __restrict__ vT,
    __half* __restrict__ out)
{
    __shared__ __half sQ[128 * AST], sK[128 * AST], sV[64 * VST];
    const int bh = blockIdx.x;
    const int qt = (int)(gridDim.y - 1) - (int)blockIdx.y;   // heavy tiles first
    const int b = bh / NH, h = bh - b * NH;
    const int tid = threadIdx.x, w = tid >> 5, lane = tid & 31;
    const int g = lane >> 2, tg = lane & 3;
    const int lr = lane & 15;
    const uint32_t lc = (lane >> 4) * 16;

    const uint32_t qb = smem_u32(sQ), kb = smem_u32(sK), vb = smem_u32(sV);

    auto loadKV = [&](int s0) {
        for (int i = tid; i < 1024; i += 256) {
            int r = i >> 3, c8 = i & 7;
            cp16f(kb + (uint32_t)(r * AST * 2 + c8 * 16),
                  qkv + (size_t)(b * NT + s0 + r) * NQKV + ND + h * NHD + c8 * 8);
        }
        for (int i = tid; i < 1024; i += 256) {
            int r = i >> 4, c16 = i & 15;
            cp16f(vb + (uint32_t)(r * VST * 2 + c16 * 16),
                  vT + ((size_t)bh * NHD + r) * NT + s0 + c16 * 8);
        }
        cp_commit();
    };

    // Q load (group A) then first KV tile (group B) -- overlapped
    for (int i = tid; i < 1024; i += 256) {
        int r = i >> 3, c8 = i & 7;
        cp16f(qb + (uint32_t)(r * AST * 2 + c8 * 16),
              qkv + (size_t)(b * NT + qt * 128 + r) * NQKV + h * NHD + c8 * 8);
    }
    cp_commit();
    loadKV(0);
    asm volatile("cp.async.wait_group 1;" ::: "memory");   // Q complete
    __syncthreads();

    uint32_t qf[4][4];
#pragma unroll
    for (int c = 0; c < 4; c++)
        ldm4(qf[c], qb + (uint32_t)((w * 16 + lr) * AST * 2 + c * 32) + lc);

    float O[8][4];
#pragma unroll
    for (int j = 0; j < 8; j++)
#pragma unroll
        for (int q = 0; q < 4; q++) O[j][q] = 0.f;
    float m0 = -1e30f, m1 = -1e30f, l0 = 0.f, l1 = 0.f;
    const float scale = rsqrtf((float)ND);

    const int wrow = qt * 128 + w * 16;

    for (int s0 = 0; s0 <= qt * 128; s0 += 128) {
        if (s0 > 0) {
            __syncthreads();   // previous PV reads complete before overwrite
            loadKV(s0);
        }
        asm volatile("cp.async.wait_group 0;" ::: "memory");
        __syncthreads();

#pragma unroll
        for (int hh = 0; hh < 2; hh++) {
            const int s0h = s0 + hh * 64;
            if (s0h > wrow + 15) continue;

            float S[8][4];
#pragma unroll
            for (int j = 0; j < 8; j++)
                S[j][0] = S[j][1] = S[j][2] = S[j][3] = 0.f;
#pragma unroll
            for (int p = 0; p < 4; p++) {
#pragma unroll
                for (int c = 0; c < 4; c++) {
                    uint32_t bf[4];
                    ldm4(bf, kb + (uint32_t)((hh * 64 + p * 16 + lr) * AST * 2 + c * 32) + lc);
                    mma_f16(S[2 * p],     qf[c], bf[0], bf[2]);
                    mma_f16(S[2 * p + 1], qf[c], bf[1], bf[3]);
                }
            }

            const bool diag = (s0h + 63 > wrow);
            const int rg0 = wrow + g, rg1 = wrow + g + 8;
#pragma unroll
            for (int j = 0; j < 8; j++) {
                int cg = s0h + j * 8 + 2 * tg;
                S[j][0] *= scale; S[j][1] *= scale;
                S[j][2] *= scale; S[j][3] *= scale;
                if (diag) {
                    if (cg     > rg0) S[j][0] = -1e30f;
                    if (cg + 1 > rg0) S[j][1] = -1e30f;
                    if (cg     > rg1) S[j][2] = -1e30f;
                    if (cg + 1 > rg1) S[j][3] = -1e30f;
                }
            }

            float tm0 = -1e30f, tm1 = -1e30f;
#pragma unroll
            for (int j = 0; j < 8; j++) {
                tm0 = fmaxf(tm0, fmaxf(S[j][0], S[j][1]));
                tm1 = fmaxf(tm1, fmaxf(S[j][2], S[j][3]));
            }
            tm0 = fmaxf(tm0, __shfl_xor_sync(0xFFFFFFFFu, tm0, 1));
            tm0 = fmaxf(tm0, __shfl_xor_sync(0xFFFFFFFFu, tm0, 2));
            tm1 = fmaxf(tm1, __shfl_xor_sync(0xFFFFFFFFu, tm1, 1));
            tm1 = fmaxf(tm1, __shfl_xor_sync(0xFFFFFFFFu, tm1, 2));
            float nm0 = fmaxf(m0, tm0), nm1 = fmaxf(m1, tm1);
            float cor0 = __expf(m0 - nm0), cor1 = __expf(m1 - nm1);
            float ts0 = 0.f, ts1 = 0.f;
#pragma unroll
            for (int j = 0; j < 8; j++) {
                S[j][0] = __expf(S[j][0] - nm0); ts0 += S[j][0];
                S[j][1] = __expf(S[j][1] - nm0); ts0 += S[j][1];
                S[j][2] = __expf(S[j][2] - nm1); ts1 += S[j][2];
                S[j][3] = __expf(S[j][3] - nm1); ts1 += S[j][3];
            }
            ts0 += __shfl_xor_sync(0xFFFFFFFFu, ts0, 1);
            ts0 += __shfl_xor_sync(0xFFFFFFFFu, ts0, 2);
            ts1 += __shfl_xor_sync(0xFFFFFFFFu, ts1, 1);
            ts1 += __shfl_xor_sync(0xFFFFFFFFu, ts1, 2);
            l0 = l0 * cor0 + ts0;  l1 = l1 * cor1 + ts1;
            m0 = nm0;  m1 = nm1;
#pragma unroll
            for (int j = 0; j < 8; j++) {
                O[j][0] *= cor0; O[j][1] *= cor0;
                O[j][2] *= cor1; O[j][3] *= cor1;
            }

            uint32_t pf[4][4];
#pragma unroll
            for (int c = 0; c < 4; c++) {
                pf[c][0] = packh2(S[2 * c][0],     S[2 * c][1]);
                pf[c][1] = packh2(S[2 * c][2],     S[2 * c][3]);
                pf[c][2] = packh2(S[2 * c + 1][0], S[2 * c + 1][1]);
                pf[c][3] = packh2(S[2 * c + 1][2], S[2 * c + 1][3]);
            }

#pragma unroll
            for (int p = 0; p < 4; p++) {
#pragma unroll
                for (int c = 0; c < 4; c++) {
                    uint32_t bf[4];
                    ldm4(bf, vb + (uint32_t)((p * 16 + lr) * VST * 2 + hh * 128 + c * 32) + lc);
                    mma_f16(O[2 * p],     pf[c], bf[0], bf[2]);
                    mma_f16(O[2 * p + 1], pf[c], bf[1], bf[3]);
                }
            }
        }
    }

    float i0 = 1.f / l0, i1 = 1.f / l1;
    int qrow = qt * 128 + w * 16 + g;
    size_t ob0 = (size_t)(b * NT + qrow) * ND + h * NHD;
    size_t ob1 = ob0 + (size_t)8 * ND;
#pragma unroll
    for (int j = 0; j < 8; j++) {
        int cc = j * 8 + 2 * tg;
        *(__half2*)(out + ob0 + cc) = __floats2half2_rn(O[j][0] * i0, O[j][1] * i0);
        *(__half2*)(out + ob1 + cc) = __floats2half2_rn(O[j][2] * i1, O[j][3] * i1);
    }
}

// ---------------------------------------------------------------------------
extern "C" void kernel_launch(void* const* d_in, const int* in_sizes, int n_in,
                              void* d_out, int out_size)
{
    const int*   idx   = (const int*)  d_in[0];
    const float* tok   = (const float*)d_in[1];
    const float* pos   = (const float*)d_in[2];
    const float* Wq    = (const float*)d_in[3];
    const float* Wk    = (const float*)d_in[4];
    const float* Wv    = (const float*)d_in[5];
    const float* Wproj = (const float*)d_in[6];
    const float* bproj = (const float*)d_in[7];
    const float* W1    = (const float*)d_in[8];
    const float* b1    = (const float*)d_in[9];
    const float* W2    = (const float*)d_in[10];
    const float* b2    = (const float*)d_in[11];
    const float* ln1g  = (const float*)d_in[12];
    const float* ln1b  = (const float*)d_in[13];
    const float* ln2g  = (const float*)d_in[14];
    const float* ln2b  = (const float*)d_in[15];
    const float* lnfg  = (const float*)d_in[16];
    const float* lnfb  = (const float*)d_in[17];
    const float* Whead = (const float*)d_in[18];
    const float* bhead = (const float*)d_in[19];
    float* out = (float*)d_out;

    float  *px;
    __half *ph, *pqkv, *pvT, *pa, *pm, *pw;
    cudaGetSymbolAddress((void**)&px,   g_x);
    cudaGetSymbolAddress((void**)&ph,   g_h16);
    cudaGetSymbolAddress((void**)&pqkv, g_qkv);
    cudaGetSymbolAddress((void**)&pvT,  g_vT);
    cudaGetSymbolAddress((void**)&pa,   g_att);
    cudaGetSymbolAddress((void**)&pm,   g_hid);
    cudaGetSymbolAddress((void**)&pw,   g_wT);

    static int attr_done = 0;
    if (!attr_done) {
        cudaFuncSetAttribute(hgemm2<false, true>,
                             cudaFuncAttributeMaxDynamicSharedMemorySize, SMB_G2);
        cudaFuncSetAttribute(hgemm2<true, false>,
                             cudaFuncAttributeMaxDynamicSharedMemorySize, SMB_G2);
        cudaFuncSetAttribute(hgemm3<false>,
                             cudaFuncAttributeMaxDynamicSharedMemorySize, SMB_G3);
        cudaFuncSetAttribute(hgemm3<true>,
                             cudaFuncAttributeMaxDynamicSharedMemorySize, SMB_G3);
        attr_done = 1;
    }

    // Weight prep: tiled transpose -> K-major [N,K] fp16
    {
        dim3 blk(32, 8);
        dim3 gqv(NHD / 32, ND / 32, NL * NH);
        size_t ssA = (size_t)NH * ND * NHD, ssB = (size_t)ND * NHD;
        size_t dsA = (size_t)NQKV * ND,     dsB = (size_t)NHD * ND;
        transpose_kernel<<<gqv, blk>>>(Wq, pw + OFF_QKV,                       ND, NHD, NH, ssA, ssB, dsA, dsB);
        transpose_kernel<<<gqv, blk>>>(Wk, pw + OFF_QKV + (size_t)ND * ND,     ND, NHD, NH, ssA, ssB, dsA, dsB);
        transpose_kernel<<<gqv, blk>>>(Wv, pw + OFF_QKV + (size_t)2 * ND * ND, ND, NHD, NH, ssA, ssB, dsA, dsB);
        transpose_kernel<<<dim3(ND / 32, ND / 32, NL), blk>>>(
            Wproj, pw + OFF_PROJ, ND, ND, 1, (size_t)ND * ND, 0, (size_t)ND * ND, 0);
        transpose_kernel<<<dim3(ND4 / 32, ND / 32, NL), blk>>>(
            W1, pw + OFF_W1, ND, ND4, 1, (size_t)ND * ND4, 0, (size_t)ND * ND4, 0);
        transpose_kernel<<<dim3(ND / 32, ND4 / 32, NL), blk>>>(
            W2, pw + OFF_W2, ND4, ND, 1, (size_t)ND * ND4, 0, (size_t)ND * ND4, 0);
        transpose_kernel<<<dim3((NV + 31) / 32, ND / 32, 1), blk>>>(
            Whead, pw + OFF_HEAD, ND, NV, 1, 0, 0, 0, 0);
    }

    // Fused embedding + layer-0 ln1
    embed_ln_kernel<<<MT / 8, 256>>>(idx, tok, pos, ln1g, ln1b, px, ph);

    dim3 gQKV(NQKV / 128, MT / 128);
    dim3 gP  (ND   / 128, MT / 64);     // BM=64 grids (proj, W2 via hgemm3)
    dim3 g4  (ND4  / 128, MT / 128);
    dim3 gH  (1, MT / 64);              // head (hgemm3<true>)

    for (int l = 0; l < NL; l++) {
        if (l > 0)
            ln_kernel<<<MT / 8, 256>>>(px, ln1g + l * ND, ln1b + l * ND, ph);

        hgemm2<false, true><<<gQKV, 128, SMB_G2>>>(
            ph, pw + OFF_QKV + (size_t)l * NQKV * ND,
            nullptr, pvT, pqkv, NQKV, ND);

        fattn_kernel<<<dim3(NB * NH, NT / 128), 256>>>(pqkv, pvT, pa);

        hgemm3<false><<<gP, 128, SMB_G3>>>(
            pa, pw + OFF_PROJ + (size_t)l * ND * ND,
            bproj + l * ND, px, px, ND, ND);

        ln_kernel<<<MT / 8, 256>>>(px, ln2g + l * ND, ln2b + l * ND, ph);

        hgemm2<true, false><<<g4, 128, SMB_G2>>>(
            ph, pw + OFF_W1 + (size_t)l * ND4 * ND,
            b1 + l * ND4, nullptr, pm, ND4, ND);

        hgemm3<false><<<gP, 128, SMB_G3>>>(
            pm, pw + OFF_W2 + (size_t)l * ND * ND4,
            b2 + l * ND, px, px, ND, ND4);
    }

    ln_kernel<<<MT / 8, 256>>>(px, lnfg, lnfb, ph);
    hgemm3<true><<<gH, 128, SMB_G3>>>(
        ph, pw + OFF_HEAD, bhead, nullptr, out, NV, ND);
}